// round 4
// baseline (speedup 1.0000x reference)
#include <cuda_runtime.h>

#define NROWS 65536
#define DDIM  256
#define KCODES 1024
#define BM 64
#define BN 128
#define DC 32
#define XSS 68    // padded stride for transposed x tile
#define ESS 132   // padded stride for transposed e tile
#define GAP_T 0.01f   // score-gap threshold for emulated-fp32 rescan
#define RB 16     // flagged rows per rescan batch

__device__ int    g_hist[KCODES];
__device__ double g_commit;
__device__ double g_div;
__device__ float  g_halfnorm[KCODES];
__device__ float  g_invnorm[KCODES];
__device__ float  g_ne[KCODES];            // emulated ||e_k||^2 (contracted warp-reduce)
__device__ float  g_Wt[DDIM * KCODES];     // transposed codebook [d][k]
__device__ int    g_idx[NROWS];
__device__ int    g_flagrows[NROWS];
__device__ int    g_nflag;

__device__ __forceinline__ unsigned f2o(float f) {   // monotone float->uint
    unsigned b = __float_as_uint(f);
    return (b & 0x80000000u) ? ~b : (b | 0x80000000u);
}
__device__ __forceinline__ float o2f(unsigned u) {
    return (u & 0x80000000u) ? __uint_as_float(u ^ 0x80000000u) : __uint_as_float(~u);
}

__global__ void vq_init() {
    int t = blockIdx.x * blockDim.x + threadIdx.x;
    if (t < KCODES) g_hist[t] = 0;
    if (t == 0) { g_commit = 0.0; g_div = 0.0; g_nflag = 0; }
}

// Transpose codebook: Wt[j][k] = W[k][j]
__global__ void vq_tr(const float* __restrict__ W) {
    int k = blockIdx.x;
    int j = threadIdx.x;
    g_Wt[j * KCODES + k] = W[(size_t)k * DDIM + j];
}

// Per-code: emulated ||e||^2 — CONTRACTED warp row-reduce:
// lane-strided fmaf(v,v,acc) over 8 elements, shfl_down tree 16..1.
__global__ void vq_pre(const float* __restrict__ W) {
    int k = blockIdx.x * 8 + (threadIdx.x >> 5);
    int lane = threadIdx.x & 31;
    float p = 0.f;
    #pragma unroll
    for (int j = 0; j < 8; j++) {
        float v = W[(size_t)k * DDIM + lane + 32 * j];
        p = __fmaf_rn(v, v, p);
    }
    #pragma unroll
    for (int o = 16; o > 0; o >>= 1)
        p = __fadd_rn(p, __shfl_down_sync(0xffffffffu, p, o));
    if (lane == 0) {
        g_ne[k] = p;
        g_halfnorm[k] = 0.5f * p;
        g_invnorm[k] = 1.0f / fmaxf(sqrtf(p), 1e-12f);
    }
}

// Main kernel: per 64-row tile, full K sweep. score = x.e - 0.5||e||^2, argmax
// with top-2 tracking; ambiguous rows flagged for emulated rescan.
// NOTE: acc chain is a single ascending-k serial FMA — bit-identical to the
// cuBLAS/Triton fp32 per-output accumulation.
__global__ void __launch_bounds__(256) vq_main(
    const float* __restrict__ X, const float* __restrict__ W)
{
    extern __shared__ float sm[];
    float* xs = sm;                                     // [256][68] transposed x tile
    float* es = xs + DDIM * XSS;                        // [32][132] transposed e chunk
    float* hn = es + DC * ESS;                          // [128] halfnorms of chunk
    unsigned long long* packed = (unsigned long long*)(hn + BN);  // [64] best
    unsigned* packed2 = (unsigned*)(packed + BM);       // [64] second-best

    const int tid  = threadIdx.x;
    const int row0 = blockIdx.x * BM;

    {
        const float4* xg = (const float4*)(X + (size_t)row0 * DDIM);
        #pragma unroll
        for (int i = 0; i < 16; i++) {
            int slot = tid + 256 * i;
            int r  = slot >> 6;
            int f4 = slot & 63;
            float4 v = xg[slot];
            int d = f4 * 4;
            xs[(d + 0) * XSS + r] = v.x;
            xs[(d + 1) * XSS + r] = v.y;
            xs[(d + 2) * XSS + r] = v.z;
            xs[(d + 3) * XSS + r] = v.w;
        }
    }
    if (tid < BM) { packed[tid] = 0ull; packed2[tid] = 0u; }

    const int rgrp = tid & 7;
    const int cgrp = tid >> 3;
    const int rb = rgrp * 8;
    const int cb = cgrp * 4;

    float tb1[8], tb2[8];
    int   ti1[8];
    #pragma unroll
    for (int i = 0; i < 8; i++) { tb1[i] = -1e30f; tb2[i] = -1e30f; ti1[i] = 0; }

    for (int nc = 0; nc < KCODES / BN; ++nc) {
        const int cbase = nc * BN;
        float acc[8][4];
        #pragma unroll
        for (int i = 0; i < 8; i++)
            #pragma unroll
            for (int j = 0; j < 4; j++) acc[i][j] = 0.f;

        for (int dc = 0; dc < DDIM / DC; ++dc) {
            __syncthreads();
            #pragma unroll
            for (int i = 0; i < 4; i++) {
                int slot = tid + 256 * i;
                int c  = slot >> 3;
                int f4 = slot & 7;
                float4 v = *(const float4*)(W + (size_t)(cbase + c) * DDIM + dc * DC + f4 * 4);
                int d = f4 * 4;
                es[(d + 0) * ESS + c] = v.x;
                es[(d + 1) * ESS + c] = v.y;
                es[(d + 2) * ESS + c] = v.z;
                es[(d + 3) * ESS + c] = v.w;
            }
            if (dc == 0 && tid < BN) hn[tid] = g_halfnorm[cbase + tid];
            __syncthreads();

            #pragma unroll
            for (int d = 0; d < DC; ++d) {
                const float* xa = xs + (dc * DC + d) * XSS + rb;
                const float* eb = es + d * ESS + cb;
                float a[8], b[4];
                #pragma unroll
                for (int i = 0; i < 8; i++) a[i] = xa[i];
                #pragma unroll
                for (int j = 0; j < 4; j++) b[j] = eb[j];
                #pragma unroll
                for (int i = 0; i < 8; i++)
                    #pragma unroll
                    for (int j = 0; j < 4; j++)
                        acc[i][j] = fmaf(a[i], b[j], acc[i][j]);
            }
        }

        #pragma unroll
        for (int i = 0; i < 8; i++) {
            #pragma unroll
            for (int j = 0; j < 4; j++) {
                float s = acc[i][j] - hn[cb + j];
                int g = cbase + cb + j;
                if (s > tb1[i] || (s == tb1[i] && g < ti1[i])) {
                    tb2[i] = tb1[i]; tb1[i] = s; ti1[i] = g;
                } else if (s > tb2[i]) {
                    tb2[i] = s;
                }
            }
        }
    }

    #pragma unroll
    for (int i = 0; i < 8; i++) {
        unsigned long long p = ((unsigned long long)f2o(tb1[i]) << 32) |
                               (unsigned long long)(KCODES - 1 - ti1[i]);
        atomicMax(&packed[rb + i], p);
    }
    __syncthreads();
    #pragma unroll
    for (int i = 0; i < 8; i++) {
        int winner = (KCODES - 1) - (int)(packed[rb + i] & 0xffffffffu);
        float cand = (ti1[i] == winner) ? tb2[i] : tb1[i];
        atomicMax(&packed2[rb + i], f2o(cand));
    }
    __syncthreads();

    if (tid < BM) {
        unsigned long long p = packed[tid];
        int idx = (KCODES - 1) - (int)(p & 0xffffffffu);
        float b1 = o2f((unsigned)(p >> 32));
        float b2 = o2f(packed2[tid]);
        int row = row0 + tid;
        g_idx[row] = idx;
        if (b1 - b2 < GAP_T) {
            int pos = atomicAdd(&g_nflag, 1);
            g_flagrows[pos] = row;
        }
    }
}

// Reference-emulating fp32 rescan (CONTRACTED variant):
//   dot : single fp32 accumulator, FMA chain ascending over d (cuBLAS/Triton order)
//   nx  : lane-strided fmaf(v,v,acc) + shfl_down tree (contracted XLA row-reduce)
//   d2  : rn(fma(dot, -2, nx) + ne), argmin first-index tiebreak
__global__ void __launch_bounds__(256) vq_rescan(const float* __restrict__ X) {
    __shared__ float xs[RB][DDIM];
    __shared__ float nx[RB];
    __shared__ int   rows[RB];
    __shared__ unsigned long long best[RB];
    const int tid = threadIdx.x;
    int n = g_nflag;
    if (n > NROWS) n = NROWS;
    int nb = (n + RB - 1) / RB;

    for (int b = blockIdx.x; b < nb; b += gridDim.x) {
        __syncthreads();
        if (tid < RB) {
            int s = b * RB + tid;
            rows[tid] = (s < n) ? g_flagrows[s] : -1;
            best[tid] = 0xFFFFFFFFFFFFFFFFull;
        }
        __syncthreads();
        for (int i = tid; i < RB * 64; i += 256) {
            int r = i >> 6, f = i & 63;
            if (rows[r] >= 0)
                *(float4*)&xs[r][f * 4] = *(const float4*)(X + (size_t)rows[r] * DDIM + f * 4);
        }
        __syncthreads();
        {
            int w = tid >> 5, lane = tid & 31;
            for (int rr = w; rr < RB; rr += 8) {
                float p = 0.f;
                #pragma unroll
                for (int j = 0; j < 8; j++) {
                    float v = xs[rr][lane + 32 * j];
                    p = __fmaf_rn(v, v, p);
                }
                #pragma unroll
                for (int o = 16; o > 0; o >>= 1)
                    p = __fadd_rn(p, __shfl_down_sync(0xffffffffu, p, o));
                if (lane == 0) nx[rr] = p;
            }
        }
        __syncthreads();

        #pragma unroll 1
        for (int p = 0; p < RB * KCODES / 256; p++) {
            int idx = p * 256 + tid;
            int r = idx >> 10;
            int k = idx & (KCODES - 1);
            if (rows[r] < 0) continue;
            float acc = 0.f;
            const float* xr = xs[r];
            const float* wt = g_Wt + k;
            #pragma unroll 8
            for (int j = 0; j < DDIM; j++)
                acc = __fmaf_rn(xr[j], wt[(size_t)j * KCODES], acc);
            float d2 = __fadd_rn(__fmaf_rn(acc, -2.0f, nx[r]), g_ne[k]);
            unsigned long long pk = ((unsigned long long)f2o(d2) << 32) | (unsigned)k;
            atomicMin(&best[r], pk);
        }
        __syncthreads();
        if (tid < RB && rows[tid] >= 0)
            g_idx[rows[tid]] = (int)(best[tid] & 0xffffffffu);
    }
}

// Gather quantized rows, commitment, histogram, indices (after rescan).
__global__ void __launch_bounds__(256) vq_gather(
    const float* __restrict__ X, const float* __restrict__ W,
    float* __restrict__ outq, float* __restrict__ out_idx)
{
    __shared__ double cred[8];
    const int tid = threadIdx.x;
    const int row0 = blockIdx.x * BM;
    const int r  = tid >> 2;
    const int dq = tid & 3;
    const int row = row0 + r;

    int idx = g_idx[row];
    const float* erow = W + (size_t)idx * DDIM;
    const float* xrow = X + (size_t)row * DDIM;
    float* orow = outq + (size_t)row * DDIM;
    double csum = 0.0;
    #pragma unroll
    for (int j = 0; j < 16; j++) {
        int f4 = dq + 4 * j;
        float4 e4 = *(const float4*)(erow + 4 * f4);
        float4 x4 = *(const float4*)(xrow + 4 * f4);
        *(float4*)(orow + 4 * f4) = e4;
        float d0 = e4.x - x4.x;
        float d1 = e4.y - x4.y;
        float d2 = e4.z - x4.z;
        float d3 = e4.w - x4.w;
        csum += (double)d0 * d0 + (double)d1 * d1 + (double)d2 * d2 + (double)d3 * d3;
    }
    if (dq == 0) {
        atomicAdd(&g_hist[idx], 1);
        if (out_idx) out_idx[row] = (float)idx;
    }

    #pragma unroll
    for (int o = 16; o > 0; o >>= 1)
        csum += __shfl_xor_sync(0xffffffffu, csum, o);
    if ((tid & 31) == 0) cred[tid >> 5] = csum;
    __syncthreads();
    if (tid < 8) {
        double v = cred[tid];
        #pragma unroll
        for (int o = 4; o > 0; o >>= 1) v += __shfl_xor_sync(0xffu, v, o);
        if (tid == 0) atomicAdd(&g_commit, v);
    }
}

// Diversity: sum over K x K of max(|cos_sim - eye|, 0.1)^2, 64x64 tiles.
__global__ void __launch_bounds__(256) vq_div(const float* __restrict__ W) {
    __shared__ float si[DC][XSS];
    __shared__ float sj[DC][XSS];
    __shared__ double red[8];
    const int tid = threadIdx.x;
    const int ibase = (blockIdx.x & 15) * 64;
    const int jbase = (blockIdx.x >> 4) * 64;
    const int ig = tid & 15;
    const int jg = tid >> 4;

    float acc[4][4];
    #pragma unroll
    for (int i = 0; i < 4; i++)
        #pragma unroll
        for (int j = 0; j < 4; j++) acc[i][j] = 0.f;

    for (int dc = 0; dc < DDIM / DC; ++dc) {
        __syncthreads();
        #pragma unroll
        for (int t = 0; t < 2; t++) {
            int slot = tid + 256 * t;
            int c  = slot >> 3;
            int f4 = slot & 7;
            float4 v = *(const float4*)(W + (size_t)(ibase + c) * DDIM + dc * DC + f4 * 4);
            float4 w = *(const float4*)(W + (size_t)(jbase + c) * DDIM + dc * DC + f4 * 4);
            int d = f4 * 4;
            si[d + 0][c] = v.x; si[d + 1][c] = v.y; si[d + 2][c] = v.z; si[d + 3][c] = v.w;
            sj[d + 0][c] = w.x; sj[d + 1][c] = w.y; sj[d + 2][c] = w.z; sj[d + 3][c] = w.w;
        }
        __syncthreads();
        #pragma unroll
        for (int d = 0; d < DC; ++d) {
            float a[4], b[4];
            #pragma unroll
            for (int i = 0; i < 4; i++) a[i] = si[d][ig * 4 + i];
            #pragma unroll
            for (int j = 0; j < 4; j++) b[j] = sj[d][jg * 4 + j];
            #pragma unroll
            for (int i = 0; i < 4; i++)
                #pragma unroll
                for (int j = 0; j < 4; j++)
                    acc[i][j] = fmaf(a[i], b[j], acc[i][j]);
        }
    }

    float invi[4], invj[4];
    #pragma unroll
    for (int i = 0; i < 4; i++) invi[i] = g_invnorm[ibase + ig * 4 + i];
    #pragma unroll
    for (int j = 0; j < 4; j++) invj[j] = g_invnorm[jbase + jg * 4 + j];

    double s = 0.0;
    #pragma unroll
    for (int i = 0; i < 4; i++)
        #pragma unroll
        for (int j = 0; j < 4; j++) {
            float v = acc[i][j] * invi[i] * invj[j];
            if (ibase + ig * 4 + i == jbase + jg * 4 + j) v -= 1.0f;
            float t = fmaxf(fabsf(v), 0.1f);
            s += (double)t * (double)t;
        }

    #pragma unroll
    for (int o = 16; o > 0; o >>= 1) s += __shfl_xor_sync(0xffffffffu, s, o);
    if ((tid & 31) == 0) red[tid >> 5] = s;
    __syncthreads();
    if (tid < 8) {
        double v = red[tid];
        #pragma unroll
        for (int o = 4; o > 0; o >>= 1) v += __shfl_xor_sync(0xffu, v, o);
        if (tid == 0) atomicAdd(&g_div, v);
    }
}

// Entropy + combine losses.
__global__ void vq_fin(float* __restrict__ out_loss) {
    __shared__ double red[32];
    int k = threadIdx.x;
    double p = (double)g_hist[k] * (1.0 / (double)NROWS);
    const double u = 1.0 / (double)KCODES;
    double term = u * (log(u) - log(p + 1e-10));
    #pragma unroll
    for (int o = 16; o > 0; o >>= 1) term += __shfl_xor_sync(0xffffffffu, term, o);
    if ((k & 31) == 0) red[k >> 5] = term;
    __syncthreads();
    if (k < 32) {
        double v = red[k];
        #pragma unroll
        for (int o = 16; o > 0; o >>= 1) v += __shfl_xor_sync(0xffffffffu, v, o);
        if (k == 0) {
            double commit = g_commit * (1.0 / ((double)NROWS * (double)DDIM));
            double divm   = g_div * (1.0 / ((double)KCODES * (double)KCODES));
            double total = 0.25 * commit + 0.5 * divm + 0.5 * v;
            if (out_loss) *out_loss = (float)total;
        }
    }
}

extern "C" void kernel_launch(void* const* d_in, const int* in_sizes, int n_in,
                              void* d_out, int out_size) {
    const float* X = (const float*)d_in[0];
    const float* W = (const float*)d_in[1];
    float* out = (float*)d_out;

    const long long Nq = (long long)NROWS * DDIM;
    float* out_loss = nullptr;
    float* out_idx  = nullptr;
    if ((long long)out_size >= Nq + 1 + NROWS) {
        out_loss = out + Nq;
        out_idx  = out + Nq + 1;
    }

    const size_t SMEM_MAIN = (size_t)(DDIM * XSS + DC * ESS + BN) * sizeof(float)
                           + (size_t)BM * 8 + (size_t)BM * 4 + 64;
    cudaFuncSetAttribute(vq_main, cudaFuncAttributeMaxDynamicSharedMemorySize, (int)SMEM_MAIN);

    vq_init<<<1, 1024>>>();
    vq_tr<<<KCODES, DDIM>>>(W);
    vq_pre<<<KCODES / 8, 256>>>(W);
    vq_main<<<NROWS / BM, 256, SMEM_MAIN>>>(X, W);
    vq_rescan<<<256, 256>>>(X);
    vq_gather<<<NROWS / BM, 256>>>(X, W, out, out_idx);
    vq_div<<<256, 256>>>(W);
    vq_fin<<<1, 1024>>>(out_loss);
}

// round 7
// speedup vs baseline: 1.6240x; 1.6240x over previous
#include <cuda_runtime.h>
#include <cuda_bf16.h>
#include <cstdint>

#define NROWS 65536
#define DDIM  256
#define KCODES 1024
#define GAP_T 0.01f
#define RB 16
#define SSTR 132   // smem row stride in 32-bit words (128 + 4 pad)

// ---------------- device globals ----------------
__device__ int    g_hist[KCODES];
__device__ double g_commit;
__device__ double g_div;
__device__ float  g_halfnorm[KCODES];
__device__ float  g_invnorm[KCODES];
__device__ float  g_ne[KCODES];
__device__ float  g_Wt[DDIM * KCODES];
__device__ int    g_idx[NROWS];
__device__ int    g_flagrows[NROWS];
__device__ int    g_nflag;

// ---------------- helpers ----------------
__device__ __forceinline__ unsigned f2o(float f) {
    unsigned b = __float_as_uint(f);
    return (b & 0x80000000u) ? ~b : (b | 0x80000000u);
}
__device__ __forceinline__ float o2f(unsigned u) {
    return (u & 0x80000000u) ? __uint_as_float(u ^ 0x80000000u) : __uint_as_float(~u);
}

__device__ __forceinline__ void mma_bf16(float* c, const uint32_t* a, const uint32_t* b) {
    asm volatile(
        "mma.sync.aligned.m16n8k16.row.col.f32.bf16.bf16.f32 "
        "{%0,%1,%2,%3}, {%4,%5,%6,%7}, {%8,%9}, {%0,%1,%2,%3};"
        : "+f"(c[0]), "+f"(c[1]), "+f"(c[2]), "+f"(c[3])
        : "r"(a[0]), "r"(a[1]), "r"(a[2]), "r"(a[3]), "r"(b[0]), "r"(b[1]));
}

__device__ __forceinline__ uint32_t pack_bf16x2(float lo, float hi) {
    __nv_bfloat162 t;
    t.x = __float2bfloat16(lo);
    t.y = __float2bfloat16(hi);
    return *(uint32_t*)&t;
}

// ---------------- small kernels ----------------
__global__ void vq_init() {
    int t = blockIdx.x * blockDim.x + threadIdx.x;
    if (t < KCODES) g_hist[t] = 0;
    if (t == 0) { g_commit = 0.0; g_div = 0.0; g_nflag = 0; }
}

__global__ void vq_tr(const float* __restrict__ W) {
    int k = blockIdx.x;
    int j = threadIdx.x;
    g_Wt[j * KCODES + k] = W[(size_t)k * DDIM + j];
}

// contracted XLA-emulated ||e||^2 + halfnorm/invnorm  (validated R4)
__global__ void vq_pre(const float* __restrict__ W) {
    int k = blockIdx.x * 8 + (threadIdx.x >> 5);
    int lane = threadIdx.x & 31;
    float p = 0.f;
    #pragma unroll
    for (int j = 0; j < 8; j++) {
        float v = W[(size_t)k * DDIM + lane + 32 * j];
        p = __fmaf_rn(v, v, p);
    }
    #pragma unroll
    for (int o = 16; o > 0; o >>= 1)
        p = __fadd_rn(p, __shfl_down_sync(0xffffffffu, p, o));
    if (lane == 0) {
        g_ne[k] = p;
        g_halfnorm[k] = 0.5f * p;
        g_invnorm[k] = 1.0f / fmaxf(sqrtf(p), 1e-12f);
    }
}

// ---------------- mma.sync bf16 3-split main GEMM + top-2 ----------------
// CTA: 128 rows x (16 chunks of 64 codes), 8 warps as 4(M) x 2(N),
// warp tile 32x32 = 2 m16-tiles x 4 n8-tiles, k-steps of 16 dims.
// Per-row reduction across all contributors via packed smem atomicMax
// tournaments (validated R1-R4 mechanism).
__global__ void __launch_bounds__(256, 1) vq_main_mma(
    const float* __restrict__ X, const float* __restrict__ W)
{
    extern __shared__ __align__(16) uint32_t sm[];
    float*    hn = (float*)sm;               // [1024]
    uint32_t* xh = sm + 1024;                // [128][SSTR]
    uint32_t* xl = xh + 128 * SSTR;
    uint32_t* wh = xl + 128 * SSTR;          // [64][SSTR]
    uint32_t* wl = wh + 64 * SSTR;
    unsigned long long* pk = (unsigned long long*)(wl + 64 * SSTR);  // [128]
    unsigned* pk2 = (unsigned*)(pk + 128);                           // [128]

    const int tid  = threadIdx.x;
    const int lane = tid & 31;
    const int wid  = tid >> 5;
    const int wm   = wid >> 1;     // 0..3 : 32-row band
    const int wn   = wid & 1;      // 0..1 : 32-code band
    const int q    = lane >> 2;    // 0..7
    const int cg   = lane & 3;     // 0..3
    const int row0 = blockIdx.x * 128;

    for (int i = tid; i < KCODES; i += 256) hn[i] = g_halfnorm[i];
    if (tid < 128) { pk[tid] = 0ull; pk2[tid] = 0u; }

    // X tile: fp32 -> bf16 hi/lo, padded layout
    for (int i = tid; i < 128 * 128; i += 256) {
        int r = i >> 7, w = i & 127;
        float2 v = *(const float2*)(X + (size_t)(row0 + r) * DDIM + 2 * w);
        float h0 = __bfloat162float(__float2bfloat16(v.x));
        float h1 = __bfloat162float(__float2bfloat16(v.y));
        xh[r * SSTR + w] = pack_bf16x2(h0, h1);
        xl[r * SSTR + w] = pack_bf16x2(v.x - h0, v.y - h1);
    }

    float s1[4], s2[4];
    int   i1[4];
    #pragma unroll
    for (int s = 0; s < 4; s++) { s1[s] = -1e30f; s2[s] = -1e30f; i1[s] = 0; }

    for (int nc = 0; nc < 16; nc++) {
        __syncthreads();
        // load + convert W chunk (64 codes x 256 dims)
        for (int i = tid; i < 64 * 128; i += 256) {
            int r = i >> 7, w = i & 127;
            float2 v = *(const float2*)(W + (size_t)(nc * 64 + r) * DDIM + 2 * w);
            float h0 = __bfloat162float(__float2bfloat16(v.x));
            float h1 = __bfloat162float(__float2bfloat16(v.y));
            wh[r * SSTR + w] = pack_bf16x2(h0, h1);
            wl[r * SSTR + w] = pack_bf16x2(v.x - h0, v.y - h1);
        }
        __syncthreads();

        float acc[2][4][4];
        #pragma unroll
        for (int t = 0; t < 2; t++)
            #pragma unroll
            for (int u = 0; u < 4; u++)
                #pragma unroll
                for (int e = 0; e < 4; e++) acc[t][u][e] = 0.f;

        #pragma unroll 4
        for (int ks = 0; ks < 16; ks++) {
            const int kw = ks * 8 + cg;
            uint32_t ah[2][4], al[2][4];
            #pragma unroll
            for (int t = 0; t < 2; t++) {
                const uint32_t* p  = xh + (wm * 32 + t * 16 + q) * SSTR + kw;
                const uint32_t* pl = xl + (wm * 32 + t * 16 + q) * SSTR + kw;
                ah[t][0] = p[0];  ah[t][1] = p[8 * SSTR];
                ah[t][2] = p[4];  ah[t][3] = p[8 * SSTR + 4];
                al[t][0] = pl[0]; al[t][1] = pl[8 * SSTR];
                al[t][2] = pl[4]; al[t][3] = pl[8 * SSTR + 4];
            }
            uint32_t bh[4][2], bl[4][2];
            #pragma unroll
            for (int u = 0; u < 4; u++) {
                const uint32_t* p  = wh + (wn * 32 + u * 8 + q) * SSTR + kw;
                const uint32_t* pl = wl + (wn * 32 + u * 8 + q) * SSTR + kw;
                bh[u][0] = p[0];  bh[u][1] = p[4];
                bl[u][0] = pl[0]; bl[u][1] = pl[4];
            }
            #pragma unroll
            for (int t = 0; t < 2; t++)
                #pragma unroll
                for (int u = 0; u < 4; u++) {
                    mma_bf16(acc[t][u], ah[t], bh[u]);
                    mma_bf16(acc[t][u], ah[t], bl[u]);
                    mma_bf16(acc[t][u], al[t], bh[u]);
                }
        }

        // epilogue: score = dot - halfnorm, running top-2 per row slot
        #pragma unroll
        for (int t = 0; t < 2; t++)
            #pragma unroll
            for (int u = 0; u < 4; u++)
                #pragma unroll
                for (int e = 0; e < 4; e++) {
                    int slot = t * 2 + (e >> 1);
                    int code = nc * 64 + wn * 32 + u * 8 + cg * 2 + (e & 1);
                    float sc = acc[t][u][e] - hn[code];
                    if (sc > s1[slot]) { s2[slot] = s1[slot]; s1[slot] = sc; i1[slot] = code; }
                    else if (sc > s2[slot]) s2[slot] = sc;
                }
    }
    __syncthreads();

    // tournament 1: per-row best (first-index tiebreak)
    #pragma unroll
    for (int s = 0; s < 4; s++) {
        int rowl = wm * 32 + s * 8 + q;
        unsigned long long p = ((unsigned long long)f2o(s1[s]) << 32) |
                               (unsigned long long)(KCODES - 1 - i1[s]);
        atomicMax(&pk[rowl], p);
    }
    __syncthreads();
    // tournament 2: per-row second-best (exclude winner's code)
    #pragma unroll
    for (int s = 0; s < 4; s++) {
        int rowl = wm * 32 + s * 8 + q;
        int winner = (KCODES - 1) - (int)(pk[rowl] & 0xffffffffu);
        float cand = (i1[s] == winner) ? s2[s] : s1[s];
        atomicMax(&pk2[rowl], f2o(cand));
    }
    __syncthreads();

    if (tid < 128) {
        unsigned long long p = pk[tid];
        int idx = (KCODES - 1) - (int)(p & 0xffffffffu);
        float b1 = o2f((unsigned)(p >> 32));
        float b2 = o2f(pk2[tid]);
        int row = row0 + tid;
        g_idx[row] = idx;
        if (b1 - b2 < GAP_T) {
            int pos = atomicAdd(&g_nflag, 1);
            g_flagrows[pos] = row;
        }
    }
}

// ---------------- reference-emulating fp32 rescan (validated R4) ----------------
__global__ void __launch_bounds__(256) vq_rescan(const float* __restrict__ X) {
    __shared__ float xs[RB][DDIM];
    __shared__ float nx[RB];
    __shared__ int   rows[RB];
    __shared__ unsigned long long best[RB];
    const int tid = threadIdx.x;
    int n = g_nflag;
    if (n > NROWS) n = NROWS;
    int nb = (n + RB - 1) / RB;

    for (int b = blockIdx.x; b < nb; b += gridDim.x) {
        __syncthreads();
        if (tid < RB) {
            int s = b * RB + tid;
            rows[tid] = (s < n) ? g_flagrows[s] : -1;
            best[tid] = 0xFFFFFFFFFFFFFFFFull;
        }
        __syncthreads();
        for (int i = tid; i < RB * 64; i += 256) {
            int r = i >> 6, f = i & 63;
            if (rows[r] >= 0)
                *(float4*)&xs[r][f * 4] = *(const float4*)(X + (size_t)rows[r] * DDIM + f * 4);
        }
        __syncthreads();
        {
            int w = tid >> 5, lane = tid & 31;
            for (int rr = w; rr < RB; rr += 8) {
                float p = 0.f;
                #pragma unroll
                for (int j = 0; j < 8; j++) {
                    float v = xs[rr][lane + 32 * j];
                    p = __fmaf_rn(v, v, p);
                }
                #pragma unroll
                for (int o = 16; o > 0; o >>= 1)
                    p = __fadd_rn(p, __shfl_down_sync(0xffffffffu, p, o));
                if (lane == 0) nx[rr] = p;
            }
        }
        __syncthreads();

        #pragma unroll 1
        for (int p = 0; p < RB * KCODES / 256; p++) {
            int idx = p * 256 + tid;
            int r = idx >> 10;
            int k = idx & (KCODES - 1);
            if (rows[r] < 0) continue;
            float acc = 0.f;
            const float* xr = xs[r];
            const float* wt = g_Wt + k;
            #pragma unroll 8
            for (int j = 0; j < DDIM; j++)
                acc = __fmaf_rn(xr[j], wt[(size_t)j * KCODES], acc);
            float d2 = __fadd_rn(__fmaf_rn(acc, -2.0f, nx[r]), g_ne[k]);
            unsigned long long pkk = ((unsigned long long)f2o(d2) << 32) | (unsigned)k;
            atomicMin(&best[r], pkk);
        }
        __syncthreads();
        if (tid < RB && rows[tid] >= 0)
            g_idx[rows[tid]] = (int)(best[tid] & 0xffffffffu);
    }
}

// ---------------- gather + commitment + histogram ----------------
__global__ void __launch_bounds__(256) vq_gather(
    const float* __restrict__ X, const float* __restrict__ W,
    float* __restrict__ outq, float* __restrict__ out_idx)
{
    __shared__ double cred[8];
    const int tid = threadIdx.x;
    const int row0 = blockIdx.x * 64;
    const int r  = tid >> 2;
    const int dq = tid & 3;
    const int row = row0 + r;

    int idx = g_idx[row];
    const float* erow = W + (size_t)idx * DDIM;
    const float* xrow = X + (size_t)row * DDIM;
    float* orow = outq + (size_t)row * DDIM;
    double csum = 0.0;
    #pragma unroll
    for (int j = 0; j < 16; j++) {
        int f4 = dq + 4 * j;
        float4 e4 = *(const float4*)(erow + 4 * f4);
        float4 x4 = *(const float4*)(xrow + 4 * f4);
        *(float4*)(orow + 4 * f4) = e4;
        float d0 = e4.x - x4.x;
        float d1 = e4.y - x4.y;
        float d2 = e4.z - x4.z;
        float d3 = e4.w - x4.w;
        csum += (double)d0 * d0 + (double)d1 * d1 + (double)d2 * d2 + (double)d3 * d3;
    }
    if (dq == 0) {
        atomicAdd(&g_hist[idx], 1);
        if (out_idx) out_idx[row] = (float)idx;
    }

    #pragma unroll
    for (int o = 16; o > 0; o >>= 1)
        csum += __shfl_xor_sync(0xffffffffu, csum, o);
    if ((tid & 31) == 0) cred[tid >> 5] = csum;
    __syncthreads();
    if (tid < 8) {
        double v = cred[tid];
        #pragma unroll
        for (int o = 4; o > 0; o >>= 1) v += __shfl_xor_sync(0xffu, v, o);
        if (tid == 0) atomicAdd(&g_commit, v);
    }
}

// ---------------- diversity loss ----------------
__global__ void __launch_bounds__(256) vq_div(const float* __restrict__ W) {
    __shared__ float si[32][68];
    __shared__ float sj[32][68];
    __shared__ double red[8];
    const int tid = threadIdx.x;
    const int ibase = (blockIdx.x & 15) * 64;
    const int jbase = (blockIdx.x >> 4) * 64;
    const int ig = tid & 15;
    const int jg = tid >> 4;

    float acc[4][4];
    #pragma unroll
    for (int i = 0; i < 4; i++)
        #pragma unroll
        for (int j = 0; j < 4; j++) acc[i][j] = 0.f;

    for (int dc = 0; dc < DDIM / 32; ++dc) {
        __syncthreads();
        #pragma unroll
        for (int t = 0; t < 2; t++) {
            int slot = tid + 256 * t;
            int c  = slot >> 3;
            int f4 = slot & 7;
            float4 v = *(const float4*)(W + (size_t)(ibase + c) * DDIM + dc * 32 + f4 * 4);
            float4 w = *(const float4*)(W + (size_t)(jbase + c) * DDIM + dc * 32 + f4 * 4);
            int d = f4 * 4;
            si[d + 0][c] = v.x; si[d + 1][c] = v.y; si[d + 2][c] = v.z; si[d + 3][c] = v.w;
            sj[d + 0][c] = w.x; sj[d + 1][c] = w.y; sj[d + 2][c] = w.z; sj[d + 3][c] = w.w;
        }
        __syncthreads();
        #pragma unroll
        for (int d = 0; d < 32; ++d) {
            float a[4], b[4];
            #pragma unroll
            for (int i = 0; i < 4; i++) a[i] = si[d][ig * 4 + i];
            #pragma unroll
            for (int j = 0; j < 4; j++) b[j] = sj[d][jg * 4 + j];
            #pragma unroll
            for (int i = 0; i < 4; i++)
                #pragma unroll
                for (int j = 0; j < 4; j++)
                    acc[i][j] = fmaf(a[i], b[j], acc[i][j]);
        }
    }

    float invi[4], invj[4];
    #pragma unroll
    for (int i = 0; i < 4; i++) invi[i] = g_invnorm[ibase + ig * 4 + i];
    #pragma unroll
    for (int j = 0; j < 4; j++) invj[j] = g_invnorm[jbase + jg * 4 + j];

    double s = 0.0;
    #pragma unroll
    for (int i = 0; i < 4; i++)
        #pragma unroll
        for (int j = 0; j < 4; j++) {
            float v = acc[i][j] * invi[i] * invj[j];
            if (ibase + ig * 4 + i == jbase + jg * 4 + j) v -= 1.0f;
            float t = fmaxf(fabsf(v), 0.1f);
            s += (double)t * (double)t;
        }

    #pragma unroll
    for (int o = 16; o > 0; o >>= 1) s += __shfl_xor_sync(0xffffffffu, s, o);
    if ((tid & 31) == 0) red[tid >> 5] = s;
    __syncthreads();
    if (tid < 8) {
        double v = red[tid];
        #pragma unroll
        for (int o = 4; o > 0; o >>= 1) v += __shfl_xor_sync(0xffu, v, o);
        if (tid == 0) atomicAdd(&g_div, v);
    }
}

// ---------------- entropy + combine ----------------
__global__ void vq_fin(float* __restrict__ out_loss) {
    __shared__ double red[32];
    int k = threadIdx.x;
    double p = (double)g_hist[k] * (1.0 / (double)NROWS);
    const double u = 1.0 / (double)KCODES;
    double term = u * (log(u) - log(p + 1e-10));
    #pragma unroll
    for (int o = 16; o > 0; o >>= 1) term += __shfl_xor_sync(0xffffffffu, term, o);
    if ((k & 31) == 0) red[k >> 5] = term;
    __syncthreads();
    if (k < 32) {
        double v = red[k];
        #pragma unroll
        for (int o = 16; o > 0; o >>= 1) v += __shfl_xor_sync(0xffffffffu, v, o);
        if (k == 0) {
            double commit = g_commit * (1.0 / ((double)NROWS * (double)DDIM));
            double divm   = g_div * (1.0 / ((double)KCODES * (double)KCODES));
            double total = 0.25 * commit + 0.5 * divm + 0.5 * v;
            if (out_loss) *out_loss = (float)total;
        }
    }
}

extern "C" void kernel_launch(void* const* d_in, const int* in_sizes, int n_in,
                              void* d_out, int out_size) {
    const float* X = (const float*)d_in[0];
    const float* W = (const float*)d_in[1];
    float* out = (float*)d_out;

    const long long Nq = (long long)NROWS * DDIM;
    float* out_loss = nullptr;
    float* out_idx  = nullptr;
    if ((long long)out_size >= Nq + 1 + NROWS) {
        out_loss = out + Nq;
        out_idx  = out + Nq + 1;
    }

    // dynamic smem: hn + X hi/lo + W hi/lo + tournament arrays
    const int SMEM_MMA = (1024 + 2 * 128 * SSTR + 2 * 64 * SSTR) * 4 + 128 * 8 + 128 * 4;
    cudaFuncSetAttribute(vq_main_mma, cudaFuncAttributeMaxDynamicSharedMemorySize, SMEM_MMA);

    vq_init<<<1, 1024>>>();
    vq_tr<<<KCODES, DDIM>>>(W);
    vq_pre<<<KCODES / 8, 256>>>(W);
    vq_main_mma<<<NROWS / 128, 256, SMEM_MMA>>>(X, W);
    vq_rescan<<<256, 256>>>(X);
    vq_gather<<<NROWS / 64, 256>>>(X, W, out, out_idx);
    vq_div<<<256, 256>>>(W);
    vq_fin<<<1, 1024>>>(out_loss);
}

// round 8
// speedup vs baseline: 1.8345x; 1.1296x over previous
#include <cuda_runtime.h>
#include <cuda_bf16.h>
#include <cstdint>

#define NROWS 65536
#define DDIM  256
#define KCODES 1024
#define GAP_T 0.15f   // 2-term split: omitted-term err sigma ~0.018 -> 6-sigma guard
#define RB 16
#define SSTR 132      // smem row stride in 32-bit words (128 + 4 pad)
#define CN 32         // codes per W chunk

// ---------------- device globals ----------------
__device__ int    g_hist[KCODES];
__device__ double g_commit;
__device__ double g_div;
__device__ float  g_halfnorm[KCODES];
__device__ float  g_invnorm[KCODES];
__device__ float  g_ne[KCODES];
__device__ float  g_Wt[DDIM * KCODES];
__device__ int    g_idx[NROWS];
__device__ int    g_flagrows[NROWS];
__device__ int    g_nflag;

// ---------------- helpers ----------------
__device__ __forceinline__ unsigned f2o(float f) {
    unsigned b = __float_as_uint(f);
    return (b & 0x80000000u) ? ~b : (b | 0x80000000u);
}
__device__ __forceinline__ float o2f(unsigned u) {
    return (u & 0x80000000u) ? __uint_as_float(u ^ 0x80000000u) : __uint_as_float(~u);
}

__device__ __forceinline__ void mma_bf16(float* c, const uint32_t* a, const uint32_t* b) {
    asm volatile(
        "mma.sync.aligned.m16n8k16.row.col.f32.bf16.bf16.f32 "
        "{%0,%1,%2,%3}, {%4,%5,%6,%7}, {%8,%9}, {%0,%1,%2,%3};"
        : "+f"(c[0]), "+f"(c[1]), "+f"(c[2]), "+f"(c[3])
        : "r"(a[0]), "r"(a[1]), "r"(a[2]), "r"(a[3]), "r"(b[0]), "r"(b[1]));
}

__device__ __forceinline__ uint32_t pack_bf16x2(float lo, float hi) {
    __nv_bfloat162 t;
    t.x = __float2bfloat16(lo);
    t.y = __float2bfloat16(hi);
    return *(uint32_t*)&t;
}

// ---------------- small kernels ----------------
__global__ void vq_tr(const float* __restrict__ W) {
    int k = blockIdx.x;
    int j = threadIdx.x;
    g_Wt[j * KCODES + k] = W[(size_t)k * DDIM + j];
}

// contracted XLA-emulated ||e||^2 + halfnorm/invnorm + init (validated R4)
__global__ void vq_pre(const float* __restrict__ W) {
    int k = blockIdx.x * 8 + (threadIdx.x >> 5);
    int lane = threadIdx.x & 31;
    if (blockIdx.x == 0 && threadIdx.x == 0) {
        g_commit = 0.0; g_div = 0.0; g_nflag = 0;
    }
    float p = 0.f;
    #pragma unroll
    for (int j = 0; j < 8; j++) {
        float v = W[(size_t)k * DDIM + lane + 32 * j];
        p = __fmaf_rn(v, v, p);
    }
    #pragma unroll
    for (int o = 16; o > 0; o >>= 1)
        p = __fadd_rn(p, __shfl_down_sync(0xffffffffu, p, o));
    if (lane == 0) {
        g_hist[k] = 0;
        g_ne[k] = p;
        g_halfnorm[k] = 0.5f * p;
        g_invnorm[k] = 1.0f / fmaxf(sqrtf(p), 1e-12f);
    }
}

// ---------------- mma.sync bf16 2-term split GEMM + top-2 ----------------
// CTA: 128 rows x (32 chunks of 32 codes); 8 warps as 4(M) x 2(N);
// warp tile 32 rows x 16 codes = 2 m16 x 2 n8; terms Ah*Bh + Ah*Bl.
// 107 KB smem -> 2 CTAs/SM. Per-row top-2 via packed atomicMax tournaments.
__global__ void __launch_bounds__(256, 2) vq_main_mma(
    const float* __restrict__ X, const float* __restrict__ W)
{
    extern __shared__ __align__(16) uint32_t sm[];
    float*    hn = (float*)sm;               // [1024]
    uint32_t* xh = sm + 1024;                // [128][SSTR]
    uint32_t* wh = xh + 128 * SSTR;          // [CN][SSTR]
    uint32_t* wl = wh + CN * SSTR;           // [CN][SSTR]
    unsigned long long* pk = (unsigned long long*)(wl + CN * SSTR);  // [128]
    unsigned* pk2 = (unsigned*)(pk + 128);                           // [128]

    const int tid  = threadIdx.x;
    const int lane = tid & 31;
    const int wid  = tid >> 5;
    const int wm   = wid >> 1;     // 0..3 : 32-row band
    const int wn   = wid & 1;      // 0..1 : 16-code band
    const int q    = lane >> 2;    // 0..7
    const int cg   = lane & 3;     // 0..3
    const int row0 = blockIdx.x * 128;

    for (int i = tid; i < KCODES; i += 256) hn[i] = g_halfnorm[i];
    if (tid < 128) { pk[tid] = 0ull; pk2[tid] = 0u; }

    // X tile: fp32 -> bf16 hi only, padded layout
    for (int i = tid; i < 128 * 128; i += 256) {
        int r = i >> 7, w = i & 127;
        float2 v = *(const float2*)(X + (size_t)(row0 + r) * DDIM + 2 * w);
        xh[r * SSTR + w] = pack_bf16x2(__bfloat162float(__float2bfloat16(v.x)),
                                       __bfloat162float(__float2bfloat16(v.y)));
    }

    float s1[4], s2[4];
    int   i1[4];
    #pragma unroll
    for (int s = 0; s < 4; s++) { s1[s] = -1e30f; s2[s] = -1e30f; i1[s] = 0; }

    for (int nc = 0; nc < KCODES / CN; nc++) {
        __syncthreads();
        // load + convert W chunk (CN codes x 256 dims, hi+lo)
        for (int i = tid; i < CN * 128; i += 256) {
            int r = i >> 7, w = i & 127;
            float2 v = *(const float2*)(W + (size_t)(nc * CN + r) * DDIM + 2 * w);
            float h0 = __bfloat162float(__float2bfloat16(v.x));
            float h1 = __bfloat162float(__float2bfloat16(v.y));
            wh[r * SSTR + w] = pack_bf16x2(h0, h1);
            wl[r * SSTR + w] = pack_bf16x2(v.x - h0, v.y - h1);
        }
        __syncthreads();

        float acc[2][2][4];
        #pragma unroll
        for (int t = 0; t < 2; t++)
            #pragma unroll
            for (int u = 0; u < 2; u++)
                #pragma unroll
                for (int e = 0; e < 4; e++) acc[t][u][e] = 0.f;

        #pragma unroll 4
        for (int ks = 0; ks < 16; ks++) {
            const int kw = ks * 8 + cg;
            uint32_t a[2][4];
            #pragma unroll
            for (int t = 0; t < 2; t++) {
                const uint32_t* p = xh + (wm * 32 + t * 16 + q) * SSTR + kw;
                a[t][0] = p[0]; a[t][1] = p[8 * SSTR];
                a[t][2] = p[4]; a[t][3] = p[8 * SSTR + 4];
            }
            uint32_t bh[2][2], bl[2][2];
            #pragma unroll
            for (int u = 0; u < 2; u++) {
                const uint32_t* p  = wh + (wn * 16 + u * 8 + q) * SSTR + kw;
                const uint32_t* pl = wl + (wn * 16 + u * 8 + q) * SSTR + kw;
                bh[u][0] = p[0];  bh[u][1] = p[4];
                bl[u][0] = pl[0]; bl[u][1] = pl[4];
            }
            #pragma unroll
            for (int t = 0; t < 2; t++)
                #pragma unroll
                for (int u = 0; u < 2; u++) {
                    mma_bf16(acc[t][u], a[t], bh[u]);
                    mma_bf16(acc[t][u], a[t], bl[u]);
                }
        }

        // epilogue: score = dot - halfnorm, running top-2 per row slot
        #pragma unroll
        for (int t = 0; t < 2; t++)
            #pragma unroll
            for (int u = 0; u < 2; u++)
                #pragma unroll
                for (int e = 0; e < 4; e++) {
                    int slot = t * 2 + (e >> 1);
                    int code = nc * CN + wn * 16 + u * 8 + cg * 2 + (e & 1);
                    float sc = acc[t][u][e] - hn[code];
                    if (sc > s1[slot]) { s2[slot] = s1[slot]; s1[slot] = sc; i1[slot] = code; }
                    else if (sc > s2[slot]) s2[slot] = sc;
                }
    }
    __syncthreads();

    // tournament 1: per-row best (first-index tiebreak)
    #pragma unroll
    for (int s = 0; s < 4; s++) {
        int rowl = wm * 32 + s * 8 + q;
        unsigned long long p = ((unsigned long long)f2o(s1[s]) << 32) |
                               (unsigned long long)(KCODES - 1 - i1[s]);
        atomicMax(&pk[rowl], p);
    }
    __syncthreads();
    // tournament 2: per-row second-best (exclude winner's code)
    #pragma unroll
    for (int s = 0; s < 4; s++) {
        int rowl = wm * 32 + s * 8 + q;
        int winner = (KCODES - 1) - (int)(pk[rowl] & 0xffffffffu);
        float cand = (i1[s] == winner) ? s2[s] : s1[s];
        atomicMax(&pk2[rowl], f2o(cand));
    }
    __syncthreads();

    if (tid < 128) {
        unsigned long long p = pk[tid];
        int idx = (KCODES - 1) - (int)(p & 0xffffffffu);
        float b1 = o2f((unsigned)(p >> 32));
        float b2 = o2f(pk2[tid]);
        int row = row0 + tid;
        g_idx[row] = idx;
        if (b1 - b2 < GAP_T) {
            int pos = atomicAdd(&g_nflag, 1);
            g_flagrows[pos] = row;
        }
    }
}

// ---------------- reference-emulating fp32 rescan (validated R4) ----------------
__global__ void __launch_bounds__(256) vq_rescan(const float* __restrict__ X) {
    __shared__ float xs[RB][DDIM];
    __shared__ float nx[RB];
    __shared__ int   rows[RB];
    __shared__ unsigned long long best[RB];
    const int tid = threadIdx.x;
    int n = g_nflag;
    if (n > NROWS) n = NROWS;
    int nb = (n + RB - 1) / RB;

    for (int b = blockIdx.x; b < nb; b += gridDim.x) {
        __syncthreads();
        if (tid < RB) {
            int s = b * RB + tid;
            rows[tid] = (s < n) ? g_flagrows[s] : -1;
            best[tid] = 0xFFFFFFFFFFFFFFFFull;
        }
        __syncthreads();
        for (int i = tid; i < RB * 64; i += 256) {
            int r = i >> 6, f = i & 63;
            if (rows[r] >= 0)
                *(float4*)&xs[r][f * 4] = *(const float4*)(X + (size_t)rows[r] * DDIM + f * 4);
        }
        __syncthreads();
        {
            int w = tid >> 5, lane = tid & 31;
            for (int rr = w; rr < RB; rr += 8) {
                float p = 0.f;
                #pragma unroll
                for (int j = 0; j < 8; j++) {
                    float v = xs[rr][lane + 32 * j];
                    p = __fmaf_rn(v, v, p);
                }
                #pragma unroll
                for (int o = 16; o > 0; o >>= 1)
                    p = __fadd_rn(p, __shfl_down_sync(0xffffffffu, p, o));
                if (lane == 0) nx[rr] = p;
            }
        }
        __syncthreads();

        #pragma unroll 1
        for (int p = 0; p < RB * KCODES / 256; p++) {
            int idx = p * 256 + tid;
            int r = idx >> 10;
            int k = idx & (KCODES - 1);
            if (rows[r] < 0) continue;
            float acc = 0.f;
            const float* xr = xs[r];
            const float* wt = g_Wt + k;
            #pragma unroll 8
            for (int j = 0; j < DDIM; j++)
                acc = __fmaf_rn(xr[j], wt[(size_t)j * KCODES], acc);
            float d2 = __fadd_rn(__fmaf_rn(acc, -2.0f, nx[r]), g_ne[k]);
            unsigned long long pkk = ((unsigned long long)f2o(d2) << 32) | (unsigned)k;
            atomicMin(&best[r], pkk);
        }
        __syncthreads();
        if (tid < RB && rows[tid] >= 0)
            g_idx[rows[tid]] = (int)(best[tid] & 0xffffffffu);
    }
}

// ---------------- gather + commitment + histogram ----------------
__global__ void __launch_bounds__(256) vq_gather(
    const float* __restrict__ X, const float* __restrict__ W,
    float* __restrict__ outq, float* __restrict__ out_idx)
{
    __shared__ double cred[8];
    const int tid = threadIdx.x;
    const int row0 = blockIdx.x * 64;
    const int r  = tid >> 2;
    const int dq = tid & 3;
    const int row = row0 + r;

    int idx = g_idx[row];
    const float* erow = W + (size_t)idx * DDIM;
    const float* xrow = X + (size_t)row * DDIM;
    float* orow = outq + (size_t)row * DDIM;
    double csum = 0.0;
    #pragma unroll
    for (int j = 0; j < 16; j++) {
        int f4 = dq + 4 * j;
        float4 e4 = *(const float4*)(erow + 4 * f4);
        float4 x4 = *(const float4*)(xrow + 4 * f4);
        *(float4*)(orow + 4 * f4) = e4;
        float d0 = e4.x - x4.x;
        float d1 = e4.y - x4.y;
        float d2 = e4.z - x4.z;
        float d3 = e4.w - x4.w;
        csum += (double)d0 * d0 + (double)d1 * d1 + (double)d2 * d2 + (double)d3 * d3;
    }
    if (dq == 0) {
        atomicAdd(&g_hist[idx], 1);
        if (out_idx) out_idx[row] = (float)idx;
    }

    #pragma unroll
    for (int o = 16; o > 0; o >>= 1)
        csum += __shfl_xor_sync(0xffffffffu, csum, o);
    if ((tid & 31) == 0) cred[tid >> 5] = csum;
    __syncthreads();
    if (tid < 8) {
        double v = cred[tid];
        #pragma unroll
        for (int o = 4; o > 0; o >>= 1) v += __shfl_xor_sync(0xffu, v, o);
        if (tid == 0) atomicAdd(&g_commit, v);
    }
}

// ---------------- diversity loss ----------------
__global__ void __launch_bounds__(256) vq_div(const float* __restrict__ W) {
    __shared__ float si[32][68];
    __shared__ float sj[32][68];
    __shared__ double red[8];
    const int tid = threadIdx.x;
    const int ibase = (blockIdx.x & 15) * 64;
    const int jbase = (blockIdx.x >> 4) * 64;
    const int ig = tid & 15;
    const int jg = tid >> 4;

    float acc[4][4];
    #pragma unroll
    for (int i = 0; i < 4; i++)
        #pragma unroll
        for (int j = 0; j < 4; j++) acc[i][j] = 0.f;

    for (int dc = 0; dc < DDIM / 32; ++dc) {
        __syncthreads();
        #pragma unroll
        for (int t = 0; t < 2; t++) {
            int slot = tid + 256 * t;
            int c  = slot >> 3;
            int f4 = slot & 7;
            float4 v = *(const float4*)(W + (size_t)(ibase + c) * DDIM + dc * 32 + f4 * 4);
            float4 w = *(const float4*)(W + (size_t)(jbase + c) * DDIM + dc * 32 + f4 * 4);
            int d = f4 * 4;
            si[d + 0][c] = v.x; si[d + 1][c] = v.y; si[d + 2][c] = v.z; si[d + 3][c] = v.w;
            sj[d + 0][c] = w.x; sj[d + 1][c] = w.y; sj[d + 2][c] = w.z; sj[d + 3][c] = w.w;
        }
        __syncthreads();
        #pragma unroll
        for (int d = 0; d < 32; ++d) {
            float a[4], b[4];
            #pragma unroll
            for (int i = 0; i < 4; i++) a[i] = si[d][ig * 4 + i];
            #pragma unroll
            for (int j = 0; j < 4; j++) b[j] = sj[d][jg * 4 + j];
            #pragma unroll
            for (int i = 0; i < 4; i++)
                #pragma unroll
                for (int j = 0; j < 4; j++)
                    acc[i][j] = fmaf(a[i], b[j], acc[i][j]);
        }
    }

    float invi[4], invj[4];
    #pragma unroll
    for (int i = 0; i < 4; i++) invi[i] = g_invnorm[ibase + ig * 4 + i];
    #pragma unroll
    for (int j = 0; j < 4; j++) invj[j] = g_invnorm[jbase + jg * 4 + j];

    double s = 0.0;
    #pragma unroll
    for (int i = 0; i < 4; i++)
        #pragma unroll
        for (int j = 0; j < 4; j++) {
            float v = acc[i][j] * invi[i] * invj[j];
            if (ibase + ig * 4 + i == jbase + jg * 4 + j) v -= 1.0f;
            float t = fmaxf(fabsf(v), 0.1f);
            s += (double)t * (double)t;
        }

    #pragma unroll
    for (int o = 16; o > 0; o >>= 1) s += __shfl_xor_sync(0xffffffffu, s, o);
    if ((tid & 31) == 0) red[tid >> 5] = s;
    __syncthreads();
    if (tid < 8) {
        double v = red[tid];
        #pragma unroll
        for (int o = 4; o > 0; o >>= 1) v += __shfl_xor_sync(0xffu, v, o);
        if (tid == 0) atomicAdd(&g_div, v);
    }
}

// ---------------- entropy + combine ----------------
__global__ void vq_fin(float* __restrict__ out_loss) {
    __shared__ double red[32];
    int k = threadIdx.x;
    double p = (double)g_hist[k] * (1.0 / (double)NROWS);
    const double u = 1.0 / (double)KCODES;
    double term = u * (log(u) - log(p + 1e-10));
    #pragma unroll
    for (int o = 16; o > 0; o >>= 1) term += __shfl_xor_sync(0xffffffffu, term, o);
    if ((k & 31) == 0) red[k >> 5] = term;
    __syncthreads();
    if (k < 32) {
        double v = red[k];
        #pragma unroll
        for (int o = 16; o > 0; o >>= 1) v += __shfl_xor_sync(0xffffffffu, v, o);
        if (k == 0) {
            double commit = g_commit * (1.0 / ((double)NROWS * (double)DDIM));
            double divm   = g_div * (1.0 / ((double)KCODES * (double)KCODES));
            double total = 0.25 * commit + 0.5 * divm + 0.5 * v;
            if (out_loss) *out_loss = (float)total;
        }
    }
}

extern "C" void kernel_launch(void* const* d_in, const int* in_sizes, int n_in,
                              void* d_out, int out_size) {
    const float* X = (const float*)d_in[0];
    const float* W = (const float*)d_in[1];
    float* out = (float*)d_out;

    const long long Nq = (long long)NROWS * DDIM;
    float* out_loss = nullptr;
    float* out_idx  = nullptr;
    if ((long long)out_size >= Nq + 1 + NROWS) {
        out_loss = out + Nq;
        out_idx  = out + Nq + 1;
    }

    // dynamic smem: hn + X hi + W hi/lo + tournament arrays  (~107 KB)
    const int SMEM_MMA = (1024 + 128 * SSTR + 2 * CN * SSTR) * 4 + 128 * 8 + 128 * 4;
    cudaFuncSetAttribute(vq_main_mma, cudaFuncAttributeMaxDynamicSharedMemorySize, SMEM_MMA);

    vq_tr<<<KCODES, DDIM>>>(W);
    vq_pre<<<KCODES / 8, 256>>>(W);
    vq_main_mma<<<NROWS / 128, 256, SMEM_MMA>>>(X, W);
    vq_rescan<<<256, 256>>>(X);
    vq_gather<<<NROWS / 64, 256>>>(X, W, out, out_idx);
    vq_div<<<256, 256>>>(W);
    vq_fin<<<1, 1024>>>(out_loss);
}

// round 9
// speedup vs baseline: 4.1642x; 2.2699x over previous
#include <cuda_runtime.h>
#include <cuda_bf16.h>
#include <cstdint>

#define NROWS 65536
#define DDIM  256
#define KCODES 1024
#define GAP_T 0.15f   // 2-term split: omitted-term err sigma ~0.018 -> 6-sigma guard
#define SSTR 132      // smem row stride in 32-bit words (128 + 4 pad)
#define CN 32         // codes per W chunk

// ---------------- device globals ----------------
__device__ int    g_hist[KCODES];
__device__ double g_commit;
__device__ double g_div;
__device__ float  g_halfnorm[KCODES];
__device__ float  g_invnorm[KCODES];
__device__ float  g_ne[KCODES];
__device__ float  g_Wt[DDIM * KCODES];
__device__ int    g_idx[NROWS];
__device__ int    g_flagrows[NROWS];
__device__ int    g_nflag;
__device__ unsigned long long g_best[NROWS];

// ---------------- helpers ----------------
__device__ __forceinline__ unsigned f2o(float f) {
    unsigned b = __float_as_uint(f);
    return (b & 0x80000000u) ? ~b : (b | 0x80000000u);
}
__device__ __forceinline__ float o2f(unsigned u) {
    return (u & 0x80000000u) ? __uint_as_float(u ^ 0x80000000u) : __uint_as_float(~u);
}

__device__ __forceinline__ void mma_bf16(float* c, const uint32_t* a, const uint32_t* b) {
    asm volatile(
        "mma.sync.aligned.m16n8k16.row.col.f32.bf16.bf16.f32 "
        "{%0,%1,%2,%3}, {%4,%5,%6,%7}, {%8,%9}, {%0,%1,%2,%3};"
        : "+f"(c[0]), "+f"(c[1]), "+f"(c[2]), "+f"(c[3])
        : "r"(a[0]), "r"(a[1]), "r"(a[2]), "r"(a[3]), "r"(b[0]), "r"(b[1]));
}

__device__ __forceinline__ uint32_t pack_bf16x2(float lo, float hi) {
    __nv_bfloat162 t;
    t.x = __float2bfloat16(lo);
    t.y = __float2bfloat16(hi);
    return *(uint32_t*)&t;
}

// ---------------- small kernels ----------------
__global__ void vq_tr(const float* __restrict__ W) {
    int k = blockIdx.x;
    int j = threadIdx.x;
    g_Wt[j * KCODES + k] = W[(size_t)k * DDIM + j];
}

// contracted XLA-emulated ||e||^2 + halfnorm/invnorm + init (validated R4)
__global__ void vq_pre(const float* __restrict__ W) {
    int k = blockIdx.x * 8 + (threadIdx.x >> 5);
    int lane = threadIdx.x & 31;
    if (blockIdx.x == 0 && threadIdx.x == 0) {
        g_commit = 0.0; g_div = 0.0; g_nflag = 0;
    }
    float p = 0.f;
    #pragma unroll
    for (int j = 0; j < 8; j++) {
        float v = W[(size_t)k * DDIM + lane + 32 * j];
        p = __fmaf_rn(v, v, p);
    }
    #pragma unroll
    for (int o = 16; o > 0; o >>= 1)
        p = __fadd_rn(p, __shfl_down_sync(0xffffffffu, p, o));
    if (lane == 0) {
        g_hist[k] = 0;
        g_ne[k] = p;
        g_halfnorm[k] = 0.5f * p;
        g_invnorm[k] = 1.0f / fmaxf(sqrtf(p), 1e-12f);
    }
}

// ---------------- mma.sync bf16 2-term split GEMM + top-2 (validated R8) ----------------
__global__ void __launch_bounds__(256, 2) vq_main_mma(
    const float* __restrict__ X, const float* __restrict__ W)
{
    extern __shared__ __align__(16) uint32_t sm[];
    float*    hn = (float*)sm;               // [1024]
    uint32_t* xh = sm + 1024;                // [128][SSTR]
    uint32_t* wh = xh + 128 * SSTR;          // [CN][SSTR]
    uint32_t* wl = wh + CN * SSTR;           // [CN][SSTR]
    unsigned long long* pk = (unsigned long long*)(wl + CN * SSTR);  // [128]
    unsigned* pk2 = (unsigned*)(pk + 128);                           // [128]

    const int tid  = threadIdx.x;
    const int lane = tid & 31;
    const int wid  = tid >> 5;
    const int wm   = wid >> 1;     // 0..3 : 32-row band
    const int wn   = wid & 1;      // 0..1 : 16-code band
    const int q    = lane >> 2;    // 0..7
    const int cg   = lane & 3;     // 0..3
    const int row0 = blockIdx.x * 128;

    for (int i = tid; i < KCODES; i += 256) hn[i] = g_halfnorm[i];
    if (tid < 128) { pk[tid] = 0ull; pk2[tid] = 0u; }

    // X tile: fp32 -> bf16 hi only, padded layout
    for (int i = tid; i < 128 * 128; i += 256) {
        int r = i >> 7, w = i & 127;
        float2 v = *(const float2*)(X + (size_t)(row0 + r) * DDIM + 2 * w);
        xh[r * SSTR + w] = pack_bf16x2(__bfloat162float(__float2bfloat16(v.x)),
                                       __bfloat162float(__float2bfloat16(v.y)));
    }

    float s1[4], s2[4];
    int   i1[4];
    #pragma unroll
    for (int s = 0; s < 4; s++) { s1[s] = -1e30f; s2[s] = -1e30f; i1[s] = 0; }

    for (int nc = 0; nc < KCODES / CN; nc++) {
        __syncthreads();
        // load + convert W chunk (CN codes x 256 dims, hi+lo)
        for (int i = tid; i < CN * 128; i += 256) {
            int r = i >> 7, w = i & 127;
            float2 v = *(const float2*)(W + (size_t)(nc * CN + r) * DDIM + 2 * w);
            float h0 = __bfloat162float(__float2bfloat16(v.x));
            float h1 = __bfloat162float(__float2bfloat16(v.y));
            wh[r * SSTR + w] = pack_bf16x2(h0, h1);
            wl[r * SSTR + w] = pack_bf16x2(v.x - h0, v.y - h1);
        }
        __syncthreads();

        float acc[2][2][4];
        #pragma unroll
        for (int t = 0; t < 2; t++)
            #pragma unroll
            for (int u = 0; u < 2; u++)
                #pragma unroll
                for (int e = 0; e < 4; e++) acc[t][u][e] = 0.f;

        #pragma unroll 4
        for (int ks = 0; ks < 16; ks++) {
            const int kw = ks * 8 + cg;
            uint32_t a[2][4];
            #pragma unroll
            for (int t = 0; t < 2; t++) {
                const uint32_t* p = xh + (wm * 32 + t * 16 + q) * SSTR + kw;
                a[t][0] = p[0]; a[t][1] = p[8 * SSTR];
                a[t][2] = p[4]; a[t][3] = p[8 * SSTR + 4];
            }
            uint32_t bh[2][2], bl[2][2];
            #pragma unroll
            for (int u = 0; u < 2; u++) {
                const uint32_t* p  = wh + (wn * 16 + u * 8 + q) * SSTR + kw;
                const uint32_t* pl = wl + (wn * 16 + u * 8 + q) * SSTR + kw;
                bh[u][0] = p[0];  bh[u][1] = p[4];
                bl[u][0] = pl[0]; bl[u][1] = pl[4];
            }
            #pragma unroll
            for (int t = 0; t < 2; t++)
                #pragma unroll
                for (int u = 0; u < 2; u++) {
                    mma_bf16(acc[t][u], a[t], bh[u]);
                    mma_bf16(acc[t][u], a[t], bl[u]);
                }
        }

        // epilogue: score = dot - halfnorm, running top-2 per row slot
        #pragma unroll
        for (int t = 0; t < 2; t++)
            #pragma unroll
            for (int u = 0; u < 2; u++)
                #pragma unroll
                for (int e = 0; e < 4; e++) {
                    int slot = t * 2 + (e >> 1);
                    int code = nc * CN + wn * 16 + u * 8 + cg * 2 + (e & 1);
                    float sc = acc[t][u][e] - hn[code];
                    if (sc > s1[slot]) { s2[slot] = s1[slot]; s1[slot] = sc; i1[slot] = code; }
                    else if (sc > s2[slot]) s2[slot] = sc;
                }
    }
    __syncthreads();

    // tournament 1: per-row best (first-index tiebreak)
    #pragma unroll
    for (int s = 0; s < 4; s++) {
        int rowl = wm * 32 + s * 8 + q;
        unsigned long long p = ((unsigned long long)f2o(s1[s]) << 32) |
                               (unsigned long long)(KCODES - 1 - i1[s]);
        atomicMax(&pk[rowl], p);
    }
    __syncthreads();
    // tournament 2: per-row second-best (exclude winner's code)
    #pragma unroll
    for (int s = 0; s < 4; s++) {
        int rowl = wm * 32 + s * 8 + q;
        int winner = (KCODES - 1) - (int)(pk[rowl] & 0xffffffffu);
        float cand = (i1[s] == winner) ? s2[s] : s1[s];
        atomicMax(&pk2[rowl], f2o(cand));
    }
    __syncthreads();

    if (tid < 128) {
        unsigned long long p = pk[tid];
        int idx = (KCODES - 1) - (int)(p & 0xffffffffu);
        float b1 = o2f((unsigned)(p >> 32));
        float b2 = o2f(pk2[tid]);
        int row = row0 + tid;
        g_idx[row] = idx;
        if (b1 - b2 < GAP_T) {
            g_best[row] = 0xFFFFFFFFFFFFFFFFull;
            int pos = atomicAdd(&g_nflag, 1);
            g_flagrows[pos] = row;
        }
    }
}

// ---------------- rescan v2: latency-hiding, bit-exact (arithmetic per R4) ----------------
// Unit = (flagged row, 512-code half). Thread owns 2 interleaved serial FMA
// chains (k, k+256) -> 2x MLP; unroll 16 for prefetch depth. Results merged
// via global atomicMin of packed (d2, k).
__global__ void vq_rescan2(const float* __restrict__ X) {
    __shared__ float xrow[DDIM];
    __shared__ float s_nx;
    const int tid = threadIdx.x;
    int n = g_nflag;
    if (n > NROWS) n = NROWS;
    int nu = 2 * n;

    for (int u = blockIdx.x; u < nu; u += gridDim.x) {
        int row = g_flagrows[u >> 1];
        int k0 = (u & 1) * 512 + tid;
        __syncthreads();   // protect prev iteration's xrow
        if (tid < 64)
            *(float4*)&xrow[tid * 4] = *(const float4*)(X + (size_t)row * DDIM + tid * 4);
        __syncthreads();
        if (tid < 32) {
            float p = 0.f;
            #pragma unroll
            for (int j = 0; j < 8; j++) {
                float v = xrow[tid + 32 * j];
                p = __fmaf_rn(v, v, p);
            }
            #pragma unroll
            for (int o = 16; o > 0; o >>= 1)
                p = __fadd_rn(p, __shfl_down_sync(0xffffffffu, p, o));
            if (tid == 0) s_nx = p;
        }
        __syncthreads();
        float nx = s_nx;

        float a0 = 0.f, a1 = 0.f;
        const float* w0 = g_Wt + k0;
        #pragma unroll 16
        for (int j = 0; j < DDIM; j++) {
            float x = xrow[j];
            a0 = __fmaf_rn(x, w0[(size_t)j * KCODES], a0);
            a1 = __fmaf_rn(x, w0[(size_t)j * KCODES + 256], a1);
        }
        float d0 = __fadd_rn(__fmaf_rn(a0, -2.0f, nx), g_ne[k0]);
        float d1 = __fadd_rn(__fmaf_rn(a1, -2.0f, nx), g_ne[k0 + 256]);
        unsigned long long p0 = ((unsigned long long)f2o(d0) << 32) | (unsigned)k0;
        unsigned long long p1 = ((unsigned long long)f2o(d1) << 32) | (unsigned)(k0 + 256);
        atomicMin(&g_best[row], p0 < p1 ? p0 : p1);
    }
}

// write winning indices for flagged rows
__global__ void vq_fix() {
    int n = g_nflag;
    if (n > NROWS) n = NROWS;
    for (int u = blockIdx.x * blockDim.x + threadIdx.x; u < n; u += gridDim.x * blockDim.x) {
        int row = g_flagrows[u];
        g_idx[row] = (int)(g_best[row] & 0xffffffffu);
    }
}

// ---------------- gather + commitment + histogram ----------------
__global__ void __launch_bounds__(256) vq_gather(
    const float* __restrict__ X, const float* __restrict__ W,
    float* __restrict__ outq, float* __restrict__ out_idx)
{
    __shared__ double cred[8];
    const int tid = threadIdx.x;
    const int row0 = blockIdx.x * 64;
    const int r  = tid >> 2;
    const int dq = tid & 3;
    const int row = row0 + r;

    int idx = g_idx[row];
    const float* erow = W + (size_t)idx * DDIM;
    const float* xrow = X + (size_t)row * DDIM;
    float* orow = outq + (size_t)row * DDIM;
    double csum = 0.0;
    #pragma unroll
    for (int j = 0; j < 16; j++) {
        int f4 = dq + 4 * j;
        float4 e4 = *(const float4*)(erow + 4 * f4);
        float4 x4 = *(const float4*)(xrow + 4 * f4);
        *(float4*)(orow + 4 * f4) = e4;
        float d0 = e4.x - x4.x;
        float d1 = e4.y - x4.y;
        float d2 = e4.z - x4.z;
        float d3 = e4.w - x4.w;
        csum += (double)d0 * d0 + (double)d1 * d1 + (double)d2 * d2 + (double)d3 * d3;
    }
    if (dq == 0) {
        atomicAdd(&g_hist[idx], 1);
        if (out_idx) out_idx[row] = (float)idx;
    }

    #pragma unroll
    for (int o = 16; o > 0; o >>= 1)
        csum += __shfl_xor_sync(0xffffffffu, csum, o);
    if ((tid & 31) == 0) cred[tid >> 5] = csum;
    __syncthreads();
    if (tid < 8) {
        double v = cred[tid];
        #pragma unroll
        for (int o = 4; o > 0; o >>= 1) v += __shfl_xor_sync(0xffu, v, o);
        if (tid == 0) atomicAdd(&g_commit, v);
    }
}

// ---------------- diversity loss ----------------
__global__ void __launch_bounds__(256) vq_div(const float* __restrict__ W) {
    __shared__ float si[32][68];
    __shared__ float sj[32][68];
    __shared__ double red[8];
    const int tid = threadIdx.x;
    const int ibase = (blockIdx.x & 15) * 64;
    const int jbase = (blockIdx.x >> 4) * 64;
    const int ig = tid & 15;
    const int jg = tid >> 4;

    float acc[4][4];
    #pragma unroll
    for (int i = 0; i < 4; i++)
        #pragma unroll
        for (int j = 0; j < 4; j++) acc[i][j] = 0.f;

    for (int dc = 0; dc < DDIM / 32; ++dc) {
        __syncthreads();
        #pragma unroll
        for (int t = 0; t < 2; t++) {
            int slot = tid + 256 * t;
            int c  = slot >> 3;
            int f4 = slot & 7;
            float4 v = *(const float4*)(W + (size_t)(ibase + c) * DDIM + dc * 32 + f4 * 4);
            float4 w = *(const float4*)(W + (size_t)(jbase + c) * DDIM + dc * 32 + f4 * 4);
            int d = f4 * 4;
            si[d + 0][c] = v.x; si[d + 1][c] = v.y; si[d + 2][c] = v.z; si[d + 3][c] = v.w;
            sj[d + 0][c] = w.x; sj[d + 1][c] = w.y; sj[d + 2][c] = w.z; sj[d + 3][c] = w.w;
        }
        __syncthreads();
        #pragma unroll
        for (int d = 0; d < 32; ++d) {
            float a[4], b[4];
            #pragma unroll
            for (int i = 0; i < 4; i++) a[i] = si[d][ig * 4 + i];
            #pragma unroll
            for (int j = 0; j < 4; j++) b[j] = sj[d][jg * 4 + j];
            #pragma unroll
            for (int i = 0; i < 4; i++)
                #pragma unroll
                for (int j = 0; j < 4; j++)
                    acc[i][j] = fmaf(a[i], b[j], acc[i][j]);
        }
    }

    float invi[4], invj[4];
    #pragma unroll
    for (int i = 0; i < 4; i++) invi[i] = g_invnorm[ibase + ig * 4 + i];
    #pragma unroll
    for (int j = 0; j < 4; j++) invj[j] = g_invnorm[jbase + jg * 4 + j];

    double s = 0.0;
    #pragma unroll
    for (int i = 0; i < 4; i++)
        #pragma unroll
        for (int j = 0; j < 4; j++) {
            float v = acc[i][j] * invi[i] * invj[j];
            if (ibase + ig * 4 + i == jbase + jg * 4 + j) v -= 1.0f;
            float t = fmaxf(fabsf(v), 0.1f);
            s += (double)t * (double)t;
        }

    #pragma unroll
    for (int o = 16; o > 0; o >>= 1) s += __shfl_xor_sync(0xffffffffu, s, o);
    if ((tid & 31) == 0) red[tid >> 5] = s;
    __syncthreads();
    if (tid < 8) {
        double v = red[tid];
        #pragma unroll
        for (int o = 4; o > 0; o >>= 1) v += __shfl_xor_sync(0xffu, v, o);
        if (tid == 0) atomicAdd(&g_div, v);
    }
}

// ---------------- entropy + combine ----------------
__global__ void vq_fin(float* __restrict__ out_loss) {
    __shared__ double red[32];
    int k = threadIdx.x;
    double p = (double)g_hist[k] * (1.0 / (double)NROWS);
    const double u = 1.0 / (double)KCODES;
    double term = u * (log(u) - log(p + 1e-10));
    #pragma unroll
    for (int o = 16; o > 0; o >>= 1) term += __shfl_xor_sync(0xffffffffu, term, o);
    if ((k & 31) == 0) red[k >> 5] = term;
    __syncthreads();
    if (k < 32) {
        double v = red[k];
        #pragma unroll
        for (int o = 16; o > 0; o >>= 1) v += __shfl_xor_sync(0xffffffffu, v, o);
        if (k == 0) {
            double commit = g_commit * (1.0 / ((double)NROWS * (double)DDIM));
            double divm   = g_div * (1.0 / ((double)KCODES * (double)KCODES));
            double total = 0.25 * commit + 0.5 * divm + 0.5 * v;
            if (out_loss) *out_loss = (float)total;
        }
    }
}

extern "C" void kernel_launch(void* const* d_in, const int* in_sizes, int n_in,
                              void* d_out, int out_size) {
    const float* X = (const float*)d_in[0];
    const float* W = (const float*)d_in[1];
    float* out = (float*)d_out;

    const long long Nq = (long long)NROWS * DDIM;
    float* out_loss = nullptr;
    float* out_idx  = nullptr;
    if ((long long)out_size >= Nq + 1 + NROWS) {
        out_loss = out + Nq;
        out_idx  = out + Nq + 1;
    }

    // dynamic smem: hn + X hi + W hi/lo + tournament arrays  (~107 KB)
    const int SMEM_MMA = (1024 + 128 * SSTR + 2 * CN * SSTR) * 4 + 128 * 8 + 128 * 4;
    cudaFuncSetAttribute(vq_main_mma, cudaFuncAttributeMaxDynamicSharedMemorySize, SMEM_MMA);

    vq_tr<<<KCODES, DDIM>>>(W);
    vq_pre<<<KCODES / 8, 256>>>(W);
    vq_main_mma<<<NROWS / 128, 256, SMEM_MMA>>>(X, W);
    vq_rescan2<<<2048, 256>>>(X);
    vq_fix<<<64, 256>>>();
    vq_gather<<<NROWS / 64, 256>>>(X, W, out, out_idx);
    vq_div<<<256, 256>>>(W);
    vq_fin<<<1, 1024>>>(out_loss);
}

// round 10
// speedup vs baseline: 4.4566x; 1.0702x over previous
#include <cuda_runtime.h>
#include <cuda_bf16.h>
#include <cstdint>

#define NROWS 65536
#define DDIM  256
#define KCODES 1024
#define GAP_T 0.15f   // 2-term split: omitted-term err sigma ~0.018 -> 6-sigma guard
#define SSTR 132      // smem row stride in 32-bit words (128 + 4 pad)
#define CN 16         // codes per W chunk (double-buffered)
#define BUFW (CN * SSTR)

// ---------------- device globals ----------------
__device__ int    g_hist[KCODES];
__device__ double g_commit;
__device__ double g_div;
__device__ float  g_halfnorm[KCODES];
__device__ float  g_invnorm[KCODES];
__device__ float  g_ne[KCODES];
__device__ float  g_Wt[DDIM * KCODES];
__device__ uint32_t g_Whx[KCODES * 128];   // bf16x2-packed W hi
__device__ uint32_t g_Wlx[KCODES * 128];   // bf16x2-packed W lo
__device__ int    g_idx[NROWS];
__device__ int    g_flagrows[NROWS];
__device__ int    g_nflag;
__device__ unsigned long long g_best[NROWS];

// ---------------- helpers ----------------
__device__ __forceinline__ unsigned f2o(float f) {
    unsigned b = __float_as_uint(f);
    return (b & 0x80000000u) ? ~b : (b | 0x80000000u);
}
__device__ __forceinline__ float o2f(unsigned u) {
    return (u & 0x80000000u) ? __uint_as_float(u ^ 0x80000000u) : __uint_as_float(~u);
}
__device__ __forceinline__ uint32_t smem_u32(const void* p) {
    uint32_t a;
    asm("{ .reg .u64 t; cvta.to.shared.u64 t, %1; cvt.u32.u64 %0, t; }" : "=r"(a) : "l"(p));
    return a;
}
__device__ __forceinline__ void cpa16(uint32_t dst, const void* src) {
    asm volatile("cp.async.cg.shared.global [%0], [%1], 16;" :: "r"(dst), "l"(src));
}
__device__ __forceinline__ void cpa_commit() {
    asm volatile("cp.async.commit_group;" ::: "memory");
}
__device__ __forceinline__ void cpa_wait1() {
    asm volatile("cp.async.wait_group 1;" ::: "memory");
}

__device__ __forceinline__ void mma_bf16(float* c, const uint32_t* a, const uint32_t* b) {
    asm volatile(
        "mma.sync.aligned.m16n8k16.row.col.f32.bf16.bf16.f32 "
        "{%0,%1,%2,%3}, {%4,%5,%6,%7}, {%8,%9}, {%0,%1,%2,%3};"
        : "+f"(c[0]), "+f"(c[1]), "+f"(c[2]), "+f"(c[3])
        : "r"(a[0]), "r"(a[1]), "r"(a[2]), "r"(a[3]), "r"(b[0]), "r"(b[1]));
}

__device__ __forceinline__ uint32_t pack_bf16x2(float lo, float hi) {
    __nv_bfloat162 t;
    t.x = __float2bfloat16(lo);
    t.y = __float2bfloat16(hi);
    return *(uint32_t*)&t;
}

// ---------------- small kernels ----------------
// transpose for rescan + bf16 hi/lo packed W for main GEMM
__global__ void vq_tr(const float* __restrict__ W) {
    int k = blockIdx.x;
    int j = threadIdx.x;   // 256
    g_Wt[j * KCODES + k] = W[(size_t)k * DDIM + j];
    if (j < 128) {
        float2 v = *(const float2*)(W + (size_t)k * DDIM + 2 * j);
        float h0 = __bfloat162float(__float2bfloat16(v.x));
        float h1 = __bfloat162float(__float2bfloat16(v.y));
        g_Whx[k * 128 + j] = pack_bf16x2(h0, h1);
        g_Wlx[k * 128 + j] = pack_bf16x2(v.x - h0, v.y - h1);
    }
}

// contracted XLA-emulated ||e||^2 + halfnorm/invnorm + init (validated R4)
__global__ void vq_pre(const float* __restrict__ W) {
    int k = blockIdx.x * 8 + (threadIdx.x >> 5);
    int lane = threadIdx.x & 31;
    if (blockIdx.x == 0 && threadIdx.x == 0) {
        g_commit = 0.0; g_div = 0.0; g_nflag = 0;
    }
    float p = 0.f;
    #pragma unroll
    for (int j = 0; j < 8; j++) {
        float v = W[(size_t)k * DDIM + lane + 32 * j];
        p = __fmaf_rn(v, v, p);
    }
    #pragma unroll
    for (int o = 16; o > 0; o >>= 1)
        p = __fadd_rn(p, __shfl_down_sync(0xffffffffu, p, o));
    if (lane == 0) {
        g_hist[k] = 0;
        g_ne[k] = p;
        g_halfnorm[k] = 0.5f * p;
        g_invnorm[k] = 1.0f / fmaxf(sqrtf(p), 1e-12f);
    }
}

// ---------------- mma.sync bf16 2-term split GEMM + top-2 ----------------
// CN=16 code chunks, cp.async double-buffered from packed bf16 W.
// 8 warps: 4(M) x 2(N); warp tile 32 rows x 8 codes; per-row top-2 via
// packed atomicMax tournaments (validated R7/R8 mechanism).
__global__ void __launch_bounds__(256, 2) vq_main_mma(
    const float* __restrict__ X, const float* __restrict__ W)
{
    extern __shared__ __align__(16) uint32_t sm[];
    float*    hn = (float*)sm;               // [1024]
    uint32_t* xh = sm + 1024;                // [128][SSTR]
    uint32_t* wh = xh + 128 * SSTR;          // [2][CN][SSTR]
    uint32_t* wl = wh + 2 * BUFW;            // [2][CN][SSTR]
    unsigned long long* pk = (unsigned long long*)(wl + 2 * BUFW);  // [128]
    unsigned* pk2 = (unsigned*)(pk + 128);                          // [128]

    const int tid  = threadIdx.x;
    const int lane = tid & 31;
    const int wid  = tid >> 5;
    const int wm   = wid >> 1;     // 0..3 : 32-row band
    const int wn   = wid & 1;      // 0..1 : 8-code band
    const int q    = lane >> 2;    // 0..7
    const int cg   = lane & 3;     // 0..3
    const int row0 = blockIdx.x * 128;

    const uint32_t whu = smem_u32(wh);
    const uint32_t wlu = smem_u32(wl);

    for (int i = tid; i < KCODES; i += 256) hn[i] = g_halfnorm[i];
    if (tid < 128) { pk[tid] = 0ull; pk2[tid] = 0u; }

    // X tile: fp32 -> bf16 hi only, padded layout
    for (int i = tid; i < 128 * 128; i += 256) {
        int r = i >> 7, w = i & 127;
        float2 v = *(const float2*)(X + (size_t)(row0 + r) * DDIM + 2 * w);
        xh[r * SSTR + w] = pack_bf16x2(__bfloat162float(__float2bfloat16(v.x)),
                                       __bfloat162float(__float2bfloat16(v.y)));
    }

    // async copy of W chunk c into buffer b (hi + lo)
    auto copy_chunk = [&](int c, int b) {
        int code0 = c * CN;
        #pragma unroll
        for (int i = tid; i < CN * 32; i += 256) {
            int r = i >> 5, f4 = i & 31;
            uint32_t doff = (uint32_t)(b * BUFW + r * SSTR + f4 * 4) * 4;
            uint32_t goff = (uint32_t)(code0 + r) * 128 + f4 * 4;
            cpa16(whu + doff, &g_Whx[goff]);
            cpa16(wlu + doff, &g_Wlx[goff]);
        }
    };

    float s1[4], s2[4];
    int   i1[4];
    #pragma unroll
    for (int s = 0; s < 4; s++) { s1[s] = -1e30f; s2[s] = -1e30f; i1[s] = 0; }

    copy_chunk(0, 0); cpa_commit();
    copy_chunk(1, 1); cpa_commit();

    for (int nc = 0; nc < KCODES / CN; nc++) {
        const int b = nc & 1;
        cpa_wait1();         // chunk nc arrived
        __syncthreads();     // visible to all threads (also covers X tile on nc=0)

        float acc[2][4];
        #pragma unroll
        for (int t = 0; t < 2; t++)
            #pragma unroll
            for (int e = 0; e < 4; e++) acc[t][e] = 0.f;

        #pragma unroll 4
        for (int ks = 0; ks < 16; ks++) {
            const int kw = ks * 8 + cg;
            uint32_t a[2][4];
            #pragma unroll
            for (int t = 0; t < 2; t++) {
                const uint32_t* p = xh + (wm * 32 + t * 16 + q) * SSTR + kw;
                a[t][0] = p[0]; a[t][1] = p[8 * SSTR];
                a[t][2] = p[4]; a[t][3] = p[8 * SSTR + 4];
            }
            const uint32_t* pbh = wh + b * BUFW + (wn * 8 + q) * SSTR + kw;
            const uint32_t* pbl = wl + b * BUFW + (wn * 8 + q) * SSTR + kw;
            uint32_t bh[2] = { pbh[0], pbh[4] };
            uint32_t bl[2] = { pbl[0], pbl[4] };
            #pragma unroll
            for (int t = 0; t < 2; t++) {
                mma_bf16(acc[t], a[t], bh);
                mma_bf16(acc[t], a[t], bl);
            }
        }

        // epilogue: score = dot - halfnorm, running top-2 per row slot
        #pragma unroll
        for (int t = 0; t < 2; t++)
            #pragma unroll
            for (int e = 0; e < 4; e++) {
                int slot = t * 2 + (e >> 1);
                int code = nc * CN + wn * 8 + cg * 2 + (e & 1);
                float sc = acc[t][e] - hn[code];
                if (sc > s1[slot]) { s2[slot] = s1[slot]; s1[slot] = sc; i1[slot] = code; }
                else if (sc > s2[slot]) s2[slot] = sc;
            }

        __syncthreads();     // all reads of buffer b done
        if (nc < KCODES / CN - 2) copy_chunk(nc + 2, b);
        cpa_commit();        // always commit (possibly empty) to keep group count aligned
    }
    __syncthreads();

    // tournament 1: per-row best (first-index tiebreak)
    #pragma unroll
    for (int s = 0; s < 4; s++) {
        int rowl = wm * 32 + s * 8 + q;
        unsigned long long p = ((unsigned long long)f2o(s1[s]) << 32) |
                               (unsigned long long)(KCODES - 1 - i1[s]);
        atomicMax(&pk[rowl], p);
    }
    __syncthreads();
    // tournament 2: per-row second-best (exclude winner's code)
    #pragma unroll
    for (int s = 0; s < 4; s++) {
        int rowl = wm * 32 + s * 8 + q;
        int winner = (KCODES - 1) - (int)(pk[rowl] & 0xffffffffu);
        float cand = (i1[s] == winner) ? s2[s] : s1[s];
        atomicMax(&pk2[rowl], f2o(cand));
    }
    __syncthreads();

    if (tid < 128) {
        unsigned long long p = pk[tid];
        int idx = (KCODES - 1) - (int)(p & 0xffffffffu);
        float b1 = o2f((unsigned)(p >> 32));
        float b2 = o2f(pk2[tid]);
        int row = row0 + tid;
        g_idx[row] = idx;
        if (b1 - b2 < GAP_T) {
            g_best[row] = 0xFFFFFFFFFFFFFFFFull;
            int pos = atomicAdd(&g_nflag, 1);
            g_flagrows[pos] = row;
        }
    }
}

// ---------------- rescan v3: 8-row batched, bit-exact (arithmetic per R4) ----------------
// Unit = (group of 8 flagged rows, 512-code half). Thread owns 2 interleaved
// code chains shared across 8 rows -> 8x W reuse. Padding rows are clamped
// duplicates (idempotent atomicMin).
__global__ void __launch_bounds__(256) vq_rescan3(const float* __restrict__ X) {
    __shared__ float xs[8][DDIM];
    __shared__ float nxs[8];
    __shared__ int   rws[8];
    const int tid = threadIdx.x;
    int n = g_nflag;
    if (n > NROWS) n = NROWS;
    if (n == 0) return;
    int nu = ((n + 7) >> 3) * 2;

    for (int u = blockIdx.x; u < nu; u += gridDim.x) {
        int g = u >> 1, h = u & 1;
        __syncthreads();   // protect previous iteration's xs/nxs
        if (tid < 8) {
            int s = g * 8 + tid;
            rws[tid] = g_flagrows[s < n ? s : n - 1];
        }
        __syncthreads();
        for (int i = tid; i < 8 * 64; i += 256) {
            int r = i >> 6, f = i & 63;
            *(float4*)&xs[r][f * 4] = *(const float4*)(X + (size_t)rws[r] * DDIM + f * 4);
        }
        __syncthreads();
        {   // emulated nx per row (warp w -> row w)
            int w = tid >> 5, lane = tid & 31;
            float p = 0.f;
            #pragma unroll
            for (int j = 0; j < 8; j++) {
                float v = xs[w][lane + 32 * j];
                p = __fmaf_rn(v, v, p);
            }
            #pragma unroll
            for (int o = 16; o > 0; o >>= 1)
                p = __fadd_rn(p, __shfl_down_sync(0xffffffffu, p, o));
            if (lane == 0) nxs[w] = p;
        }
        __syncthreads();

        const int k0 = h * 512 + tid;
        float a[8][2];
        #pragma unroll
        for (int r = 0; r < 8; r++) { a[r][0] = 0.f; a[r][1] = 0.f; }
        const float* w0 = g_Wt + k0;
        #pragma unroll 4
        for (int j = 0; j < DDIM; j++) {
            float wv0 = w0[(size_t)j * KCODES];
            float wv1 = w0[(size_t)j * KCODES + 256];
            #pragma unroll
            for (int r = 0; r < 8; r++) {
                float x = xs[r][j];
                a[r][0] = __fmaf_rn(x, wv0, a[r][0]);
                a[r][1] = __fmaf_rn(x, wv1, a[r][1]);
            }
        }
        float ne0 = g_ne[k0], ne1 = g_ne[k0 + 256];
        #pragma unroll
        for (int r = 0; r < 8; r++) {
            float d0 = __fadd_rn(__fmaf_rn(a[r][0], -2.0f, nxs[r]), ne0);
            float d1 = __fadd_rn(__fmaf_rn(a[r][1], -2.0f, nxs[r]), ne1);
            unsigned long long p0 = ((unsigned long long)f2o(d0) << 32) | (unsigned)k0;
            unsigned long long p1 = ((unsigned long long)f2o(d1) << 32) | (unsigned)(k0 + 256);
            atomicMin(&g_best[rws[r]], p0 < p1 ? p0 : p1);
        }
    }
}

// write winning indices for flagged rows
__global__ void vq_fix() {
    int n = g_nflag;
    if (n > NROWS) n = NROWS;
    for (int u = blockIdx.x * blockDim.x + threadIdx.x; u < n; u += gridDim.x * blockDim.x) {
        int row = g_flagrows[u];
        g_idx[row] = (int)(g_best[row] & 0xffffffffu);
    }
}

// ---------------- gather + commitment + histogram ----------------
__global__ void __launch_bounds__(256) vq_gather(
    const float* __restrict__ X, const float* __restrict__ W,
    float* __restrict__ outq, float* __restrict__ out_idx)
{
    __shared__ double cred[8];
    const int tid = threadIdx.x;
    const int row0 = blockIdx.x * 64;
    const int r  = tid >> 2;
    const int dq = tid & 3;
    const int row = row0 + r;

    int idx = g_idx[row];
    const float* erow = W + (size_t)idx * DDIM;
    const float* xrow = X + (size_t)row * DDIM;
    float* orow = outq + (size_t)row * DDIM;
    double csum = 0.0;
    #pragma unroll
    for (int j = 0; j < 16; j++) {
        int f4 = dq + 4 * j;
        float4 e4 = *(const float4*)(erow + 4 * f4);
        float4 x4 = *(const float4*)(xrow + 4 * f4);
        *(float4*)(orow + 4 * f4) = e4;
        float d0 = e4.x - x4.x;
        float d1 = e4.y - x4.y;
        float d2 = e4.z - x4.z;
        float d3 = e4.w - x4.w;
        csum += (double)d0 * d0 + (double)d1 * d1 + (double)d2 * d2 + (double)d3 * d3;
    }
    if (dq == 0) {
        atomicAdd(&g_hist[idx], 1);
        if (out_idx) out_idx[row] = (float)idx;
    }

    #pragma unroll
    for (int o = 16; o > 0; o >>= 1)
        csum += __shfl_xor_sync(0xffffffffu, csum, o);
    if ((tid & 31) == 0) cred[tid >> 5] = csum;
    __syncthreads();
    if (tid < 8) {
        double v = cred[tid];
        #pragma unroll
        for (int o = 4; o > 0; o >>= 1) v += __shfl_xor_sync(0xffu, v, o);
        if (tid == 0) atomicAdd(&g_commit, v);
    }
}

// ---------------- diversity loss ----------------
__global__ void __launch_bounds__(256) vq_div(const float* __restrict__ W) {
    __shared__ float si[32][68];
    __shared__ float sj[32][68];
    __shared__ double red[8];
    const int tid = threadIdx.x;
    const int ibase = (blockIdx.x & 15) * 64;
    const int jbase = (blockIdx.x >> 4) * 64;
    const int ig = tid & 15;
    const int jg = tid >> 4;

    float acc[4][4];
    #pragma unroll
    for (int i = 0; i < 4; i++)
        #pragma unroll
        for (int j = 0; j < 4; j++) acc[i][j] = 0.f;

    for (int dc = 0; dc < DDIM / 32; ++dc) {
        __syncthreads();
        #pragma unroll
        for (int t = 0; t < 2; t++) {
            int slot = tid + 256 * t;
            int c  = slot >> 3;
            int f4 = slot & 7;
            float4 v = *(const float4*)(W + (size_t)(ibase + c) * DDIM + dc * 32 + f4 * 4);
            float4 w = *(const float4*)(W + (size_t)(jbase + c) * DDIM + dc * 32 + f4 * 4);
            int d = f4 * 4;
            si[d + 0][c] = v.x; si[d + 1][c] = v.y; si[d + 2][c] = v.z; si[d + 3][c] = v.w;
            sj[d + 0][c] = w.x; sj[d + 1][c] = w.y; sj[d + 2][c] = w.z; sj[d + 3][c] = w.w;
        }
        __syncthreads();
        #pragma unroll
        for (int d = 0; d < 32; ++d) {
            float a[4], b[4];
            #pragma unroll
            for (int i = 0; i < 4; i++) a[i] = si[d][ig * 4 + i];
            #pragma unroll
            for (int j = 0; j < 4; j++) b[j] = sj[d][jg * 4 + j];
            #pragma unroll
            for (int i = 0; i < 4; i++)
                #pragma unroll
                for (int j = 0; j < 4; j++)
                    acc[i][j] = fmaf(a[i], b[j], acc[i][j]);
        }
    }

    float invi[4], invj[4];
    #pragma unroll
    for (int i = 0; i < 4; i++) invi[i] = g_invnorm[ibase + ig * 4 + i];
    #pragma unroll
    for (int j = 0; j < 4; j++) invj[j] = g_invnorm[jbase + jg * 4 + j];

    double s = 0.0;
    #pragma unroll
    for (int i = 0; i < 4; i++)
        #pragma unroll
        for (int j = 0; j < 4; j++) {
            float v = acc[i][j] * invi[i] * invj[j];
            if (ibase + ig * 4 + i == jbase + jg * 4 + j) v -= 1.0f;
            float t = fmaxf(fabsf(v), 0.1f);
            s += (double)t * (double)t;
        }

    #pragma unroll
    for (int o = 16; o > 0; o >>= 1) s += __shfl_xor_sync(0xffffffffu, s, o);
    if ((tid & 31) == 0) red[tid >> 5] = s;
    __syncthreads();
    if (tid < 8) {
        double v = red[tid];
        #pragma unroll
        for (int o = 4; o > 0; o >>= 1) v += __shfl_xor_sync(0xffu, v, o);
        if (tid == 0) atomicAdd(&g_div, v);
    }
}

// ---------------- entropy + combine ----------------
__global__ void vq_fin(float* __restrict__ out_loss) {
    __shared__ double red[32];
    int k = threadIdx.x;
    double p = (double)g_hist[k] * (1.0 / (double)NROWS);
    const double u = 1.0 / (double)KCODES;
    double term = u * (log(u) - log(p + 1e-10));
    #pragma unroll
    for (int o = 16; o > 0; o >>= 1) term += __shfl_xor_sync(0xffffffffu, term, o);
    if ((k & 31) == 0) red[k >> 5] = term;
    __syncthreads();
    if (k < 32) {
        double v = red[k];
        #pragma unroll
        for (int o = 16; o > 0; o >>= 1) v += __shfl_xor_sync(0xffffffffu, v, o);
        if (k == 0) {
            double commit = g_commit * (1.0 / ((double)NROWS * (double)DDIM));
            double divm   = g_div * (1.0 / ((double)KCODES * (double)KCODES));
            double total = 0.25 * commit + 0.5 * divm + 0.5 * v;
            if (out_loss) *out_loss = (float)total;
        }
    }
}

extern "C" void kernel_launch(void* const* d_in, const int* in_sizes, int n_in,
                              void* d_out, int out_size) {
    const float* X = (const float*)d_in[0];
    const float* W = (const float*)d_in[1];
    float* out = (float*)d_out;

    const long long Nq = (long long)NROWS * DDIM;
    float* out_loss = nullptr;
    float* out_idx  = nullptr;
    if ((long long)out_size >= Nq + 1 + NROWS) {
        out_loss = out + Nq;
        out_idx  = out + Nq + 1;
    }

    // dynamic smem: hn + X hi + 2x double-buffered W hi/lo + tournaments (~107 KB)
    const int SMEM_MMA = (1024 + 128 * SSTR + 4 * BUFW) * 4 + 128 * 8 + 128 * 4;
    cudaFuncSetAttribute(vq_main_mma, cudaFuncAttributeMaxDynamicSharedMemorySize, SMEM_MMA);

    vq_tr<<<KCODES, DDIM>>>(W);
    vq_pre<<<KCODES / 8, 256>>>(W);
    vq_main_mma<<<NROWS / 128, 256, SMEM_MMA>>>(X, W);
    vq_rescan3<<<1024, 256>>>(X);
    vq_fix<<<64, 256>>>();
    vq_gather<<<NROWS / 64, 256>>>(X, W, out, out_idx);
    vq_div<<<256, 256>>>(W);
    vq_fin<<<1, 1024>>>(out_loss);
}

// round 11
// speedup vs baseline: 4.6186x; 1.0364x over previous
#include <cuda_runtime.h>
#include <cuda_bf16.h>
#include <cstdint>

#define NROWS 65536
#define DDIM  256
#define KCODES 1024
#define GAP_T 0.15f   // 2-term split: omitted-term err sigma ~0.018 -> 6-sigma guard
#define SSTR 132      // smem row stride in 32-bit words (128 + 4 pad)
#define CN 32         // codes per W chunk (double-buffered)
#define BM 64         // rows per CTA
#define BUFW (CN * SSTR)

// ---------------- device globals ----------------
__device__ int    g_hist[KCODES];
__device__ double g_commit;
__device__ double g_div;
__device__ float  g_halfnorm[KCODES];
__device__ float  g_invnorm[KCODES];
__device__ float  g_ne[KCODES];
__device__ float  g_Wt[DDIM * KCODES];
__device__ uint32_t g_Whx[KCODES * 128];   // bf16x2-packed W hi
__device__ uint32_t g_Wlx[KCODES * 128];   // bf16x2-packed W lo
__device__ int    g_idx[NROWS];
__device__ int    g_flagrows[NROWS];
__device__ int    g_nflag;
__device__ unsigned long long g_best[NROWS];

// ---------------- helpers ----------------
__device__ __forceinline__ unsigned f2o(float f) {
    unsigned b = __float_as_uint(f);
    return (b & 0x80000000u) ? ~b : (b | 0x80000000u);
}
__device__ __forceinline__ float o2f(unsigned u) {
    return (u & 0x80000000u) ? __uint_as_float(u ^ 0x80000000u) : __uint_as_float(~u);
}
__device__ __forceinline__ uint32_t smem_u32(const void* p) {
    uint32_t a;
    asm("{ .reg .u64 t; cvta.to.shared.u64 t, %1; cvt.u32.u64 %0, t; }" : "=r"(a) : "l"(p));
    return a;
}
__device__ __forceinline__ void cpa16(uint32_t dst, const void* src) {
    asm volatile("cp.async.cg.shared.global [%0], [%1], 16;" :: "r"(dst), "l"(src));
}
__device__ __forceinline__ void cpa_commit() {
    asm volatile("cp.async.commit_group;" ::: "memory");
}
__device__ __forceinline__ void cpa_wait1() {
    asm volatile("cp.async.wait_group 1;" ::: "memory");
}

__device__ __forceinline__ void mma_bf16(float* c, const uint32_t* a, const uint32_t* b) {
    asm volatile(
        "mma.sync.aligned.m16n8k16.row.col.f32.bf16.bf16.f32 "
        "{%0,%1,%2,%3}, {%4,%5,%6,%7}, {%8,%9}, {%0,%1,%2,%3};"
        : "+f"(c[0]), "+f"(c[1]), "+f"(c[2]), "+f"(c[3])
        : "r"(a[0]), "r"(a[1]), "r"(a[2]), "r"(a[3]), "r"(b[0]), "r"(b[1]));
}

__device__ __forceinline__ uint32_t pack_bf16x2(float lo, float hi) {
    __nv_bfloat162 t;
    t.x = __float2bfloat16(lo);
    t.y = __float2bfloat16(hi);
    return *(uint32_t*)&t;
}

// ---------------- small kernels ----------------
// coalesced tiled transpose: g_Wt[j][k] = W[k][j]
__global__ void vq_tr(const float* __restrict__ W) {
    __shared__ float ts[32][33];
    const int tid = threadIdx.x;          // 256 = 32x8
    const int tx = tid & 31, ty = tid >> 5;
    const int kb = (blockIdx.x & 31) * 32;     // 32 k-tiles
    const int jb = (blockIdx.x >> 5) * 32;     // 8 j-tiles
    #pragma unroll
    for (int dy = 0; dy < 4; dy++) {
        int k = kb + ty + 8 * dy;
        ts[ty + 8 * dy][tx] = W[(size_t)k * DDIM + jb + tx];
    }
    __syncthreads();
    #pragma unroll
    for (int dy = 0; dy < 4; dy++) {
        int j = jb + ty + 8 * dy;
        g_Wt[(size_t)j * KCODES + kb + tx] = ts[tx][ty + 8 * dy];
    }
}

// contracted XLA-emulated ||e||^2 + halfnorm/invnorm + packed bf16 W + init
__global__ void vq_pre(const float* __restrict__ W) {
    int k = blockIdx.x * 8 + (threadIdx.x >> 5);
    int lane = threadIdx.x & 31;
    if (blockIdx.x == 0 && threadIdx.x == 0) {
        g_commit = 0.0; g_div = 0.0; g_nflag = 0;
    }
    float p = 0.f;
    #pragma unroll
    for (int j = 0; j < 8; j++) {
        float v = W[(size_t)k * DDIM + lane + 32 * j];
        p = __fmaf_rn(v, v, p);
    }
    #pragma unroll
    for (int o = 16; o > 0; o >>= 1)
        p = __fadd_rn(p, __shfl_down_sync(0xffffffffu, p, o));
    if (lane == 0) {
        g_hist[k] = 0;
        g_ne[k] = p;
        g_halfnorm[k] = 0.5f * p;
        g_invnorm[k] = 1.0f / fmaxf(sqrtf(p), 1e-12f);
    }
    // packed bf16 hi/lo W
    #pragma unroll
    for (int t = 0; t < 4; t++) {
        int w = lane + 32 * t;
        float2 v = *(const float2*)(W + (size_t)k * DDIM + 2 * w);
        float h0 = __bfloat162float(__float2bfloat16(v.x));
        float h1 = __bfloat162float(__float2bfloat16(v.y));
        g_Whx[k * 128 + w] = pack_bf16x2(h0, h1);
        g_Wlx[k * 128 + w] = pack_bf16x2(v.x - h0, v.y - h1);
    }
}

// ---------------- mma.sync bf16 2-term split GEMM + top-2 ----------------
// 64-row CTA, CN=32 code chunks double-buffered via cp.async from packed W.
// 8 warps: 4(M bands of 16 rows) x 2(N bands of 16 codes); warp tile
// 16x16 = 1 m16 x 2 n8, terms Ah*Bh + Ah*Bl. ~106 KB smem -> 2 CTAs/SM.
__global__ void __launch_bounds__(256, 2) vq_main_mma(const float* __restrict__ X)
{
    extern __shared__ __align__(16) uint32_t sm[];
    float*    hn = (float*)sm;               // [1024]
    uint32_t* xh = sm + 1024;                // [64][SSTR]
    uint32_t* wh = xh + BM * SSTR;           // [2][CN][SSTR]
    uint32_t* wl = wh + 2 * BUFW;            // [2][CN][SSTR]
    unsigned long long* pk = (unsigned long long*)(wl + 2 * BUFW);  // [64]
    unsigned* pk2 = (unsigned*)(pk + BM);                           // [64]

    const int tid  = threadIdx.x;
    const int lane = tid & 31;
    const int wid  = tid >> 5;
    const int wm   = wid >> 1;     // 0..3 : 16-row band
    const int wn   = wid & 1;      // 0..1 : 16-code band
    const int q    = lane >> 2;    // 0..7
    const int cg   = lane & 3;     // 0..3
    const int row0 = blockIdx.x * BM;

    const uint32_t whu = smem_u32(wh);
    const uint32_t wlu = smem_u32(wl);

    for (int i = tid; i < KCODES; i += 256) hn[i] = g_halfnorm[i];
    if (tid < BM) { pk[tid] = 0ull; pk2[tid] = 0u; }

    // X tile: fp32 -> bf16 hi only, padded layout
    for (int i = tid; i < BM * 128; i += 256) {
        int r = i >> 7, w = i & 127;
        float2 v = *(const float2*)(X + (size_t)(row0 + r) * DDIM + 2 * w);
        xh[r * SSTR + w] = pack_bf16x2(__bfloat162float(__float2bfloat16(v.x)),
                                       __bfloat162float(__float2bfloat16(v.y)));
    }

    // async copy of W chunk c into buffer b (hi + lo)
    auto copy_chunk = [&](int c, int b) {
        int code0 = c * CN;
        #pragma unroll
        for (int i = tid; i < CN * 32; i += 256) {
            int r = i >> 5, f4 = i & 31;
            uint32_t doff = (uint32_t)(b * BUFW + r * SSTR + f4 * 4) * 4;
            uint32_t goff = (uint32_t)(code0 + r) * 128 + f4 * 4;
            cpa16(whu + doff, &g_Whx[goff]);
            cpa16(wlu + doff, &g_Wlx[goff]);
        }
    };

    float s1[2], s2[2];
    int   i1[2];
    #pragma unroll
    for (int s = 0; s < 2; s++) { s1[s] = -1e30f; s2[s] = -1e30f; i1[s] = 0; }

    copy_chunk(0, 0); cpa_commit();
    copy_chunk(1, 1); cpa_commit();

    for (int nc = 0; nc < KCODES / CN; nc++) {
        const int b = nc & 1;
        cpa_wait1();         // chunk nc arrived
        __syncthreads();     // visible to all threads (covers X tile on nc=0)

        float acc[2][4];
        #pragma unroll
        for (int u = 0; u < 2; u++)
            #pragma unroll
            for (int e = 0; e < 4; e++) acc[u][e] = 0.f;

        #pragma unroll 4
        for (int ks = 0; ks < 16; ks++) {
            const int kw = ks * 8 + cg;
            const uint32_t* pa = xh + (wm * 16 + q) * SSTR + kw;
            uint32_t a[4] = { pa[0], pa[8 * SSTR], pa[4], pa[8 * SSTR + 4] };
            #pragma unroll
            for (int u = 0; u < 2; u++) {
                const uint32_t* pbh = wh + b * BUFW + (wn * 16 + u * 8 + q) * SSTR + kw;
                const uint32_t* pbl = wl + b * BUFW + (wn * 16 + u * 8 + q) * SSTR + kw;
                uint32_t bh[2] = { pbh[0], pbh[4] };
                uint32_t bl[2] = { pbl[0], pbl[4] };
                mma_bf16(acc[u], a, bh);
                mma_bf16(acc[u], a, bl);
            }
        }

        __syncthreads();     // all reads of buffer b done
        if (nc < KCODES / CN - 2) copy_chunk(nc + 2, b);
        cpa_commit();        // always commit to keep group count aligned

        // epilogue overlaps with copy flight: registers + hn only
        #pragma unroll
        for (int u = 0; u < 2; u++)
            #pragma unroll
            for (int e = 0; e < 4; e++) {
                int slot = e >> 1;
                int code = nc * CN + wn * 16 + u * 8 + cg * 2 + (e & 1);
                float sc = acc[u][e] - hn[code];
                if (sc > s1[slot]) { s2[slot] = s1[slot]; s1[slot] = sc; i1[slot] = code; }
                else if (sc > s2[slot]) s2[slot] = sc;
            }
    }
    __syncthreads();

    // tournament 1: per-row best (first-index tiebreak)
    #pragma unroll
    for (int s = 0; s < 2; s++) {
        int rowl = wm * 16 + s * 8 + q;
        unsigned long long p = ((unsigned long long)f2o(s1[s]) << 32) |
                               (unsigned long long)(KCODES - 1 - i1[s]);
        atomicMax(&pk[rowl], p);
    }
    __syncthreads();
    // tournament 2: per-row second-best (exclude winner's code)
    #pragma unroll
    for (int s = 0; s < 2; s++) {
        int rowl = wm * 16 + s * 8 + q;
        int winner = (KCODES - 1) - (int)(pk[rowl] & 0xffffffffu);
        float cand = (i1[s] == winner) ? s2[s] : s1[s];
        atomicMax(&pk2[rowl], f2o(cand));
    }
    __syncthreads();

    if (tid < BM) {
        unsigned long long p = pk[tid];
        int idx = (KCODES - 1) - (int)(p & 0xffffffffu);
        float b1 = o2f((unsigned)(p >> 32));
        float b2 = o2f(pk2[tid]);
        int row = row0 + tid;
        g_idx[row] = idx;
        if (b1 - b2 < GAP_T) {
            g_best[row] = 0xFFFFFFFFFFFFFFFFull;
            int pos = atomicAdd(&g_nflag, 1);
            g_flagrows[pos] = row;
        }
    }
}

// ---------------- rescan v3: 8-row batched, bit-exact (validated R10) ----------------
__global__ void __launch_bounds__(256) vq_rescan3(const float* __restrict__ X) {
    __shared__ float xs[8][DDIM];
    __shared__ float nxs[8];
    __shared__ int   rws[8];
    const int tid = threadIdx.x;
    int n = g_nflag;
    if (n > NROWS) n = NROWS;
    if (n == 0) return;
    int nu = ((n + 7) >> 3) * 2;

    for (int u = blockIdx.x; u < nu; u += gridDim.x) {
        int g = u >> 1, h = u & 1;
        __syncthreads();   // protect previous iteration's xs/nxs
        if (tid < 8) {
            int s = g * 8 + tid;
            rws[tid] = g_flagrows[s < n ? s : n - 1];
        }
        __syncthreads();
        for (int i = tid; i < 8 * 64; i += 256) {
            int r = i >> 6, f = i & 63;
            *(float4*)&xs[r][f * 4] = *(const float4*)(X + (size_t)rws[r] * DDIM + f * 4);
        }
        __syncthreads();
        {   // emulated nx per row (warp w -> row w)
            int w = tid >> 5, lane = tid & 31;
            float p = 0.f;
            #pragma unroll
            for (int j = 0; j < 8; j++) {
                float v = xs[w][lane + 32 * j];
                p = __fmaf_rn(v, v, p);
            }
            #pragma unroll
            for (int o = 16; o > 0; o >>= 1)
                p = __fadd_rn(p, __shfl_down_sync(0xffffffffu, p, o));
            if (lane == 0) nxs[w] = p;
        }
        __syncthreads();

        const int k0 = h * 512 + tid;
        float a[8][2];
        #pragma unroll
        for (int r = 0; r < 8; r++) { a[r][0] = 0.f; a[r][1] = 0.f; }
        const float* w0 = g_Wt + k0;
        #pragma unroll 4
        for (int j = 0; j < DDIM; j++) {
            float wv0 = w0[(size_t)j * KCODES];
            float wv1 = w0[(size_t)j * KCODES + 256];
            #pragma unroll
            for (int r = 0; r < 8; r++) {
                float x = xs[r][j];
                a[r][0] = __fmaf_rn(x, wv0, a[r][0]);
                a[r][1] = __fmaf_rn(x, wv1, a[r][1]);
            }
        }
        float ne0 = g_ne[k0], ne1 = g_ne[k0 + 256];
        #pragma unroll
        for (int r = 0; r < 8; r++) {
            float d0 = __fadd_rn(__fmaf_rn(a[r][0], -2.0f, nxs[r]), ne0);
            float d1 = __fadd_rn(__fmaf_rn(a[r][1], -2.0f, nxs[r]), ne1);
            unsigned long long p0 = ((unsigned long long)f2o(d0) << 32) | (unsigned)k0;
            unsigned long long p1 = ((unsigned long long)f2o(d1) << 32) | (unsigned)(k0 + 256);
            atomicMin(&g_best[rws[r]], p0 < p1 ? p0 : p1);
        }
    }
}

// write winning indices for flagged rows
__global__ void vq_fix() {
    int n = g_nflag;
    if (n > NROWS) n = NROWS;
    for (int u = blockIdx.x * blockDim.x + threadIdx.x; u < n; u += gridDim.x * blockDim.x) {
        int row = g_flagrows[u];
        g_idx[row] = (int)(g_best[row] & 0xffffffffu);
    }
}

// ---------------- gather + commitment + histogram ----------------
__global__ void __launch_bounds__(256) vq_gather(
    const float* __restrict__ X, const float* __restrict__ W,
    float* __restrict__ outq, float* __restrict__ out_idx)
{
    __shared__ double cred[8];
    const int tid = threadIdx.x;
    const int row0 = blockIdx.x * 64;
    const int r  = tid >> 2;
    const int dq = tid & 3;
    const int row = row0 + r;

    int idx = g_idx[row];
    const float* erow = W + (size_t)idx * DDIM;
    const float* xrow = X + (size_t)row * DDIM;
    float* orow = outq + (size_t)row * DDIM;
    double csum = 0.0;
    #pragma unroll
    for (int j = 0; j < 16; j++) {
        int f4 = dq + 4 * j;
        float4 e4 = *(const float4*)(erow + 4 * f4);
        float4 x4 = *(const float4*)(xrow + 4 * f4);
        *(float4*)(orow + 4 * f4) = e4;
        float d0 = e4.x - x4.x;
        float d1 = e4.y - x4.y;
        float d2 = e4.z - x4.z;
        float d3 = e4.w - x4.w;
        csum += (double)d0 * d0 + (double)d1 * d1 + (double)d2 * d2 + (double)d3 * d3;
    }
    if (dq == 0) {
        atomicAdd(&g_hist[idx], 1);
        if (out_idx) out_idx[row] = (float)idx;
    }

    #pragma unroll
    for (int o = 16; o > 0; o >>= 1)
        csum += __shfl_xor_sync(0xffffffffu, csum, o);
    if ((tid & 31) == 0) cred[tid >> 5] = csum;
    __syncthreads();
    if (tid < 8) {
        double v = cred[tid];
        #pragma unroll
        for (int o = 4; o > 0; o >>= 1) v += __shfl_xor_sync(0xffu, v, o);
        if (tid == 0) atomicAdd(&g_commit, v);
    }
}

// ---------------- diversity loss ----------------
__global__ void __launch_bounds__(256) vq_div(const float* __restrict__ W) {
    __shared__ float si[32][68];
    __shared__ float sj[32][68];
    __shared__ double red[8];
    const int tid = threadIdx.x;
    const int ibase = (blockIdx.x & 15) * 64;
    const int jbase = (blockIdx.x >> 4) * 64;
    const int ig = tid & 15;
    const int jg = tid >> 4;

    float acc[4][4];
    #pragma unroll
    for (int i = 0; i < 4; i++)
        #pragma unroll
        for (int j = 0; j < 4; j++) acc[i][j] = 0.f;

    for (int dc = 0; dc < DDIM / 32; ++dc) {
        __syncthreads();
        #pragma unroll
        for (int t = 0; t < 2; t++) {
            int slot = tid + 256 * t;
            int c  = slot >> 3;
            int f4 = slot & 7;
            float4 v = *(const float4*)(W + (size_t)(ibase + c) * DDIM + dc * 32 + f4 * 4);
            float4 w = *(const float4*)(W + (size_t)(jbase + c) * DDIM + dc * 32 + f4 * 4);
            int d = f4 * 4;
            si[d + 0][c] = v.x; si[d + 1][c] = v.y; si[d + 2][c] = v.z; si[d + 3][c] = v.w;
            sj[d + 0][c] = w.x; sj[d + 1][c] = w.y; sj[d + 2][c] = w.z; sj[d + 3][c] = w.w;
        }
        __syncthreads();
        #pragma unroll
        for (int d = 0; d < 32; ++d) {
            float a[4], b[4];
            #pragma unroll
            for (int i = 0; i < 4; i++) a[i] = si[d][ig * 4 + i];
            #pragma unroll
            for (int j = 0; j < 4; j++) b[j] = sj[d][jg * 4 + j];
            #pragma unroll
            for (int i = 0; i < 4; i++)
                #pragma unroll
                for (int j = 0; j < 4; j++)
                    acc[i][j] = fmaf(a[i], b[j], acc[i][j]);
        }
    }

    float invi[4], invj[4];
    #pragma unroll
    for (int i = 0; i < 4; i++) invi[i] = g_invnorm[ibase + ig * 4 + i];
    #pragma unroll
    for (int j = 0; j < 4; j++) invj[j] = g_invnorm[jbase + jg * 4 + j];

    double s = 0.0;
    #pragma unroll
    for (int i = 0; i < 4; i++)
        #pragma unroll
        for (int j = 0; j < 4; j++) {
            float v = acc[i][j] * invi[i] * invj[j];
            if (ibase + ig * 4 + i == jbase + jg * 4 + j) v -= 1.0f;
            float t = fmaxf(fabsf(v), 0.1f);
            s += (double)t * (double)t;
        }

    #pragma unroll
    for (int o = 16; o > 0; o >>= 1) s += __shfl_xor_sync(0xffffffffu, s, o);
    if ((tid & 31) == 0) red[tid >> 5] = s;
    __syncthreads();
    if (tid < 8) {
        double v = red[tid];
        #pragma unroll
        for (int o = 4; o > 0; o >>= 1) v += __shfl_xor_sync(0xffu, v, o);
        if (tid == 0) atomicAdd(&g_div, v);
    }
}

// ---------------- entropy + combine ----------------
__global__ void vq_fin(float* __restrict__ out_loss) {
    __shared__ double red[32];
    int k = threadIdx.x;
    double p = (double)g_hist[k] * (1.0 / (double)NROWS);
    const double u = 1.0 / (double)KCODES;
    double term = u * (log(u) - log(p + 1e-10));
    #pragma unroll
    for (int o = 16; o > 0; o >>= 1) term += __shfl_xor_sync(0xffffffffu, term, o);
    if ((k & 31) == 0) red[k >> 5] = term;
    __syncthreads();
    if (k < 32) {
        double v = red[k];
        #pragma unroll
        for (int o = 16; o > 0; o >>= 1) v += __shfl_xor_sync(0xffffffffu, v, o);
        if (k == 0) {
            double commit = g_commit * (1.0 / ((double)NROWS * (double)DDIM));
            double divm   = g_div * (1.0 / ((double)KCODES * (double)KCODES));
            double total = 0.25 * commit + 0.5 * divm + 0.5 * v;
            if (out_loss) *out_loss = (float)total;
        }
    }
}

extern "C" void kernel_launch(void* const* d_in, const int* in_sizes, int n_in,
                              void* d_out, int out_size) {
    const float* X = (const float*)d_in[0];
    const float* W = (const float*)d_in[1];
    float* out = (float*)d_out;

    const long long Nq = (long long)NROWS * DDIM;
    float* out_loss = nullptr;
    float* out_idx  = nullptr;
    if ((long long)out_size >= Nq + 1 + NROWS) {
        out_loss = out + Nq;
        out_idx  = out + Nq + 1;
    }

    // dynamic smem: hn + X hi (64 rows) + 2x double-buffered W hi/lo + tournaments (~106 KB)
    const int SMEM_MMA = (1024 + BM * SSTR + 4 * BUFW) * 4 + BM * 8 + BM * 4;
    cudaFuncSetAttribute(vq_main_mma, cudaFuncAttributeMaxDynamicSharedMemorySize, SMEM_MMA);

    vq_tr<<<256, 256>>>(W);
    vq_pre<<<KCODES / 8, 256>>>(W);
    vq_main_mma<<<NROWS / BM, 256, SMEM_MMA>>>(X);
    vq_rescan3<<<1024, 256>>>(X);
    vq_fix<<<64, 256>>>();
    vq_gather<<<NROWS / 64, 256>>>(X, W, out, out_idx);
    vq_div<<<256, 256>>>(W);
    vq_fin<<<1, 1024>>>(out_loss);
}

// round 12
// speedup vs baseline: 4.6503x; 1.0069x over previous
#include <cuda_runtime.h>
#include <cuda_bf16.h>
#include <cstdint>

#define NROWS 65536
#define DDIM  256
#define KCODES 1024
#define GAP_T 0.15f   // 2-term split: omitted-term err sigma ~0.018 -> 6-sigma guard
#define SSTR 132      // smem row stride in 32-bit words (128 + 4 pad)
#define CN 32         // codes per W chunk (double-buffered)
#define BM 64         // rows per CTA
#define BUFW (CN * SSTR)

// ---------------- device globals ----------------
__device__ int    g_hist[KCODES];
__device__ double g_commit;
__device__ double g_div;
__device__ float  g_halfnorm[KCODES];
__device__ float  g_invnorm[KCODES];
__device__ float  g_ne[KCODES];
__device__ float  g_Wt[DDIM * KCODES];
__device__ uint32_t g_Whx[KCODES * 128];   // bf16x2-packed W hi
__device__ uint32_t g_Wlx[KCODES * 128];   // bf16x2-packed W lo
__device__ int    g_idx[NROWS];
__device__ int    g_flagrows[NROWS];
__device__ int    g_nflag;
__device__ unsigned long long g_best[NROWS];

// ---------------- helpers ----------------
__device__ __forceinline__ unsigned f2o(float f) {
    unsigned b = __float_as_uint(f);
    return (b & 0x80000000u) ? ~b : (b | 0x80000000u);
}
__device__ __forceinline__ float o2f(unsigned u) {
    return (u & 0x80000000u) ? __uint_as_float(u ^ 0x80000000u) : __uint_as_float(~u);
}
__device__ __forceinline__ uint32_t smem_u32(const void* p) {
    uint32_t a;
    asm("{ .reg .u64 t; cvta.to.shared.u64 t, %1; cvt.u32.u64 %0, t; }" : "=r"(a) : "l"(p));
    return a;
}
__device__ __forceinline__ void cpa16(uint32_t dst, const void* src) {
    asm volatile("cp.async.cg.shared.global [%0], [%1], 16;" :: "r"(dst), "l"(src));
}
__device__ __forceinline__ void cpa_commit() {
    asm volatile("cp.async.commit_group;" ::: "memory");
}
__device__ __forceinline__ void cpa_wait1() {
    asm volatile("cp.async.wait_group 1;" ::: "memory");
}

__device__ __forceinline__ void mma_bf16(float* c, const uint32_t* a, const uint32_t* b) {
    asm volatile(
        "mma.sync.aligned.m16n8k16.row.col.f32.bf16.bf16.f32 "
        "{%0,%1,%2,%3}, {%4,%5,%6,%7}, {%8,%9}, {%0,%1,%2,%3};"
        : "+f"(c[0]), "+f"(c[1]), "+f"(c[2]), "+f"(c[3])
        : "r"(a[0]), "r"(a[1]), "r"(a[2]), "r"(a[3]), "r"(b[0]), "r"(b[1]));
}

__device__ __forceinline__ uint32_t pack_bf16x2(float lo, float hi) {
    __nv_bfloat162 t;
    t.x = __float2bfloat16(lo);
    t.y = __float2bfloat16(hi);
    return *(uint32_t*)&t;
}

// ---------------- small kernels ----------------
// coalesced tiled transpose: g_Wt[j][k] = W[k][j]
__global__ void vq_tr(const float* __restrict__ W) {
    __shared__ float ts[32][33];
    const int tid = threadIdx.x;          // 256 = 32x8
    const int tx = tid & 31, ty = tid >> 5;
    const int kb = (blockIdx.x & 31) * 32;     // 32 k-tiles
    const int jb = (blockIdx.x >> 5) * 32;     // 8 j-tiles
    #pragma unroll
    for (int dy = 0; dy < 4; dy++) {
        int k = kb + ty + 8 * dy;
        ts[ty + 8 * dy][tx] = W[(size_t)k * DDIM + jb + tx];
    }
    __syncthreads();
    #pragma unroll
    for (int dy = 0; dy < 4; dy++) {
        int j = jb + ty + 8 * dy;
        g_Wt[(size_t)j * KCODES + kb + tx] = ts[tx][ty + 8 * dy];
    }
}

// contracted XLA-emulated ||e||^2 + halfnorm/invnorm + packed bf16 W + init
__global__ void vq_pre(const float* __restrict__ W) {
    int k = blockIdx.x * 8 + (threadIdx.x >> 5);
    int lane = threadIdx.x & 31;
    if (blockIdx.x == 0 && threadIdx.x == 0) {
        g_commit = 0.0; g_div = 0.0; g_nflag = 0;
    }
    float p = 0.f;
    #pragma unroll
    for (int j = 0; j < 8; j++) {
        float v = W[(size_t)k * DDIM + lane + 32 * j];
        p = __fmaf_rn(v, v, p);
    }
    #pragma unroll
    for (int o = 16; o > 0; o >>= 1)
        p = __fadd_rn(p, __shfl_down_sync(0xffffffffu, p, o));
    if (lane == 0) {
        g_hist[k] = 0;
        g_ne[k] = p;
        g_halfnorm[k] = 0.5f * p;
        g_invnorm[k] = 1.0f / fmaxf(sqrtf(p), 1e-12f);
    }
    // packed bf16 hi/lo W
    #pragma unroll
    for (int t = 0; t < 4; t++) {
        int w = lane + 32 * t;
        float2 v = *(const float2*)(W + (size_t)k * DDIM + 2 * w);
        float h0 = __bfloat162float(__float2bfloat16(v.x));
        float h1 = __bfloat162float(__float2bfloat16(v.y));
        g_Whx[k * 128 + w] = pack_bf16x2(h0, h1);
        g_Wlx[k * 128 + w] = pack_bf16x2(v.x - h0, v.y - h1);
    }
}

// ---------------- mma.sync bf16 2-term split GEMM + top-2 ----------------
// 64-row CTA, CN=32 code chunks double-buffered via cp.async from packed W.
// 8 warps: 4(M bands of 16 rows) x 2(N bands of 16 codes); warp tile
// 16x16 = 1 m16 x 2 n8. Terms Ah*Bh / Ah*Bl kept in SEPARATE accumulators
// (4 independent HMMA chains per warp), summed in the epilogue.
// ~106 KB smem -> 2 CTAs/SM.
__global__ void __launch_bounds__(256, 2) vq_main_mma(const float* __restrict__ X)
{
    extern __shared__ __align__(16) uint32_t sm[];
    float*    hn = (float*)sm;               // [1024]
    uint32_t* xh = sm + 1024;                // [64][SSTR]
    uint32_t* wh = xh + BM * SSTR;           // [2][CN][SSTR]
    uint32_t* wl = wh + 2 * BUFW;            // [2][CN][SSTR]
    unsigned long long* pk = (unsigned long long*)(wl + 2 * BUFW);  // [64]
    unsigned* pk2 = (unsigned*)(pk + BM);                           // [64]

    const int tid  = threadIdx.x;
    const int lane = tid & 31;
    const int wid  = tid >> 5;
    const int wm   = wid >> 1;     // 0..3 : 16-row band
    const int wn   = wid & 1;      // 0..1 : 16-code band
    const int q    = lane >> 2;    // 0..7
    const int cg   = lane & 3;     // 0..3
    const int row0 = blockIdx.x * BM;

    const uint32_t whu = smem_u32(wh);
    const uint32_t wlu = smem_u32(wl);

    for (int i = tid; i < KCODES; i += 256) hn[i] = g_halfnorm[i];
    if (tid < BM) { pk[tid] = 0ull; pk2[tid] = 0u; }

    // X tile: fp32 -> bf16 hi only, padded layout
    for (int i = tid; i < BM * 128; i += 256) {
        int r = i >> 7, w = i & 127;
        float2 v = *(const float2*)(X + (size_t)(row0 + r) * DDIM + 2 * w);
        xh[r * SSTR + w] = pack_bf16x2(__bfloat162float(__float2bfloat16(v.x)),
                                       __bfloat162float(__float2bfloat16(v.y)));
    }

    // async copy of W chunk c into buffer b (hi + lo)
    auto copy_chunk = [&](int c, int b) {
        int code0 = c * CN;
        #pragma unroll
        for (int i = tid; i < CN * 32; i += 256) {
            int r = i >> 5, f4 = i & 31;
            uint32_t doff = (uint32_t)(b * BUFW + r * SSTR + f4 * 4) * 4;
            uint32_t goff = (uint32_t)(code0 + r) * 128 + f4 * 4;
            cpa16(whu + doff, &g_Whx[goff]);
            cpa16(wlu + doff, &g_Wlx[goff]);
        }
    };

    float s1[2], s2[2];
    int   i1[2];
    #pragma unroll
    for (int s = 0; s < 2; s++) { s1[s] = -1e30f; s2[s] = -1e30f; i1[s] = 0; }

    copy_chunk(0, 0); cpa_commit();
    copy_chunk(1, 1); cpa_commit();

    for (int nc = 0; nc < KCODES / CN; nc++) {
        const int b = nc & 1;
        cpa_wait1();         // chunk nc arrived
        __syncthreads();     // visible to all threads (covers X tile on nc=0)

        // 4 independent accumulator chains: [u][term]
        float acc[2][2][4];
        #pragma unroll
        for (int u = 0; u < 2; u++)
            #pragma unroll
            for (int t = 0; t < 2; t++)
                #pragma unroll
                for (int e = 0; e < 4; e++) acc[u][t][e] = 0.f;

        #pragma unroll 4
        for (int ks = 0; ks < 16; ks++) {
            const int kw = ks * 8 + cg;
            const uint32_t* pa = xh + (wm * 16 + q) * SSTR + kw;
            uint32_t a[4] = { pa[0], pa[8 * SSTR], pa[4], pa[8 * SSTR + 4] };
            #pragma unroll
            for (int u = 0; u < 2; u++) {
                const uint32_t* pbh = wh + b * BUFW + (wn * 16 + u * 8 + q) * SSTR + kw;
                const uint32_t* pbl = wl + b * BUFW + (wn * 16 + u * 8 + q) * SSTR + kw;
                uint32_t bh[2] = { pbh[0], pbh[4] };
                uint32_t bl[2] = { pbl[0], pbl[4] };
                mma_bf16(acc[u][0], a, bh);
                mma_bf16(acc[u][1], a, bl);
            }
        }

        __syncthreads();     // all reads of buffer b done
        if (nc < KCODES / CN - 2) copy_chunk(nc + 2, b);
        cpa_commit();        // always commit to keep group count aligned

        // epilogue overlaps with copy flight: registers + hn only
        #pragma unroll
        for (int u = 0; u < 2; u++)
            #pragma unroll
            for (int e = 0; e < 4; e++) {
                int slot = e >> 1;
                int code = nc * CN + wn * 16 + u * 8 + cg * 2 + (e & 1);
                float sc = acc[u][0][e] + acc[u][1][e] - hn[code];
                if (sc > s1[slot]) { s2[slot] = s1[slot]; s1[slot] = sc; i1[slot] = code; }
                else if (sc > s2[slot]) s2[slot] = sc;
            }
    }
    __syncthreads();

    // tournament 1: per-row best (first-index tiebreak)
    #pragma unroll
    for (int s = 0; s < 2; s++) {
        int rowl = wm * 16 + s * 8 + q;
        unsigned long long p = ((unsigned long long)f2o(s1[s]) << 32) |
                               (unsigned long long)(KCODES - 1 - i1[s]);
        atomicMax(&pk[rowl], p);
    }
    __syncthreads();
    // tournament 2: per-row second-best (exclude winner's code)
    #pragma unroll
    for (int s = 0; s < 2; s++) {
        int rowl = wm * 16 + s * 8 + q;
        int winner = (KCODES - 1) - (int)(pk[rowl] & 0xffffffffu);
        float cand = (i1[s] == winner) ? s2[s] : s1[s];
        atomicMax(&pk2[rowl], f2o(cand));
    }
    __syncthreads();

    if (tid < BM) {
        unsigned long long p = pk[tid];
        int idx = (KCODES - 1) - (int)(p & 0xffffffffu);
        float b1 = o2f((unsigned)(p >> 32));
        float b2 = o2f(pk2[tid]);
        int row = row0 + tid;
        g_idx[row] = idx;
        if (b1 - b2 < GAP_T) {
            g_best[row] = 0xFFFFFFFFFFFFFFFFull;
            int pos = atomicAdd(&g_nflag, 1);
            g_flagrows[pos] = row;
        }
    }
}

// ---------------- rescan v3: 8-row batched, bit-exact (validated R10) ----------------
__global__ void __launch_bounds__(256) vq_rescan3(const float* __restrict__ X) {
    __shared__ float xs[8][DDIM];
    __shared__ float nxs[8];
    __shared__ int   rws[8];
    const int tid = threadIdx.x;
    int n = g_nflag;
    if (n > NROWS) n = NROWS;
    if (n == 0) return;
    int nu = ((n + 7) >> 3) * 2;

    for (int u = blockIdx.x; u < nu; u += gridDim.x) {
        int g = u >> 1, h = u & 1;
        __syncthreads();   // protect previous iteration's xs/nxs
        if (tid < 8) {
            int s = g * 8 + tid;
            rws[tid] = g_flagrows[s < n ? s : n - 1];
        }
        __syncthreads();
        for (int i = tid; i < 8 * 64; i += 256) {
            int r = i >> 6, f = i & 63;
            *(float4*)&xs[r][f * 4] = *(const float4*)(X + (size_t)rws[r] * DDIM + f * 4);
        }
        __syncthreads();
        {   // emulated nx per row (warp w -> row w)
            int w = tid >> 5, lane = tid & 31;
            float p = 0.f;
            #pragma unroll
            for (int j = 0; j < 8; j++) {
                float v = xs[w][lane + 32 * j];
                p = __fmaf_rn(v, v, p);
            }
            #pragma unroll
            for (int o = 16; o > 0; o >>= 1)
                p = __fadd_rn(p, __shfl_down_sync(0xffffffffu, p, o));
            if (lane == 0) nxs[w] = p;
        }
        __syncthreads();

        const int k0 = h * 512 + tid;
        float a[8][2];
        #pragma unroll
        for (int r = 0; r < 8; r++) { a[r][0] = 0.f; a[r][1] = 0.f; }
        const float* w0 = g_Wt + k0;
        #pragma unroll 4
        for (int j = 0; j < DDIM; j++) {
            float wv0 = w0[(size_t)j * KCODES];
            float wv1 = w0[(size_t)j * KCODES + 256];
            #pragma unroll
            for (int r = 0; r < 8; r++) {
                float x = xs[r][j];
                a[r][0] = __fmaf_rn(x, wv0, a[r][0]);
                a[r][1] = __fmaf_rn(x, wv1, a[r][1]);
            }
        }
        float ne0 = g_ne[k0], ne1 = g_ne[k0 + 256];
        #pragma unroll
        for (int r = 0; r < 8; r++) {
            float d0 = __fadd_rn(__fmaf_rn(a[r][0], -2.0f, nxs[r]), ne0);
            float d1 = __fadd_rn(__fmaf_rn(a[r][1], -2.0f, nxs[r]), ne1);
            unsigned long long p0 = ((unsigned long long)f2o(d0) << 32) | (unsigned)k0;
            unsigned long long p1 = ((unsigned long long)f2o(d1) << 32) | (unsigned)(k0 + 256);
            atomicMin(&g_best[rws[r]], p0 < p1 ? p0 : p1);
        }
    }
}

// write winning indices for flagged rows
__global__ void vq_fix() {
    int n = g_nflag;
    if (n > NROWS) n = NROWS;
    for (int u = blockIdx.x * blockDim.x + threadIdx.x; u < n; u += gridDim.x * blockDim.x) {
        int row = g_flagrows[u];
        g_idx[row] = (int)(g_best[row] & 0xffffffffu);
    }
}

// ---------------- gather + commitment + histogram ----------------
__global__ void __launch_bounds__(256) vq_gather(
    const float* __restrict__ X, const float* __restrict__ W,
    float* __restrict__ outq, float* __restrict__ out_idx)
{
    __shared__ double cred[8];
    const int tid = threadIdx.x;
    const int row0 = blockIdx.x * 64;
    const int r  = tid >> 2;
    const int dq = tid & 3;
    const int row = row0 + r;

    int idx = g_idx[row];
    const float* erow = W + (size_t)idx * DDIM;
    const float* xrow = X + (size_t)row * DDIM;
    float* orow = outq + (size_t)row * DDIM;
    double csum = 0.0;
    #pragma unroll
    for (int j = 0; j < 16; j++) {
        int f4 = dq + 4 * j;
        float4 e4 = *(const float4*)(erow + 4 * f4);
        float4 x4 = *(const float4*)(xrow + 4 * f4);
        *(float4*)(orow + 4 * f4) = e4;
        float d0 = e4.x - x4.x;
        float d1 = e4.y - x4.y;
        float d2 = e4.z - x4.z;
        float d3 = e4.w - x4.w;
        csum += (double)d0 * d0 + (double)d1 * d1 + (double)d2 * d2 + (double)d3 * d3;
    }
    if (dq == 0) {
        atomicAdd(&g_hist[idx], 1);
        if (out_idx) out_idx[row] = (float)idx;
    }

    #pragma unroll
    for (int o = 16; o > 0; o >>= 1)
        csum += __shfl_xor_sync(0xffffffffu, csum, o);
    if ((tid & 31) == 0) cred[tid >> 5] = csum;
    __syncthreads();
    if (tid < 8) {
        double v = cred[tid];
        #pragma unroll
        for (int o = 4; o > 0; o >>= 1) v += __shfl_xor_sync(0xffu, v, o);
        if (tid == 0) atomicAdd(&g_commit, v);
    }
}

// ---------------- diversity loss ----------------
__global__ void __launch_bounds__(256) vq_div(const float* __restrict__ W) {
    __shared__ float si[32][68];
    __shared__ float sj[32][68];
    __shared__ double red[8];
    const int tid = threadIdx.x;
    const int ibase = (blockIdx.x & 15) * 64;
    const int jbase = (blockIdx.x >> 4) * 64;
    const int ig = tid & 15;
    const int jg = tid >> 4;

    float acc[4][4];
    #pragma unroll
    for (int i = 0; i < 4; i++)
        #pragma unroll
        for (int j = 0; j < 4; j++) acc[i][j] = 0.f;

    for (int dc = 0; dc < DDIM / 32; ++dc) {
        __syncthreads();
        #pragma unroll
        for (int t = 0; t < 2; t++) {
            int slot = tid + 256 * t;
            int c  = slot >> 3;
            int f4 = slot & 7;
            float4 v = *(const float4*)(W + (size_t)(ibase + c) * DDIM + dc * 32 + f4 * 4);
            float4 w = *(const float4*)(W + (size_t)(jbase + c) * DDIM + dc * 32 + f4 * 4);
            int d = f4 * 4;
            si[d + 0][c] = v.x; si[d + 1][c] = v.y; si[d + 2][c] = v.z; si[d + 3][c] = v.w;
            sj[d + 0][c] = w.x; sj[d + 1][c] = w.y; sj[d + 2][c] = w.z; sj[d + 3][c] = w.w;
        }
        __syncthreads();
        #pragma unroll
        for (int d = 0; d < 32; ++d) {
            float a[4], b[4];
            #pragma unroll
            for (int i = 0; i < 4; i++) a[i] = si[d][ig * 4 + i];
            #pragma unroll
            for (int j = 0; j < 4; j++) b[j] = sj[d][jg * 4 + j];
            #pragma unroll
            for (int i = 0; i < 4; i++)
                #pragma unroll
                for (int j = 0; j < 4; j++)
                    acc[i][j] = fmaf(a[i], b[j], acc[i][j]);
        }
    }

    float invi[4], invj[4];
    #pragma unroll
    for (int i = 0; i < 4; i++) invi[i] = g_invnorm[ibase + ig * 4 + i];
    #pragma unroll
    for (int j = 0; j < 4; j++) invj[j] = g_invnorm[jbase + jg * 4 + j];

    double s = 0.0;
    #pragma unroll
    for (int i = 0; i < 4; i++)
        #pragma unroll
        for (int j = 0; j < 4; j++) {
            float v = acc[i][j] * invi[i] * invj[j];
            if (ibase + ig * 4 + i == jbase + jg * 4 + j) v -= 1.0f;
            float t = fmaxf(fabsf(v), 0.1f);
            s += (double)t * (double)t;
        }

    #pragma unroll
    for (int o = 16; o > 0; o >>= 1) s += __shfl_xor_sync(0xffffffffu, s, o);
    if ((tid & 31) == 0) red[tid >> 5] = s;
    __syncthreads();
    if (tid < 8) {
        double v = red[tid];
        #pragma unroll
        for (int o = 4; o > 0; o >>= 1) v += __shfl_xor_sync(0xffu, v, o);
        if (tid == 0) atomicAdd(&g_div, v);
    }
}

// ---------------- entropy + combine ----------------
__global__ void vq_fin(float* __restrict__ out_loss) {
    __shared__ double red[32];
    int k = threadIdx.x;
    double p = (double)g_hist[k] * (1.0 / (double)NROWS);
    const double u = 1.0 / (double)KCODES;
    double term = u * (log(u) - log(p + 1e-10));
    #pragma unroll
    for (int o = 16; o > 0; o >>= 1) term += __shfl_xor_sync(0xffffffffu, term, o);
    if ((k & 31) == 0) red[k >> 5] = term;
    __syncthreads();
    if (k < 32) {
        double v = red[k];
        #pragma unroll
        for (int o = 16; o > 0; o >>= 1) v += __shfl_xor_sync(0xffffffffu, v, o);
        if (k == 0) {
            double commit = g_commit * (1.0 / ((double)NROWS * (double)DDIM));
            double divm   = g_div * (1.0 / ((double)KCODES * (double)KCODES));
            double total = 0.25 * commit + 0.5 * divm + 0.5 * v;
            if (out_loss) *out_loss = (float)total;
        }
    }
}

extern "C" void kernel_launch(void* const* d_in, const int* in_sizes, int n_in,
                              void* d_out, int out_size) {
    const float* X = (const float*)d_in[0];
    const float* W = (const float*)d_in[1];
    float* out = (float*)d_out;

    const long long Nq = (long long)NROWS * DDIM;
    float* out_loss = nullptr;
    float* out_idx  = nullptr;
    if ((long long)out_size >= Nq + 1 + NROWS) {
        out_loss = out + Nq;
        out_idx  = out + Nq + 1;
    }

    // dynamic smem: hn + X hi (64 rows) + 2x double-buffered W hi/lo + tournaments (~106 KB)
    const int SMEM_MMA = (1024 + BM * SSTR + 4 * BUFW) * 4 + BM * 8 + BM * 4;
    cudaFuncSetAttribute(vq_main_mma, cudaFuncAttributeMaxDynamicSharedMemorySize, SMEM_MMA);

    vq_tr<<<256, 256>>>(W);
    vq_pre<<<KCODES / 8, 256>>>(W);
    vq_main_mma<<<NROWS / BM, 256, SMEM_MMA>>>(X);
    vq_rescan3<<<1024, 256>>>(X);
    vq_fix<<<64, 256>>>();
    vq_gather<<<NROWS / 64, 256>>>(X, W, out, out_idx);
    vq_div<<<256, 256>>>(W);
    vq_fin<<<1, 1024>>>(out_loss);
}

// round 13
// speedup vs baseline: 6.2237x; 1.3384x over previous
#include <cuda_runtime.h>
#include <cuda_fp16.h>
#include <cstdint>

#define NROWS 65536
#define DDIM  256
#define KCODES 1024
#define GAP_T 0.15f   // fp16 single-term: score-diff err sigma ~4e-3 -> 40-sigma guard
#define SSTR 132      // smem row stride in 32-bit words (128 + 4 pad)
#define CN 32         // codes per W chunk (double-buffered)
#define BM 128        // rows per CTA
#define BUFW (CN * SSTR)

// ---------------- device globals ----------------
__device__ int    g_hist[KCODES];
__device__ double g_commit;
__device__ double g_div;
__device__ float  g_halfnorm[KCODES];
__device__ float  g_invnorm[KCODES];
__device__ float  g_ne[KCODES];
__device__ float  g_Wt[DDIM * KCODES];
__device__ uint32_t g_Whx[KCODES * 128];   // fp16x2-packed W
__device__ int    g_idx[NROWS];
__device__ int    g_flagrows[NROWS];
__device__ int    g_nflag;
__device__ unsigned long long g_best[NROWS];

// ---------------- helpers ----------------
__device__ __forceinline__ unsigned f2o(float f) {
    unsigned b = __float_as_uint(f);
    return (b & 0x80000000u) ? ~b : (b | 0x80000000u);
}
__device__ __forceinline__ float o2f(unsigned u) {
    return (u & 0x80000000u) ? __uint_as_float(u ^ 0x80000000u) : __uint_as_float(~u);
}
__device__ __forceinline__ uint32_t smem_u32(const void* p) {
    uint32_t a;
    asm("{ .reg .u64 t; cvta.to.shared.u64 t, %1; cvt.u32.u64 %0, t; }" : "=r"(a) : "l"(p));
    return a;
}
__device__ __forceinline__ void cpa16(uint32_t dst, const void* src) {
    asm volatile("cp.async.cg.shared.global [%0], [%1], 16;" :: "r"(dst), "l"(src));
}
__device__ __forceinline__ void cpa_commit() {
    asm volatile("cp.async.commit_group;" ::: "memory");
}
__device__ __forceinline__ void cpa_wait1() {
    asm volatile("cp.async.wait_group 1;" ::: "memory");
}

__device__ __forceinline__ void mma_f16(float* c, const uint32_t* a, const uint32_t* b) {
    asm volatile(
        "mma.sync.aligned.m16n8k16.row.col.f32.f16.f16.f32 "
        "{%0,%1,%2,%3}, {%4,%5,%6,%7}, {%8,%9}, {%0,%1,%2,%3};"
        : "+f"(c[0]), "+f"(c[1]), "+f"(c[2]), "+f"(c[3])
        : "r"(a[0]), "r"(a[1]), "r"(a[2]), "r"(a[3]), "r"(b[0]), "r"(b[1]));
}

__device__ __forceinline__ uint32_t pack_h16x2(float lo, float hi) {
    __half2 t;
    t.x = __float2half_rn(lo);
    t.y = __float2half_rn(hi);
    return *(uint32_t*)&t;
}

// ---------------- small kernels ----------------
// coalesced tiled transpose: g_Wt[j][k] = W[k][j]
__global__ void vq_tr(const float* __restrict__ W) {
    __shared__ float ts[32][33];
    const int tid = threadIdx.x;          // 256 = 32x8
    const int tx = tid & 31, ty = tid >> 5;
    const int kb = (blockIdx.x & 31) * 32;     // 32 k-tiles
    const int jb = (blockIdx.x >> 5) * 32;     // 8 j-tiles
    #pragma unroll
    for (int dy = 0; dy < 4; dy++) {
        int k = kb + ty + 8 * dy;
        ts[ty + 8 * dy][tx] = W[(size_t)k * DDIM + jb + tx];
    }
    __syncthreads();
    #pragma unroll
    for (int dy = 0; dy < 4; dy++) {
        int j = jb + ty + 8 * dy;
        g_Wt[(size_t)j * KCODES + kb + tx] = ts[tx][ty + 8 * dy];
    }
}

// contracted XLA-emulated ||e||^2 + halfnorm/invnorm + packed fp16 W + init
__global__ void vq_pre(const float* __restrict__ W) {
    int k = blockIdx.x * 8 + (threadIdx.x >> 5);
    int lane = threadIdx.x & 31;
    if (blockIdx.x == 0 && threadIdx.x == 0) {
        g_commit = 0.0; g_div = 0.0; g_nflag = 0;
    }
    float p = 0.f;
    #pragma unroll
    for (int j = 0; j < 8; j++) {
        float v = W[(size_t)k * DDIM + lane + 32 * j];
        p = __fmaf_rn(v, v, p);
    }
    #pragma unroll
    for (int o = 16; o > 0; o >>= 1)
        p = __fadd_rn(p, __shfl_down_sync(0xffffffffu, p, o));
    if (lane == 0) {
        g_hist[k] = 0;
        g_ne[k] = p;
        g_halfnorm[k] = 0.5f * p;
        g_invnorm[k] = 1.0f / fmaxf(sqrtf(p), 1e-12f);
    }
    // packed fp16 W
    #pragma unroll
    for (int t = 0; t < 4; t++) {
        int w = lane + 32 * t;
        float2 v = *(const float2*)(W + (size_t)k * DDIM + 2 * w);
        g_Whx[k * 128 + w] = pack_h16x2(v.x, v.y);
    }
}

// ---------------- mma.sync fp16 single-term GEMM + top-2 ----------------
// 128-row CTA, CN=32 code chunks double-buffered via cp.async from packed W.
// 8 warps: 4(M bands of 32 rows) x 2(N bands of 16 codes); warp tile
// 32x16 = 2 m16 x 2 n8 (validated R8 mapping). ~104.5 KB smem -> 2 CTAs/SM.
__global__ void __launch_bounds__(256, 2) vq_main_mma(const float* __restrict__ X)
{
    extern __shared__ __align__(16) uint32_t sm[];
    float*    hn = (float*)sm;               // [1024]
    uint32_t* xh = sm + 1024;                // [128][SSTR]
    uint32_t* wh = xh + BM * SSTR;           // [2][CN][SSTR]
    unsigned long long* pk = (unsigned long long*)(wh + 2 * BUFW);  // [128]
    unsigned* pk2 = (unsigned*)(pk + BM);                           // [128]

    const int tid  = threadIdx.x;
    const int lane = tid & 31;
    const int wid  = tid >> 5;
    const int wm   = wid >> 1;     // 0..3 : 32-row band
    const int wn   = wid & 1;      // 0..1 : 16-code band
    const int q    = lane >> 2;    // 0..7
    const int cg   = lane & 3;     // 0..3
    const int row0 = blockIdx.x * BM;

    const uint32_t whu = smem_u32(wh);

    for (int i = tid; i < KCODES; i += 256) hn[i] = g_halfnorm[i];
    if (tid < BM) { pk[tid] = 0ull; pk2[tid] = 0u; }

    // X tile: fp32 -> fp16, padded layout
    for (int i = tid; i < BM * 128; i += 256) {
        int r = i >> 7, w = i & 127;
        float2 v = *(const float2*)(X + (size_t)(row0 + r) * DDIM + 2 * w);
        xh[r * SSTR + w] = pack_h16x2(v.x, v.y);
    }

    // async copy of W chunk c into buffer b
    auto copy_chunk = [&](int c, int b) {
        int code0 = c * CN;
        #pragma unroll
        for (int i = tid; i < CN * 32; i += 256) {
            int r = i >> 5, f4 = i & 31;
            uint32_t doff = (uint32_t)(b * BUFW + r * SSTR + f4 * 4) * 4;
            uint32_t goff = (uint32_t)(code0 + r) * 128 + f4 * 4;
            cpa16(whu + doff, &g_Whx[goff]);
        }
    };

    float s1[4], s2[4];
    int   i1[4];
    #pragma unroll
    for (int s = 0; s < 4; s++) { s1[s] = -1e30f; s2[s] = -1e30f; i1[s] = 0; }

    copy_chunk(0, 0); cpa_commit();
    copy_chunk(1, 1); cpa_commit();

    for (int nc = 0; nc < KCODES / CN; nc++) {
        const int b = nc & 1;
        cpa_wait1();         // chunk nc arrived
        __syncthreads();     // visible to all threads (covers X tile on nc=0)

        float acc[2][2][4];  // [m-tile][n-tile]
        #pragma unroll
        for (int t = 0; t < 2; t++)
            #pragma unroll
            for (int u = 0; u < 2; u++)
                #pragma unroll
                for (int e = 0; e < 4; e++) acc[t][u][e] = 0.f;

        #pragma unroll 4
        for (int ks = 0; ks < 16; ks++) {
            const int kw = ks * 8 + cg;
            uint32_t a[2][4];
            #pragma unroll
            for (int t = 0; t < 2; t++) {
                const uint32_t* pa = xh + (wm * 32 + t * 16 + q) * SSTR + kw;
                a[t][0] = pa[0]; a[t][1] = pa[8 * SSTR];
                a[t][2] = pa[4]; a[t][3] = pa[8 * SSTR + 4];
            }
            uint32_t bf[2][2];
            #pragma unroll
            for (int u = 0; u < 2; u++) {
                const uint32_t* pb = wh + b * BUFW + (wn * 16 + u * 8 + q) * SSTR + kw;
                bf[u][0] = pb[0]; bf[u][1] = pb[4];
            }
            #pragma unroll
            for (int t = 0; t < 2; t++)
                #pragma unroll
                for (int u = 0; u < 2; u++)
                    mma_f16(acc[t][u], a[t], bf[u]);
        }

        __syncthreads();     // all reads of buffer b done
        if (nc < KCODES / CN - 2) copy_chunk(nc + 2, b);
        cpa_commit();        // always commit to keep group count aligned

        // epilogue overlaps with copy flight: registers + hn only
        #pragma unroll
        for (int t = 0; t < 2; t++)
            #pragma unroll
            for (int u = 0; u < 2; u++)
                #pragma unroll
                for (int e = 0; e < 4; e++) {
                    int slot = t * 2 + (e >> 1);
                    int code = nc * CN + wn * 16 + u * 8 + cg * 2 + (e & 1);
                    float sc = acc[t][u][e] - hn[code];
                    if (sc > s1[slot]) { s2[slot] = s1[slot]; s1[slot] = sc; i1[slot] = code; }
                    else if (sc > s2[slot]) s2[slot] = sc;
                }
    }
    __syncthreads();

    // tournament 1: per-row best (first-index tiebreak)
    #pragma unroll
    for (int s = 0; s < 4; s++) {
        int rowl = wm * 32 + s * 8 + q;
        unsigned long long p = ((unsigned long long)f2o(s1[s]) << 32) |
                               (unsigned long long)(KCODES - 1 - i1[s]);
        atomicMax(&pk[rowl], p);
    }
    __syncthreads();
    // tournament 2: per-row second-best (exclude winner's code)
    #pragma unroll
    for (int s = 0; s < 4; s++) {
        int rowl = wm * 32 + s * 8 + q;
        int winner = (KCODES - 1) - (int)(pk[rowl] & 0xffffffffu);
        float cand = (i1[s] == winner) ? s2[s] : s1[s];
        atomicMax(&pk2[rowl], f2o(cand));
    }
    __syncthreads();

    if (tid < BM) {
        unsigned long long p = pk[tid];
        int idx = (KCODES - 1) - (int)(p & 0xffffffffu);
        float b1 = o2f((unsigned)(p >> 32));
        float b2 = o2f(pk2[tid]);
        int row = row0 + tid;
        g_idx[row] = idx;
        if (b1 - b2 < GAP_T) {
            g_best[row] = 0xFFFFFFFFFFFFFFFFull;
            int pos = atomicAdd(&g_nflag, 1);
            g_flagrows[pos] = row;
        }
    }
}

// ---------------- rescan v3: 8-row batched, bit-exact (validated R10) ----------------
__global__ void __launch_bounds__(256) vq_rescan3(const float* __restrict__ X) {
    __shared__ float xs[8][DDIM];
    __shared__ float nxs[8];
    __shared__ int   rws[8];
    const int tid = threadIdx.x;
    int n = g_nflag;
    if (n > NROWS) n = NROWS;
    if (n == 0) return;
    int nu = ((n + 7) >> 3) * 2;

    for (int u = blockIdx.x; u < nu; u += gridDim.x) {
        int g = u >> 1, h = u & 1;
        __syncthreads();   // protect previous iteration's xs/nxs
        if (tid < 8) {
            int s = g * 8 + tid;
            rws[tid] = g_flagrows[s < n ? s : n - 1];
        }
        __syncthreads();
        for (int i = tid; i < 8 * 64; i += 256) {
            int r = i >> 6, f = i & 63;
            *(float4*)&xs[r][f * 4] = *(const float4*)(X + (size_t)rws[r] * DDIM + f * 4);
        }
        __syncthreads();
        {   // emulated nx per row (warp w -> row w)
            int w = tid >> 5, lane = tid & 31;
            float p = 0.f;
            #pragma unroll
            for (int j = 0; j < 8; j++) {
                float v = xs[w][lane + 32 * j];
                p = __fmaf_rn(v, v, p);
            }
            #pragma unroll
            for (int o = 16; o > 0; o >>= 1)
                p = __fadd_rn(p, __shfl_down_sync(0xffffffffu, p, o));
            if (lane == 0) nxs[w] = p;
        }
        __syncthreads();

        const int k0 = h * 512 + tid;
        float a[8][2];
        #pragma unroll
        for (int r = 0; r < 8; r++) { a[r][0] = 0.f; a[r][1] = 0.f; }
        const float* w0 = g_Wt + k0;
        #pragma unroll 4
        for (int j = 0; j < DDIM; j++) {
            float wv0 = w0[(size_t)j * KCODES];
            float wv1 = w0[(size_t)j * KCODES + 256];
            #pragma unroll
            for (int r = 0; r < 8; r++) {
                float x = xs[r][j];
                a[r][0] = __fmaf_rn(x, wv0, a[r][0]);
                a[r][1] = __fmaf_rn(x, wv1, a[r][1]);
            }
        }
        float ne0 = g_ne[k0], ne1 = g_ne[k0 + 256];
        #pragma unroll
        for (int r = 0; r < 8; r++) {
            float d0 = __fadd_rn(__fmaf_rn(a[r][0], -2.0f, nxs[r]), ne0);
            float d1 = __fadd_rn(__fmaf_rn(a[r][1], -2.0f, nxs[r]), ne1);
            unsigned long long p0 = ((unsigned long long)f2o(d0) << 32) | (unsigned)k0;
            unsigned long long p1 = ((unsigned long long)f2o(d1) << 32) | (unsigned)(k0 + 256);
            atomicMin(&g_best[rws[r]], p0 < p1 ? p0 : p1);
        }
    }
}

// write winning indices for flagged rows
__global__ void vq_fix() {
    int n = g_nflag;
    if (n > NROWS) n = NROWS;
    for (int u = blockIdx.x * blockDim.x + threadIdx.x; u < n; u += gridDim.x * blockDim.x) {
        int row = g_flagrows[u];
        g_idx[row] = (int)(g_best[row] & 0xffffffffu);
    }
}

// ---------------- gather + commitment + histogram ----------------
__global__ void __launch_bounds__(256) vq_gather(
    const float* __restrict__ X, const float* __restrict__ W,
    float* __restrict__ outq, float* __restrict__ out_idx)
{
    __shared__ double cred[8];
    const int tid = threadIdx.x;
    const int row0 = blockIdx.x * 64;
    const int r  = tid >> 2;
    const int dq = tid & 3;
    const int row = row0 + r;

    int idx = g_idx[row];
    const float* erow = W + (size_t)idx * DDIM;
    const float* xrow = X + (size_t)row * DDIM;
    float* orow = outq + (size_t)row * DDIM;
    double csum = 0.0;
    #pragma unroll
    for (int j = 0; j < 16; j++) {
        int f4 = dq + 4 * j;
        float4 e4 = *(const float4*)(erow + 4 * f4);
        float4 x4 = *(const float4*)(xrow + 4 * f4);
        *(float4*)(orow + 4 * f4) = e4;
        float d0 = e4.x - x4.x;
        float d1 = e4.y - x4.y;
        float d2 = e4.z - x4.z;
        float d3 = e4.w - x4.w;
        csum += (double)d0 * d0 + (double)d1 * d1 + (double)d2 * d2 + (double)d3 * d3;
    }
    if (dq == 0) {
        atomicAdd(&g_hist[idx], 1);
        if (out_idx) out_idx[row] = (float)idx;
    }

    #pragma unroll
    for (int o = 16; o > 0; o >>= 1)
        csum += __shfl_xor_sync(0xffffffffu, csum, o);
    if ((tid & 31) == 0) cred[tid >> 5] = csum;
    __syncthreads();
    if (tid < 8) {
        double v = cred[tid];
        #pragma unroll
        for (int o = 4; o > 0; o >>= 1) v += __shfl_xor_sync(0xffu, v, o);
        if (tid == 0) atomicAdd(&g_commit, v);
    }
}

// ---------------- diversity loss ----------------
__global__ void __launch_bounds__(256) vq_div(const float* __restrict__ W) {
    __shared__ float si[32][68];
    __shared__ float sj[32][68];
    __shared__ double red[8];
    const int tid = threadIdx.x;
    const int ibase = (blockIdx.x & 15) * 64;
    const int jbase = (blockIdx.x >> 4) * 64;
    const int ig = tid & 15;
    const int jg = tid >> 4;

    float acc[4][4];
    #pragma unroll
    for (int i = 0; i < 4; i++)
        #pragma unroll
        for (int j = 0; j < 4; j++) acc[i][j] = 0.f;

    for (int dc = 0; dc < DDIM / 32; ++dc) {
        __syncthreads();
        #pragma unroll
        for (int t = 0; t < 2; t++) {
            int slot = tid + 256 * t;
            int c  = slot >> 3;
            int f4 = slot & 7;
            float4 v = *(const float4*)(W + (size_t)(ibase + c) * DDIM + dc * 32 + f4 * 4);
            float4 w = *(const float4*)(W + (size_t)(jbase + c) * DDIM + dc * 32 + f4 * 4);
            int d = f4 * 4;
            si[d + 0][c] = v.x; si[d + 1][c] = v.y; si[d + 2][c] = v.z; si[d + 3][c] = v.w;
            sj[d + 0][c] = w.x; sj[d + 1][c] = w.y; sj[d + 2][c] = w.z; sj[d + 3][c] = w.w;
        }
        __syncthreads();
        #pragma unroll
        for (int d = 0; d < 32; ++d) {
            float a[4], b[4];
            #pragma unroll
            for (int i = 0; i < 4; i++) a[i] = si[d][ig * 4 + i];
            #pragma unroll
            for (int j = 0; j < 4; j++) b[j] = sj[d][jg * 4 + j];
            #pragma unroll
            for (int i = 0; i < 4; i++)
                #pragma unroll
                for (int j = 0; j < 4; j++)
                    acc[i][j] = fmaf(a[i], b[j], acc[i][j]);
        }
    }

    float invi[4], invj[4];
    #pragma unroll
    for (int i = 0; i < 4; i++) invi[i] = g_invnorm[ibase + ig * 4 + i];
    #pragma unroll
    for (int j = 0; j < 4; j++) invj[j] = g_invnorm[jbase + jg * 4 + j];

    double s = 0.0;
    #pragma unroll
    for (int i = 0; i < 4; i++)
        #pragma unroll
        for (int j = 0; j < 4; j++) {
            float v = acc[i][j] * invi[i] * invj[j];
            if (ibase + ig * 4 + i == jbase + jg * 4 + j) v -= 1.0f;
            float t = fmaxf(fabsf(v), 0.1f);
            s += (double)t * (double)t;
        }

    #pragma unroll
    for (int o = 16; o > 0; o >>= 1) s += __shfl_xor_sync(0xffffffffu, s, o);
    if ((tid & 31) == 0) red[tid >> 5] = s;
    __syncthreads();
    if (tid < 8) {
        double v = red[tid];
        #pragma unroll
        for (int o = 4; o > 0; o >>= 1) v += __shfl_xor_sync(0xffu, v, o);
        if (tid == 0) atomicAdd(&g_div, v);
    }
}

// ---------------- entropy + combine ----------------
__global__ void vq_fin(float* __restrict__ out_loss) {
    __shared__ double red[32];
    int k = threadIdx.x;
    double p = (double)g_hist[k] * (1.0 / (double)NROWS);
    const double u = 1.0 / (double)KCODES;
    double term = u * (log(u) - log(p + 1e-10));
    #pragma unroll
    for (int o = 16; o > 0; o >>= 1) term += __shfl_xor_sync(0xffffffffu, term, o);
    if ((k & 31) == 0) red[k >> 5] = term;
    __syncthreads();
    if (k < 32) {
        double v = red[k];
        #pragma unroll
        for (int o = 16; o > 0; o >>= 1) v += __shfl_xor_sync(0xffffffffu, v, o);
        if (k == 0) {
            double commit = g_commit * (1.0 / ((double)NROWS * (double)DDIM));
            double divm   = g_div * (1.0 / ((double)KCODES * (double)KCODES));
            double total = 0.25 * commit + 0.5 * divm + 0.5 * v;
            if (out_loss) *out_loss = (float)total;
        }
    }
}

extern "C" void kernel_launch(void* const* d_in, const int* in_sizes, int n_in,
                              void* d_out, int out_size) {
    const float* X = (const float*)d_in[0];
    const float* W = (const float*)d_in[1];
    float* out = (float*)d_out;

    const long long Nq = (long long)NROWS * DDIM;
    float* out_loss = nullptr;
    float* out_idx  = nullptr;
    if ((long long)out_size >= Nq + 1 + NROWS) {
        out_loss = out + Nq;
        out_idx  = out + Nq + 1;
    }

    // dynamic smem: hn + X fp16 (128 rows) + 2x double-buffered W fp16 + tournaments (~104.5 KB)
    const int SMEM_MMA = (1024 + BM * SSTR + 2 * BUFW) * 4 + BM * 8 + BM * 4;
    cudaFuncSetAttribute(vq_main_mma, cudaFuncAttributeMaxDynamicSharedMemorySize, SMEM_MMA);

    vq_tr<<<256, 256>>>(W);
    vq_pre<<<KCODES / 8, 256>>>(W);
    vq_main_mma<<<NROWS / BM, 256, SMEM_MMA>>>(X);
    vq_rescan3<<<1024, 256>>>(X);
    vq_fix<<<64, 256>>>();
    vq_gather<<<NROWS / 64, 256>>>(X, W, out, out_idx);
    vq_div<<<256, 256>>>(W);
    vq_fin<<<1, 1024>>>(out_loss);
}

// round 14
// speedup vs baseline: 6.4902x; 1.0428x over previous
#include <cuda_runtime.h>
#include <cuda_fp16.h>
#include <cstdint>

#define NROWS 65536
#define DDIM  256
#define KCODES 1024
#define GAP_T 0.15f   // fp16 single-term: score-diff err sigma ~4e-3 -> 40-sigma guard
#define SSTR 132      // smem row stride in 32-bit words (128 + 4 pad)
#define CN 32         // codes per W chunk (double-buffered)
#define BM 128        // rows per CTA
#define BUFW (CN * SSTR)

// ---------------- device globals ----------------
__device__ int    g_hist[KCODES];
__device__ double g_commit;
__device__ double g_div;
__device__ float  g_halfnorm[KCODES];
__device__ float  g_invnorm[KCODES];
__device__ float  g_ne[KCODES];
__device__ float  g_Wt[DDIM * KCODES];
__device__ uint32_t g_Whx[KCODES * 128];   // fp16x2-packed W
__device__ int    g_idx[NROWS];
__device__ int    g_flagrows[NROWS];
__device__ int    g_nflag;
__device__ unsigned long long g_best[NROWS];

// ---------------- helpers ----------------
__device__ __forceinline__ unsigned f2o(float f) {
    unsigned b = __float_as_uint(f);
    return (b & 0x80000000u) ? ~b : (b | 0x80000000u);
}
__device__ __forceinline__ float o2f(unsigned u) {
    return (u & 0x80000000u) ? __uint_as_float(u ^ 0x80000000u) : __uint_as_float(~u);
}
__device__ __forceinline__ uint32_t smem_u32(const void* p) {
    uint32_t a;
    asm("{ .reg .u64 t; cvta.to.shared.u64 t, %1; cvt.u32.u64 %0, t; }" : "=r"(a) : "l"(p));
    return a;
}
__device__ __forceinline__ void cpa16(uint32_t dst, const void* src) {
    asm volatile("cp.async.cg.shared.global [%0], [%1], 16;" :: "r"(dst), "l"(src));
}
__device__ __forceinline__ void cpa_commit() {
    asm volatile("cp.async.commit_group;" ::: "memory");
}
__device__ __forceinline__ void cpa_wait1() {
    asm volatile("cp.async.wait_group 1;" ::: "memory");
}
__device__ __forceinline__ void ldsm_x4(uint32_t& r0, uint32_t& r1, uint32_t& r2, uint32_t& r3,
                                        uint32_t addr) {
    asm volatile("ldmatrix.sync.aligned.m8n8.x4.shared.b16 {%0,%1,%2,%3}, [%4];"
        : "=r"(r0), "=r"(r1), "=r"(r2), "=r"(r3) : "r"(addr));
}

__device__ __forceinline__ void mma_f16(float* c, const uint32_t* a, const uint32_t* b) {
    asm volatile(
        "mma.sync.aligned.m16n8k16.row.col.f32.f16.f16.f32 "
        "{%0,%1,%2,%3}, {%4,%5,%6,%7}, {%8,%9}, {%0,%1,%2,%3};"
        : "+f"(c[0]), "+f"(c[1]), "+f"(c[2]), "+f"(c[3])
        : "r"(a[0]), "r"(a[1]), "r"(a[2]), "r"(a[3]), "r"(b[0]), "r"(b[1]));
}

__device__ __forceinline__ uint32_t pack_h16x2(float lo, float hi) {
    __half2 t;
    t.x = __float2half_rn(lo);
    t.y = __float2half_rn(hi);
    return *(uint32_t*)&t;
}

// ---------------- small kernels ----------------
// coalesced tiled transpose: g_Wt[j][k] = W[k][j]
__global__ void vq_tr(const float* __restrict__ W) {
    __shared__ float ts[32][33];
    const int tid = threadIdx.x;          // 256 = 32x8
    const int tx = tid & 31, ty = tid >> 5;
    const int kb = (blockIdx.x & 31) * 32;     // 32 k-tiles
    const int jb = (blockIdx.x >> 5) * 32;     // 8 j-tiles
    #pragma unroll
    for (int dy = 0; dy < 4; dy++) {
        int k = kb + ty + 8 * dy;
        ts[ty + 8 * dy][tx] = W[(size_t)k * DDIM + jb + tx];
    }
    __syncthreads();
    #pragma unroll
    for (int dy = 0; dy < 4; dy++) {
        int j = jb + ty + 8 * dy;
        g_Wt[(size_t)j * KCODES + kb + tx] = ts[tx][ty + 8 * dy];
    }
}

// contracted XLA-emulated ||e||^2 + halfnorm/invnorm + packed fp16 W + init
__global__ void vq_pre(const float* __restrict__ W) {
    int k = blockIdx.x * 8 + (threadIdx.x >> 5);
    int lane = threadIdx.x & 31;
    if (blockIdx.x == 0 && threadIdx.x == 0) {
        g_commit = 0.0; g_div = 0.0; g_nflag = 0;
    }
    float p = 0.f;
    #pragma unroll
    for (int j = 0; j < 8; j++) {
        float v = W[(size_t)k * DDIM + lane + 32 * j];
        p = __fmaf_rn(v, v, p);
    }
    #pragma unroll
    for (int o = 16; o > 0; o >>= 1)
        p = __fadd_rn(p, __shfl_down_sync(0xffffffffu, p, o));
    if (lane == 0) {
        g_hist[k] = 0;
        g_ne[k] = p;
        g_halfnorm[k] = 0.5f * p;
        g_invnorm[k] = 1.0f / fmaxf(sqrtf(p), 1e-12f);
    }
    // packed fp16 W
    #pragma unroll
    for (int t = 0; t < 4; t++) {
        int w = lane + 32 * t;
        float2 v = *(const float2*)(W + (size_t)k * DDIM + 2 * w);
        g_Whx[k * 128 + w] = pack_h16x2(v.x, v.y);
    }
}

// ---------------- mma.sync fp16 single-term GEMM + top-2 (ldmatrix) ----------------
// 128-row CTA, CN=32 code chunks double-buffered via cp.async from packed W.
// 8 warps: 4(M bands of 32 rows) x 2(N bands of 16 codes); warp tile
// 32x16 = 2 m16 x 2 n8. Fragments via ldmatrix.x4 (3 LDSM per k-step).
// ~104.5 KB smem -> 2 CTAs/SM.
__global__ void __launch_bounds__(256, 2) vq_main_mma(const float* __restrict__ X)
{
    extern __shared__ __align__(16) uint32_t sm[];
    float*    hn = (float*)sm;               // [1024]
    uint32_t* xh = sm + 1024;                // [128][SSTR]
    uint32_t* wh = xh + BM * SSTR;           // [2][CN][SSTR]
    unsigned long long* pk = (unsigned long long*)(wh + 2 * BUFW);  // [128]
    unsigned* pk2 = (unsigned*)(pk + BM);                           // [128]

    const int tid  = threadIdx.x;
    const int lane = tid & 31;
    const int wid  = tid >> 5;
    const int wm   = wid >> 1;     // 0..3 : 32-row band
    const int wn   = wid & 1;      // 0..1 : 16-code band
    const int q    = lane >> 2;    // 0..7
    const int cg   = lane & 3;     // 0..3
    const int row0 = blockIdx.x * BM;

    const uint32_t whu = smem_u32(wh);
    const uint32_t xhu = smem_u32(xh);

    for (int i = tid; i < KCODES; i += 256) hn[i] = g_halfnorm[i];
    if (tid < BM) { pk[tid] = 0ull; pk2[tid] = 0u; }

    // X tile: fp32 -> fp16, padded layout
    for (int i = tid; i < BM * 128; i += 256) {
        int r = i >> 7, w = i & 127;
        float2 v = *(const float2*)(X + (size_t)(row0 + r) * DDIM + 2 * w);
        xh[r * SSTR + w] = pack_h16x2(v.x, v.y);
    }

    // ldmatrix per-lane base addresses (bytes)
    // A (per m-tile t): matrices [m0-7,k0-7][m8-15,k0-7][m0-7,k8-15][m8-15,k8-15]
    //   row = wm*32 + t*16 + (lane&15), col words = 4*(lane>>4)
    uint32_t a_addr[2];
    #pragma unroll
    for (int t = 0; t < 2; t++)
        a_addr[t] = xhu + (((wm * 32 + t * 16 + (lane & 15)) * SSTR + 4 * (lane >> 4)) << 2);
    // B: matrices [u0,k0-7][u0,k8-15][u1,k0-7][u1,k8-15]
    //   code = wn*16 + 8*(lane>>4) + (lane&7), col words = 4*((lane>>3)&1)
    const uint32_t b_off = (((wn * 16 + 8 * (lane >> 4) + (lane & 7)) * SSTR
                            + 4 * ((lane >> 3) & 1)) << 2);

    // async copy of W chunk c into buffer b
    auto copy_chunk = [&](int c, int b) {
        int code0 = c * CN;
        #pragma unroll
        for (int i = tid; i < CN * 32; i += 256) {
            int r = i >> 5, f4 = i & 31;
            uint32_t doff = (uint32_t)(b * BUFW + r * SSTR + f4 * 4) * 4;
            uint32_t goff = (uint32_t)(code0 + r) * 128 + f4 * 4;
            cpa16(whu + doff, &g_Whx[goff]);
        }
    };

    float s1[4], s2[4];
    int   i1[4];
    #pragma unroll
    for (int s = 0; s < 4; s++) { s1[s] = -1e30f; s2[s] = -1e30f; i1[s] = 0; }

    copy_chunk(0, 0); cpa_commit();
    copy_chunk(1, 1); cpa_commit();

    for (int nc = 0; nc < KCODES / CN; nc++) {
        const int b = nc & 1;
        cpa_wait1();         // chunk nc arrived
        __syncthreads();     // visible to all threads (covers X tile on nc=0)

        const uint32_t b_base = whu + (uint32_t)(b * BUFW * 4) + b_off;

        float acc[2][2][4];  // [m-tile][n-tile]
        #pragma unroll
        for (int t = 0; t < 2; t++)
            #pragma unroll
            for (int u = 0; u < 2; u++)
                #pragma unroll
                for (int e = 0; e < 4; e++) acc[t][u][e] = 0.f;

        #pragma unroll 4
        for (int ks = 0; ks < 16; ks++) {
            const uint32_t koff = ks * 32;   // 8 words
            uint32_t a[2][4];
            ldsm_x4(a[0][0], a[0][1], a[0][2], a[0][3], a_addr[0] + koff);
            ldsm_x4(a[1][0], a[1][1], a[1][2], a[1][3], a_addr[1] + koff);
            uint32_t bf[2][2];
            ldsm_x4(bf[0][0], bf[0][1], bf[1][0], bf[1][1], b_base + koff);
            #pragma unroll
            for (int t = 0; t < 2; t++)
                #pragma unroll
                for (int u = 0; u < 2; u++)
                    mma_f16(acc[t][u], a[t], bf[u]);
        }

        __syncthreads();     // all reads of buffer b done
        if (nc < KCODES / CN - 2) copy_chunk(nc + 2, b);
        cpa_commit();        // always commit to keep group count aligned

        // epilogue overlaps with copy flight: registers + hn only
        #pragma unroll
        for (int t = 0; t < 2; t++)
            #pragma unroll
            for (int u = 0; u < 2; u++)
                #pragma unroll
                for (int e = 0; e < 4; e++) {
                    int slot = t * 2 + (e >> 1);
                    int code = nc * CN + wn * 16 + u * 8 + cg * 2 + (e & 1);
                    float sc = acc[t][u][e] - hn[code];
                    if (sc > s1[slot]) { s2[slot] = s1[slot]; s1[slot] = sc; i1[slot] = code; }
                    else if (sc > s2[slot]) s2[slot] = sc;
                }
    }
    __syncthreads();

    // tournament 1: per-row best (first-index tiebreak)
    #pragma unroll
    for (int s = 0; s < 4; s++) {
        int rowl = wm * 32 + s * 8 + q;
        unsigned long long p = ((unsigned long long)f2o(s1[s]) << 32) |
                               (unsigned long long)(KCODES - 1 - i1[s]);
        atomicMax(&pk[rowl], p);
    }
    __syncthreads();
    // tournament 2: per-row second-best (exclude winner's code)
    #pragma unroll
    for (int s = 0; s < 4; s++) {
        int rowl = wm * 32 + s * 8 + q;
        int winner = (KCODES - 1) - (int)(pk[rowl] & 0xffffffffu);
        float cand = (i1[s] == winner) ? s2[s] : s1[s];
        atomicMax(&pk2[rowl], f2o(cand));
    }
    __syncthreads();

    if (tid < BM) {
        unsigned long long p = pk[tid];
        int idx = (KCODES - 1) - (int)(p & 0xffffffffu);
        float b1 = o2f((unsigned)(p >> 32));
        float b2 = o2f(pk2[tid]);
        int row = row0 + tid;
        g_idx[row] = idx;
        if (b1 - b2 < GAP_T) {
            g_best[row] = 0xFFFFFFFFFFFFFFFFull;
            int pos = atomicAdd(&g_nflag, 1);
            g_flagrows[pos] = row;
        }
    }
}

// ---------------- rescan v3: 8-row batched, bit-exact (validated R10) ----------------
__global__ void __launch_bounds__(256) vq_rescan3(const float* __restrict__ X) {
    __shared__ float xs[8][DDIM];
    __shared__ float nxs[8];
    __shared__ int   rws[8];
    const int tid = threadIdx.x;
    int n = g_nflag;
    if (n > NROWS) n = NROWS;
    if (n == 0) return;
    int nu = ((n + 7) >> 3) * 2;

    for (int u = blockIdx.x; u < nu; u += gridDim.x) {
        int g = u >> 1, h = u & 1;
        __syncthreads();   // protect previous iteration's xs/nxs
        if (tid < 8) {
            int s = g * 8 + tid;
            rws[tid] = g_flagrows[s < n ? s : n - 1];
        }
        __syncthreads();
        for (int i = tid; i < 8 * 64; i += 256) {
            int r = i >> 6, f = i & 63;
            *(float4*)&xs[r][f * 4] = *(const float4*)(X + (size_t)rws[r] * DDIM + f * 4);
        }
        __syncthreads();
        {   // emulated nx per row (warp w -> row w)
            int w = tid >> 5, lane = tid & 31;
            float p = 0.f;
            #pragma unroll
            for (int j = 0; j < 8; j++) {
                float v = xs[w][lane + 32 * j];
                p = __fmaf_rn(v, v, p);
            }
            #pragma unroll
            for (int o = 16; o > 0; o >>= 1)
                p = __fadd_rn(p, __shfl_down_sync(0xffffffffu, p, o));
            if (lane == 0) nxs[w] = p;
        }
        __syncthreads();

        const int k0 = h * 512 + tid;
        float a[8][2];
        #pragma unroll
        for (int r = 0; r < 8; r++) { a[r][0] = 0.f; a[r][1] = 0.f; }
        const float* w0 = g_Wt + k0;
        #pragma unroll 4
        for (int j = 0; j < DDIM; j++) {
            float wv0 = w0[(size_t)j * KCODES];
            float wv1 = w0[(size_t)j * KCODES + 256];
            #pragma unroll
            for (int r = 0; r < 8; r++) {
                float x = xs[r][j];
                a[r][0] = __fmaf_rn(x, wv0, a[r][0]);
                a[r][1] = __fmaf_rn(x, wv1, a[r][1]);
            }
        }
        float ne0 = g_ne[k0], ne1 = g_ne[k0 + 256];
        #pragma unroll
        for (int r = 0; r < 8; r++) {
            float d0 = __fadd_rn(__fmaf_rn(a[r][0], -2.0f, nxs[r]), ne0);
            float d1 = __fadd_rn(__fmaf_rn(a[r][1], -2.0f, nxs[r]), ne1);
            unsigned long long p0 = ((unsigned long long)f2o(d0) << 32) | (unsigned)k0;
            unsigned long long p1 = ((unsigned long long)f2o(d1) << 32) | (unsigned)(k0 + 256);
            atomicMin(&g_best[rws[r]], p0 < p1 ? p0 : p1);
        }
    }
}

// write winning indices for flagged rows
__global__ void vq_fix() {
    int n = g_nflag;
    if (n > NROWS) n = NROWS;
    for (int u = blockIdx.x * blockDim.x + threadIdx.x; u < n; u += gridDim.x * blockDim.x) {
        int row = g_flagrows[u];
        g_idx[row] = (int)(g_best[row] & 0xffffffffu);
    }
}

// ---------------- gather + commitment + histogram ----------------
__global__ void __launch_bounds__(256) vq_gather(
    const float* __restrict__ X, const float* __restrict__ W,
    float* __restrict__ outq, float* __restrict__ out_idx)
{
    __shared__ double cred[8];
    const int tid = threadIdx.x;
    const int row0 = blockIdx.x * 64;
    const int r  = tid >> 2;
    const int dq = tid & 3;
    const int row = row0 + r;

    int idx = g_idx[row];
    const float* erow = W + (size_t)idx * DDIM;
    const float* xrow = X + (size_t)row * DDIM;
    float* orow = outq + (size_t)row * DDIM;
    double csum = 0.0;
    #pragma unroll
    for (int j = 0; j < 16; j++) {
        int f4 = dq + 4 * j;
        float4 e4 = *(const float4*)(erow + 4 * f4);
        float4 x4 = *(const float4*)(xrow + 4 * f4);
        *(float4*)(orow + 4 * f4) = e4;
        float d0 = e4.x - x4.x;
        float d1 = e4.y - x4.y;
        float d2 = e4.z - x4.z;
        float d3 = e4.w - x4.w;
        csum += (double)d0 * d0 + (double)d1 * d1 + (double)d2 * d2 + (double)d3 * d3;
    }
    if (dq == 0) {
        atomicAdd(&g_hist[idx], 1);
        if (out_idx) out_idx[row] = (float)idx;
    }

    #pragma unroll
    for (int o = 16; o > 0; o >>= 1)
        csum += __shfl_xor_sync(0xffffffffu, csum, o);
    if ((tid & 31) == 0) cred[tid >> 5] = csum;
    __syncthreads();
    if (tid < 8) {
        double v = cred[tid];
        #pragma unroll
        for (int o = 4; o > 0; o >>= 1) v += __shfl_xor_sync(0xffu, v, o);
        if (tid == 0) atomicAdd(&g_commit, v);
    }
}

// ---------------- diversity loss ----------------
__global__ void __launch_bounds__(256) vq_div(const float* __restrict__ W) {
    __shared__ float si[32][68];
    __shared__ float sj[32][68];
    __shared__ double red[8];
    const int tid = threadIdx.x;
    const int ibase = (blockIdx.x & 15) * 64;
    const int jbase = (blockIdx.x >> 4) * 64;
    const int ig = tid & 15;
    const int jg = tid >> 4;

    float acc[4][4];
    #pragma unroll
    for (int i = 0; i < 4; i++)
        #pragma unroll
        for (int j = 0; j < 4; j++) acc[i][j] = 0.f;

    for (int dc = 0; dc < DDIM / 32; ++dc) {
        __syncthreads();
        #pragma unroll
        for (int t = 0; t < 2; t++) {
            int slot = tid + 256 * t;
            int c  = slot >> 3;
            int f4 = slot & 7;
            float4 v = *(const float4*)(W + (size_t)(ibase + c) * DDIM + dc * 32 + f4 * 4);
            float4 w = *(const float4*)(W + (size_t)(jbase + c) * DDIM + dc * 32 + f4 * 4);
            int d = f4 * 4;
            si[d + 0][c] = v.x; si[d + 1][c] = v.y; si[d + 2][c] = v.z; si[d + 3][c] = v.w;
            sj[d + 0][c] = w.x; sj[d + 1][c] = w.y; sj[d + 2][c] = w.z; sj[d + 3][c] = w.w;
        }
        __syncthreads();
        #pragma unroll
        for (int d = 0; d < 32; ++d) {
            float a[4], b[4];
            #pragma unroll
            for (int i = 0; i < 4; i++) a[i] = si[d][ig * 4 + i];
            #pragma unroll
            for (int j = 0; j < 4; j++) b[j] = sj[d][jg * 4 + j];
            #pragma unroll
            for (int i = 0; i < 4; i++)
                #pragma unroll
                for (int j = 0; j < 4; j++)
                    acc[i][j] = fmaf(a[i], b[j], acc[i][j]);
        }
    }

    float invi[4], invj[4];
    #pragma unroll
    for (int i = 0; i < 4; i++) invi[i] = g_invnorm[ibase + ig * 4 + i];
    #pragma unroll
    for (int j = 0; j < 4; j++) invj[j] = g_invnorm[jbase + jg * 4 + j];

    double s = 0.0;
    #pragma unroll
    for (int i = 0; i < 4; i++)
        #pragma unroll
        for (int j = 0; j < 4; j++) {
            float v = acc[i][j] * invi[i] * invj[j];
            if (ibase + ig * 4 + i == jbase + jg * 4 + j) v -= 1.0f;
            float t = fmaxf(fabsf(v), 0.1f);
            s += (double)t * (double)t;
        }

    #pragma unroll
    for (int o = 16; o > 0; o >>= 1) s += __shfl_xor_sync(0xffffffffu, s, o);
    if ((tid & 31) == 0) red[tid >> 5] = s;
    __syncthreads();
    if (tid < 8) {
        double v = red[tid];
        #pragma unroll
        for (int o = 4; o > 0; o >>= 1) v += __shfl_xor_sync(0xffu, v, o);
        if (tid == 0) atomicAdd(&g_div, v);
    }
}

// ---------------- entropy + combine ----------------
__global__ void vq_fin(float* __restrict__ out_loss) {
    __shared__ double red[32];
    int k = threadIdx.x;
    double p = (double)g_hist[k] * (1.0 / (double)NROWS);
    const double u = 1.0 / (double)KCODES;
    double term = u * (log(u) - log(p + 1e-10));
    #pragma unroll
    for (int o = 16; o > 0; o >>= 1) term += __shfl_xor_sync(0xffffffffu, term, o);
    if ((k & 31) == 0) red[k >> 5] = term;
    __syncthreads();
    if (k < 32) {
        double v = red[k];
        #pragma unroll
        for (int o = 16; o > 0; o >>= 1) v += __shfl_xor_sync(0xffffffffu, v, o);
        if (k == 0) {
            double commit = g_commit * (1.0 / ((double)NROWS * (double)DDIM));
            double divm   = g_div * (1.0 / ((double)KCODES * (double)KCODES));
            double total = 0.25 * commit + 0.5 * divm + 0.5 * v;
            if (out_loss) *out_loss = (float)total;
        }
    }
}

extern "C" void kernel_launch(void* const* d_in, const int* in_sizes, int n_in,
                              void* d_out, int out_size) {
    const float* X = (const float*)d_in[0];
    const float* W = (const float*)d_in[1];
    float* out = (float*)d_out;

    const long long Nq = (long long)NROWS * DDIM;
    float* out_loss = nullptr;
    float* out_idx  = nullptr;
    if ((long long)out_size >= Nq + 1 + NROWS) {
        out_loss = out + Nq;
        out_idx  = out + Nq + 1;
    }

    // dynamic smem: hn + X fp16 (128 rows) + 2x double-buffered W fp16 + tournaments (~104.5 KB)
    const int SMEM_MMA = (1024 + BM * SSTR + 2 * BUFW) * 4 + BM * 8 + BM * 4;
    cudaFuncSetAttribute(vq_main_mma, cudaFuncAttributeMaxDynamicSharedMemorySize, SMEM_MMA);

    vq_tr<<<256, 256>>>(W);
    vq_pre<<<KCODES / 8, 256>>>(W);
    vq_main_mma<<<NROWS / BM, 256, SMEM_MMA>>>(X);
    vq_rescan3<<<1024, 256>>>(X);
    vq_fix<<<64, 256>>>();
    vq_gather<<<NROWS / 64, 256>>>(X, W, out, out_idx);
    vq_div<<<256, 256>>>(W);
    vq_fin<<<1, 1024>>>(out_loss);
}

// round 15
// speedup vs baseline: 6.8229x; 1.0513x over previous
#include <cuda_runtime.h>
#include <cuda_fp16.h>
#include <cstdint>

#define NROWS 65536
#define DDIM  256
#define KCODES 1024
#define GAP_T 0.05f   // fp16 single-term: score-diff err sigma ~3.7e-3 -> 13.5-sigma guard
#define SSTR 132      // smem row stride in 32-bit words (128 + 4 pad)
#define CN 64         // codes per W chunk (single-buffered)
#define BM 64         // rows per CTA
#define BUFW (CN * SSTR)

// ---------------- device globals ----------------
__device__ int    g_hist[KCODES];
__device__ double g_commit;
__device__ double g_div;
__device__ float  g_halfnorm[KCODES];
__device__ float  g_invnorm[KCODES];
__device__ float  g_ne[KCODES];
__device__ float  g_Wt[DDIM * KCODES];
__device__ uint32_t g_Whx[KCODES * 128];   // fp16x2-packed W
__device__ int    g_idx[NROWS];
__device__ int    g_flagrows[NROWS];
__device__ int    g_nflag;
__device__ unsigned long long g_best[NROWS];

// ---------------- helpers ----------------
__device__ __forceinline__ unsigned f2o(float f) {
    unsigned b = __float_as_uint(f);
    return (b & 0x80000000u) ? ~b : (b | 0x80000000u);
}
__device__ __forceinline__ float o2f(unsigned u) {
    return (u & 0x80000000u) ? __uint_as_float(u ^ 0x80000000u) : __uint_as_float(~u);
}
__device__ __forceinline__ uint32_t smem_u32(const void* p) {
    uint32_t a;
    asm("{ .reg .u64 t; cvta.to.shared.u64 t, %1; cvt.u32.u64 %0, t; }" : "=r"(a) : "l"(p));
    return a;
}
__device__ __forceinline__ void cpa16(uint32_t dst, const void* src) {
    asm volatile("cp.async.cg.shared.global [%0], [%1], 16;" :: "r"(dst), "l"(src));
}
__device__ __forceinline__ void cpa_commit() {
    asm volatile("cp.async.commit_group;" ::: "memory");
}
__device__ __forceinline__ void cpa_wait0() {
    asm volatile("cp.async.wait_group 0;" ::: "memory");
}
__device__ __forceinline__ void ldsm_x4(uint32_t& r0, uint32_t& r1, uint32_t& r2, uint32_t& r3,
                                        uint32_t addr) {
    asm volatile("ldmatrix.sync.aligned.m8n8.x4.shared.b16 {%0,%1,%2,%3}, [%4];"
        : "=r"(r0), "=r"(r1), "=r"(r2), "=r"(r3) : "r"(addr));
}

__device__ __forceinline__ void mma_f16(float* c, const uint32_t* a, const uint32_t* b) {
    asm volatile(
        "mma.sync.aligned.m16n8k16.row.col.f32.f16.f16.f32 "
        "{%0,%1,%2,%3}, {%4,%5,%6,%7}, {%8,%9}, {%0,%1,%2,%3};"
        : "+f"(c[0]), "+f"(c[1]), "+f"(c[2]), "+f"(c[3])
        : "r"(a[0]), "r"(a[1]), "r"(a[2]), "r"(a[3]), "r"(b[0]), "r"(b[1]));
}

__device__ __forceinline__ uint32_t pack_h16x2(float lo, float hi) {
    __half2 t;
    t.x = __float2half_rn(lo);
    t.y = __float2half_rn(hi);
    return *(uint32_t*)&t;
}

// ---------------- small kernels ----------------
// coalesced tiled transpose: g_Wt[j][k] = W[k][j]
__global__ void vq_tr(const float* __restrict__ W) {
    __shared__ float ts[32][33];
    const int tid = threadIdx.x;          // 256 = 32x8
    const int tx = tid & 31, ty = tid >> 5;
    const int kb = (blockIdx.x & 31) * 32;     // 32 k-tiles
    const int jb = (blockIdx.x >> 5) * 32;     // 8 j-tiles
    #pragma unroll
    for (int dy = 0; dy < 4; dy++) {
        int k = kb + ty + 8 * dy;
        ts[ty + 8 * dy][tx] = W[(size_t)k * DDIM + jb + tx];
    }
    __syncthreads();
    #pragma unroll
    for (int dy = 0; dy < 4; dy++) {
        int j = jb + ty + 8 * dy;
        g_Wt[(size_t)j * KCODES + kb + tx] = ts[tx][ty + 8 * dy];
    }
}

// contracted XLA-emulated ||e||^2 + halfnorm/invnorm + packed fp16 W + init
__global__ void vq_pre(const float* __restrict__ W) {
    int k = blockIdx.x * 8 + (threadIdx.x >> 5);
    int lane = threadIdx.x & 31;
    if (blockIdx.x == 0 && threadIdx.x == 0) {
        g_commit = 0.0; g_div = 0.0; g_nflag = 0;
    }
    float p = 0.f;
    #pragma unroll
    for (int j = 0; j < 8; j++) {
        float v = W[(size_t)k * DDIM + lane + 32 * j];
        p = __fmaf_rn(v, v, p);
    }
    #pragma unroll
    for (int o = 16; o > 0; o >>= 1)
        p = __fadd_rn(p, __shfl_down_sync(0xffffffffu, p, o));
    if (lane == 0) {
        g_hist[k] = 0;
        g_ne[k] = p;
        g_halfnorm[k] = 0.5f * p;
        g_invnorm[k] = 1.0f / fmaxf(sqrtf(p), 1e-12f);
    }
    // packed fp16 W
    #pragma unroll
    for (int t = 0; t < 4; t++) {
        int w = lane + 32 * t;
        float2 v = *(const float2*)(W + (size_t)k * DDIM + 2 * w);
        g_Whx[k * 128 + w] = pack_h16x2(v.x, v.y);
    }
}

// ---------------- mma.sync fp16 single-term GEMM + top-2 (ldmatrix, 3 CTA/SM) ----------------
// 64-row CTA, CN=64 code chunks single-buffered via cp.async from packed W.
// 8 warps: 2(M bands of 32 rows) x 4(N bands of 16 codes); warp tile
// 32x16 = 2 m16 x 2 n8. ~72.4 KB smem -> 3 CTAs/SM.
__global__ void __launch_bounds__(256, 3) vq_main_mma(const float* __restrict__ X)
{
    extern __shared__ __align__(16) uint32_t sm[];
    float*    hn = (float*)sm;               // [1024]
    uint32_t* xh = sm + 1024;                // [64][SSTR]
    uint32_t* wh = xh + BM * SSTR;           // [CN][SSTR]
    unsigned long long* pk = (unsigned long long*)(wh + BUFW);  // [64]
    unsigned* pk2 = (unsigned*)(pk + BM);                       // [64]

    const int tid  = threadIdx.x;
    const int lane = tid & 31;
    const int wid  = tid >> 5;
    const int wm   = wid >> 2;     // 0..1 : 32-row band
    const int wn   = wid & 3;      // 0..3 : 16-code band
    const int q    = lane >> 2;    // 0..7
    const int cg   = lane & 3;     // 0..3
    const int row0 = blockIdx.x * BM;

    const uint32_t whu = smem_u32(wh);
    const uint32_t xhu = smem_u32(xh);

    // async copy of W chunk c (CN codes x 256 dims fp16 = 32 KB)
    auto copy_chunk = [&](int c) {
        int code0 = c * CN;
        #pragma unroll
        for (int i = tid; i < CN * 32; i += 256) {
            int r = i >> 5, f4 = i & 31;
            uint32_t doff = (uint32_t)(r * SSTR + f4 * 4) * 4;
            uint32_t goff = (uint32_t)(code0 + r) * 128 + f4 * 4;
            cpa16(whu + doff, &g_Whx[goff]);
        }
    };

    copy_chunk(0); cpa_commit();   // overlap with X conversion below

    for (int i = tid; i < KCODES; i += 256) hn[i] = g_halfnorm[i];
    if (tid < BM) { pk[tid] = 0ull; pk2[tid] = 0u; }

    // X tile: fp32 -> fp16, padded layout
    for (int i = tid; i < BM * 128; i += 256) {
        int r = i >> 7, w = i & 127;
        float2 v = *(const float2*)(X + (size_t)(row0 + r) * DDIM + 2 * w);
        xh[r * SSTR + w] = pack_h16x2(v.x, v.y);
    }

    // ldmatrix per-lane base addresses (bytes)
    // A (per m-tile t): row = wm*32 + t*16 + (lane&15), col words = 4*(lane>>4)
    uint32_t a_addr[2];
    #pragma unroll
    for (int t = 0; t < 2; t++)
        a_addr[t] = xhu + (((wm * 32 + t * 16 + (lane & 15)) * SSTR + 4 * (lane >> 4)) << 2);
    // B: code = wn*16 + 8*(lane>>4) + (lane&7), col words = 4*((lane>>3)&1)
    const uint32_t b_base = whu + (((wn * 16 + 8 * (lane >> 4) + (lane & 7)) * SSTR
                                   + 4 * ((lane >> 3) & 1)) << 2);

    float s1[4], s2[4];
    int   i1[4];
    #pragma unroll
    for (int s = 0; s < 4; s++) { s1[s] = -1e30f; s2[s] = -1e30f; i1[s] = 0; }

    for (int nc = 0; nc < KCODES / CN; nc++) {
        cpa_wait0();         // chunk nc arrived
        __syncthreads();     // visible to all threads (covers X tile on nc=0)

        float acc[2][2][4];  // [m-tile][n-tile]
        #pragma unroll
        for (int t = 0; t < 2; t++)
            #pragma unroll
            for (int u = 0; u < 2; u++)
                #pragma unroll
                for (int e = 0; e < 4; e++) acc[t][u][e] = 0.f;

        #pragma unroll 4
        for (int ks = 0; ks < 16; ks++) {
            const uint32_t koff = ks * 32;   // 8 words
            uint32_t a[2][4];
            ldsm_x4(a[0][0], a[0][1], a[0][2], a[0][3], a_addr[0] + koff);
            ldsm_x4(a[1][0], a[1][1], a[1][2], a[1][3], a_addr[1] + koff);
            uint32_t bf[2][2];
            ldsm_x4(bf[0][0], bf[0][1], bf[1][0], bf[1][1], b_base + koff);
            #pragma unroll
            for (int t = 0; t < 2; t++)
                #pragma unroll
                for (int u = 0; u < 2; u++)
                    mma_f16(acc[t][u], a[t], bf[u]);
        }

        __syncthreads();     // all warps done reading buffer before overwrite
        if (nc < KCODES / CN - 1) copy_chunk(nc + 1);
        cpa_commit();

        // epilogue overlaps with copy flight: registers + hn only
        #pragma unroll
        for (int t = 0; t < 2; t++)
            #pragma unroll
            for (int u = 0; u < 2; u++)
                #pragma unroll
                for (int e = 0; e < 4; e++) {
                    int slot = t * 2 + (e >> 1);
                    int code = nc * CN + wn * 16 + u * 8 + cg * 2 + (e & 1);
                    float sc = acc[t][u][e] - hn[code];
                    if (sc > s1[slot]) { s2[slot] = s1[slot]; s1[slot] = sc; i1[slot] = code; }
                    else if (sc > s2[slot]) s2[slot] = sc;
                }
    }
    __syncthreads();

    // tournament 1: per-row best (first-index tiebreak)
    #pragma unroll
    for (int s = 0; s < 4; s++) {
        int rowl = wm * 32 + s * 8 + q;
        unsigned long long p = ((unsigned long long)f2o(s1[s]) << 32) |
                               (unsigned long long)(KCODES - 1 - i1[s]);
        atomicMax(&pk[rowl], p);
    }
    __syncthreads();
    // tournament 2: per-row second-best (exclude winner's code)
    #pragma unroll
    for (int s = 0; s < 4; s++) {
        int rowl = wm * 32 + s * 8 + q;
        int winner = (KCODES - 1) - (int)(pk[rowl] & 0xffffffffu);
        float cand = (i1[s] == winner) ? s2[s] : s1[s];
        atomicMax(&pk2[rowl], f2o(cand));
    }
    __syncthreads();

    if (tid < BM) {
        unsigned long long p = pk[tid];
        int idx = (KCODES - 1) - (int)(p & 0xffffffffu);
        float b1 = o2f((unsigned)(p >> 32));
        float b2 = o2f(pk2[tid]);
        int row = row0 + tid;
        g_idx[row] = idx;
        if (b1 - b2 < GAP_T) {
            g_best[row] = 0xFFFFFFFFFFFFFFFFull;
            int pos = atomicAdd(&g_nflag, 1);
            g_flagrows[pos] = row;
        }
    }
}

// ---------------- rescan v3: 8-row batched, bit-exact (validated R10) ----------------
__global__ void __launch_bounds__(256) vq_rescan3(const float* __restrict__ X) {
    __shared__ float xs[8][DDIM];
    __shared__ float nxs[8];
    __shared__ int   rws[8];
    const int tid = threadIdx.x;
    int n = g_nflag;
    if (n > NROWS) n = NROWS;
    if (n == 0) return;
    int nu = ((n + 7) >> 3) * 2;

    for (int u = blockIdx.x; u < nu; u += gridDim.x) {
        int g = u >> 1, h = u & 1;
        __syncthreads();   // protect previous iteration's xs/nxs
        if (tid < 8) {
            int s = g * 8 + tid;
            rws[tid] = g_flagrows[s < n ? s : n - 1];
        }
        __syncthreads();
        for (int i = tid; i < 8 * 64; i += 256) {
            int r = i >> 6, f = i & 63;
            *(float4*)&xs[r][f * 4] = *(const float4*)(X + (size_t)rws[r] * DDIM + f * 4);
        }
        __syncthreads();
        {   // emulated nx per row (warp w -> row w)
            int w = tid >> 5, lane = tid & 31;
            float p = 0.f;
            #pragma unroll
            for (int j = 0; j < 8; j++) {
                float v = xs[w][lane + 32 * j];
                p = __fmaf_rn(v, v, p);
            }
            #pragma unroll
            for (int o = 16; o > 0; o >>= 1)
                p = __fadd_rn(p, __shfl_down_sync(0xffffffffu, p, o));
            if (lane == 0) nxs[w] = p;
        }
        __syncthreads();

        const int k0 = h * 512 + tid;
        float a[8][2];
        #pragma unroll
        for (int r = 0; r < 8; r++) { a[r][0] = 0.f; a[r][1] = 0.f; }
        const float* w0 = g_Wt + k0;
        #pragma unroll 4
        for (int j = 0; j < DDIM; j++) {
            float wv0 = w0[(size_t)j * KCODES];
            float wv1 = w0[(size_t)j * KCODES + 256];
            #pragma unroll
            for (int r = 0; r < 8; r++) {
                float x = xs[r][j];
                a[r][0] = __fmaf_rn(x, wv0, a[r][0]);
                a[r][1] = __fmaf_rn(x, wv1, a[r][1]);
            }
        }
        float ne0 = g_ne[k0], ne1 = g_ne[k0 + 256];
        #pragma unroll
        for (int r = 0; r < 8; r++) {
            float d0 = __fadd_rn(__fmaf_rn(a[r][0], -2.0f, nxs[r]), ne0);
            float d1 = __fadd_rn(__fmaf_rn(a[r][1], -2.0f, nxs[r]), ne1);
            unsigned long long p0 = ((unsigned long long)f2o(d0) << 32) | (unsigned)k0;
            unsigned long long p1 = ((unsigned long long)f2o(d1) << 32) | (unsigned)(k0 + 256);
            atomicMin(&g_best[rws[r]], p0 < p1 ? p0 : p1);
        }
    }
}

// write winning indices for flagged rows
__global__ void vq_fix() {
    int n = g_nflag;
    if (n > NROWS) n = NROWS;
    for (int u = blockIdx.x * blockDim.x + threadIdx.x; u < n; u += gridDim.x * blockDim.x) {
        int row = g_flagrows[u];
        g_idx[row] = (int)(g_best[row] & 0xffffffffu);
    }
}

// ---------------- gather + commitment + histogram ----------------
__global__ void __launch_bounds__(256) vq_gather(
    const float* __restrict__ X, const float* __restrict__ W,
    float* __restrict__ outq, float* __restrict__ out_idx)
{
    __shared__ double cred[8];
    const int tid = threadIdx.x;
    const int row0 = blockIdx.x * 64;
    const int r  = tid >> 2;
    const int dq = tid & 3;
    const int row = row0 + r;

    int idx = g_idx[row];
    const float* erow = W + (size_t)idx * DDIM;
    const float* xrow = X + (size_t)row * DDIM;
    float* orow = outq + (size_t)row * DDIM;
    double csum = 0.0;
    #pragma unroll
    for (int j = 0; j < 16; j++) {
        int f4 = dq + 4 * j;
        float4 e4 = *(const float4*)(erow + 4 * f4);
        float4 x4 = *(const float4*)(xrow + 4 * f4);
        *(float4*)(orow + 4 * f4) = e4;
        float d0 = e4.x - x4.x;
        float d1 = e4.y - x4.y;
        float d2 = e4.z - x4.z;
        float d3 = e4.w - x4.w;
        csum += (double)d0 * d0 + (double)d1 * d1 + (double)d2 * d2 + (double)d3 * d3;
    }
    if (dq == 0) {
        atomicAdd(&g_hist[idx], 1);
        if (out_idx) out_idx[row] = (float)idx;
    }

    #pragma unroll
    for (int o = 16; o > 0; o >>= 1)
        csum += __shfl_xor_sync(0xffffffffu, csum, o);
    if ((tid & 31) == 0) cred[tid >> 5] = csum;
    __syncthreads();
    if (tid < 8) {
        double v = cred[tid];
        #pragma unroll
        for (int o = 4; o > 0; o >>= 1) v += __shfl_xor_sync(0xffu, v, o);
        if (tid == 0) atomicAdd(&g_commit, v);
    }
}

// ---------------- diversity loss ----------------
__global__ void __launch_bounds__(256) vq_div(const float* __restrict__ W) {
    __shared__ float si[32][68];
    __shared__ float sj[32][68];
    __shared__ double red[8];
    const int tid = threadIdx.x;
    const int ibase = (blockIdx.x & 15) * 64;
    const int jbase = (blockIdx.x >> 4) * 64;
    const int ig = tid & 15;
    const int jg = tid >> 4;

    float acc[4][4];
    #pragma unroll
    for (int i = 0; i < 4; i++)
        #pragma unroll
        for (int j = 0; j < 4; j++) acc[i][j] = 0.f;

    for (int dc = 0; dc < DDIM / 32; ++dc) {
        __syncthreads();
        #pragma unroll
        for (int t = 0; t < 2; t++) {
            int slot = tid + 256 * t;
            int c  = slot >> 3;
            int f4 = slot & 7;
            float4 v = *(const float4*)(W + (size_t)(ibase + c) * DDIM + dc * 32 + f4 * 4);
            float4 w = *(const float4*)(W + (size_t)(jbase + c) * DDIM + dc * 32 + f4 * 4);
            int d = f4 * 4;
            si[d + 0][c] = v.x; si[d + 1][c] = v.y; si[d + 2][c] = v.z; si[d + 3][c] = v.w;
            sj[d + 0][c] = w.x; sj[d + 1][c] = w.y; sj[d + 2][c] = w.z; sj[d + 3][c] = w.w;
        }
        __syncthreads();
        #pragma unroll
        for (int d = 0; d < 32; ++d) {
            float a[4], b[4];
            #pragma unroll
            for (int i = 0; i < 4; i++) a[i] = si[d][ig * 4 + i];
            #pragma unroll
            for (int j = 0; j < 4; j++) b[j] = sj[d][jg * 4 + j];
            #pragma unroll
            for (int i = 0; i < 4; i++)
                #pragma unroll
                for (int j = 0; j < 4; j++)
                    acc[i][j] = fmaf(a[i], b[j], acc[i][j]);
        }
    }

    float invi[4], invj[4];
    #pragma unroll
    for (int i = 0; i < 4; i++) invi[i] = g_invnorm[ibase + ig * 4 + i];
    #pragma unroll
    for (int j = 0; j < 4; j++) invj[j] = g_invnorm[jbase + jg * 4 + j];

    double s = 0.0;
    #pragma unroll
    for (int i = 0; i < 4; i++)
        #pragma unroll
        for (int j = 0; j < 4; j++) {
            float v = acc[i][j] * invi[i] * invj[j];
            if (ibase + ig * 4 + i == jbase + jg * 4 + j) v -= 1.0f;
            float t = fmaxf(fabsf(v), 0.1f);
            s += (double)t * (double)t;
        }

    #pragma unroll
    for (int o = 16; o > 0; o >>= 1) s += __shfl_xor_sync(0xffffffffu, s, o);
    if ((tid & 31) == 0) red[tid >> 5] = s;
    __syncthreads();
    if (tid < 8) {
        double v = red[tid];
        #pragma unroll
        for (int o = 4; o > 0; o >>= 1) v += __shfl_xor_sync(0xffu, v, o);
        if (tid == 0) atomicAdd(&g_div, v);
    }
}

// ---------------- entropy + combine ----------------
__global__ void vq_fin(float* __restrict__ out_loss) {
    __shared__ double red[32];
    int k = threadIdx.x;
    double p = (double)g_hist[k] * (1.0 / (double)NROWS);
    const double u = 1.0 / (double)KCODES;
    double term = u * (log(u) - log(p + 1e-10));
    #pragma unroll
    for (int o = 16; o > 0; o >>= 1) term += __shfl_xor_sync(0xffffffffu, term, o);
    if ((k & 31) == 0) red[k >> 5] = term;
    __syncthreads();
    if (k < 32) {
        double v = red[k];
        #pragma unroll
        for (int o = 16; o > 0; o >>= 1) v += __shfl_xor_sync(0xffffffffu, v, o);
        if (k == 0) {
            double commit = g_commit * (1.0 / ((double)NROWS * (double)DDIM));
            double divm   = g_div * (1.0 / ((double)KCODES * (double)KCODES));
            double total = 0.25 * commit + 0.5 * divm + 0.5 * v;
            if (out_loss) *out_loss = (float)total;
        }
    }
}

extern "C" void kernel_launch(void* const* d_in, const int* in_sizes, int n_in,
                              void* d_out, int out_size) {
    const float* X = (const float*)d_in[0];
    const float* W = (const float*)d_in[1];
    float* out = (float*)d_out;

    const long long Nq = (long long)NROWS * DDIM;
    float* out_loss = nullptr;
    float* out_idx  = nullptr;
    if ((long long)out_size >= Nq + 1 + NROWS) {
        out_loss = out + Nq;
        out_idx  = out + Nq + 1;
    }

    // dynamic smem: hn + X fp16 (64 rows) + W fp16 (64 codes) + tournaments (~72.4 KB)
    const int SMEM_MMA = (1024 + BM * SSTR + BUFW) * 4 + BM * 8 + BM * 4;
    cudaFuncSetAttribute(vq_main_mma, cudaFuncAttributeMaxDynamicSharedMemorySize, SMEM_MMA);

    vq_tr<<<256, 256>>>(W);
    vq_pre<<<KCODES / 8, 256>>>(W);
    vq_main_mma<<<NROWS / BM, 256, SMEM_MMA>>>(X);
    vq_rescan3<<<1024, 256>>>(X);
    vq_fix<<<64, 256>>>();
    vq_gather<<<NROWS / 64, 256>>>(X, W, out, out_idx);
    vq_div<<<256, 256>>>(W);
    vq_fin<<<1, 1024>>>(out_loss);
}